// round 6
// baseline (speedup 1.0000x reference)
#include <cuda_runtime.h>
#include <cuda_bf16.h>
#include <math.h>
#include <stdint.h>

#define BQ 16
#define NQ 2048
#define DQ 64
#define SQ 512
#define NSQ 32
#define SCQ 67
#define INCH 134
#define C0Q 128
#define C1Q 128
#define C2Q 256
#define KSQ (NSQ*SQ)
#define JQ (3+DQ+NSQ*DQ+NSQ*3)   // 2211
#define OFF_X 0
#define OFF_P 3
#define OFF_GP 67
#define OFF_GX 2115
#define XYZ_OUT (BQ*3*SQ)
#define NP_OUT  ((size_t)BQ*C2Q*SQ)
#define KP1 96    // padded K for 67
#define KPE 160   // padded K for 134

typedef unsigned short ush;

// ---------------- fp32 scratch ----------------
__device__ float g_h1t [(size_t)BQ*NQ*SCQ];
__device__ float g_h2  [(size_t)BQ*SQ*NQ];
__device__ float g_inner[(size_t)BQ*SQ*SQ];
__device__ float g_Cbig[(size_t)BQ*SQ*JQ];
__device__ float g_O0T [(size_t)BQ*KSQ*C0Q];
__device__ float g_O1T [(size_t)BQ*KSQ*C1Q];
__device__ float g_O2T [(size_t)BQ*KSQ*C2Q];
__device__ float g_norm[BQ*SQ];
__device__ int   g_amax[SQ];
__device__ int   g_idx[(size_t)BQ*NSQ*NQ];
__device__ double g_part[(size_t)256*256*2];
__device__ float g_s1[SCQ], g_sh1[SCQ];
__device__ float g_s2[SQ],  g_sh2[SQ];
__device__ float g_sc0[C0Q], g_sf0[C0Q];
__device__ float g_sc1[C1Q], g_sf1[C1Q];
__device__ float g_sc2[C2Q], g_sf2[C2Q];
__device__ float g_acc[BQ];
__device__ int   g_flags[NQ];

// ---------------- bf16 hi/lo operand arrays ----------------
__device__ ush g_aggc_h[(size_t)BQ*NQ*KP1],  g_aggc_l[(size_t)BQ*NQ*KP1];
__device__ ush g_w1c_h[SCQ*KP1],             g_w1c_l[SCQ*KP1];
__device__ ush g_h1c_h[(size_t)BQ*NQ*KP1],   g_h1c_l[(size_t)BQ*NQ*KP1];
__device__ ush g_w2c_h[SQ*KP1],              g_w2c_l[SQ*KP1];
__device__ ush g_Sc_h[(size_t)BQ*SQ*NQ],     g_Sc_l[(size_t)BQ*SQ*NQ];
__device__ ush g_BmTc_h[(size_t)BQ*JQ*NQ],   g_BmTc_l[(size_t)BQ*JQ*NQ];
__device__ ush g_ETc_h[(size_t)BQ*KSQ*KPE],  g_ETc_l[(size_t)BQ*KSQ*KPE];
__device__ ush g_c0wc_h[C0Q*KPE],            g_c0wc_l[C0Q*KPE];
__device__ ush g_c1wc_h[C1Q*C0Q],            g_c1wc_l[C1Q*C0Q];
__device__ ush g_c2wc_h[C2Q*C1Q],            g_c2wc_l[C2Q*C1Q];
__device__ ush g_O0c_h[(size_t)BQ*KSQ*C0Q],  g_O0c_l[(size_t)BQ*KSQ*C0Q];
__device__ ush g_O1c_h[(size_t)BQ*KSQ*C1Q],  g_O1c_l[(size_t)BQ*KSQ*C1Q];

// ---------------- helpers ----------------
__device__ __forceinline__ uint32_t smem_u32(const void* p) {
    uint32_t a;
    asm("{ .reg .u64 t; cvta.to.shared.u64 t, %1; cvt.u32.u64 %0, t; }" : "=r"(a) : "l"(p));
    return a;
}
__device__ __forceinline__ void ldm4(uint32_t* r, uint32_t addr) {
    asm volatile("ldmatrix.sync.aligned.m8n8.x4.shared.b16 {%0,%1,%2,%3}, [%4];"
        : "=r"(r[0]), "=r"(r[1]), "=r"(r[2]), "=r"(r[3]) : "r"(addr));
}
__device__ __forceinline__ void mma16816(float* c, const uint32_t* a, const uint32_t* b) {
    asm volatile("mma.sync.aligned.m16n8k16.row.col.f32.bf16.bf16.f32 "
        "{%0,%1,%2,%3}, {%4,%5,%6,%7}, {%8,%9}, {%0,%1,%2,%3};"
        : "+f"(c[0]), "+f"(c[1]), "+f"(c[2]), "+f"(c[3])
        : "r"(a[0]), "r"(a[1]), "r"(a[2]), "r"(a[3]), "r"(b[0]), "r"(b[1]));
}
__device__ __forceinline__ void split_write(float v, ush* ph, ush* pl) {
    __nv_bfloat16 h = __float2bfloat16(v);
    __nv_bfloat16 l = __float2bfloat16(v - __bfloat162float(h));
    *ph = __bfloat16_as_ushort(h);
    *pl = __bfloat16_as_ushort(l);
}

// ---------------- pipelined HMMA GEMM: C[b](MxN) = A[b](MxKp) * B[b](NxKp)^T ----
// Operands pre-split bf16 hi/lo. Kp % 32 == 0 and Kp/32 >= 2. M % 128 == 0.
// 3-stage cp.async pipeline, one __syncthreads per K-chunk, loads issued before compute.
#define KC 32
#define RSH 40
#define TILEH (128*RSH)
#define STAGEH (4*TILEH)
#define NSTG 3
#define SMEM_BYTES (NSTG*STAGEH*2)   // 122880 B
__global__ void __launch_bounds__(256) mma_gemm(
    const ush* __restrict__ Ah, const ush* __restrict__ Al,
    const ush* __restrict__ Bh, const ush* __restrict__ Bl,
    float* __restrict__ C, int M, int N, int Kp,
    size_t sA, size_t sB, size_t sC,
    const float* __restrict__ biasRow, const float* __restrict__ biasCol)
{
    extern __shared__ ush sm[];
    const int tid = threadIdx.x;
    const int w = tid >> 5, lane = tid & 31;
    const int wm = w & 1, wn = w >> 1;
    const int m0 = blockIdx.y * 128, n0 = blockIdx.x * 128, b = blockIdx.z;
    const ush* srcs[4] = { Ah + (size_t)b*sA, Al + (size_t)b*sA,
                           Bh + (size_t)b*sB, Bl + (size_t)b*sB };
    const uint32_t smb = smem_u32(sm);

    float acc[4][4][4];
    #pragma unroll
    for (int i = 0; i < 4; i++)
        #pragma unroll
        for (int j = 0; j < 4; j++)
            #pragma unroll
            for (int q = 0; q < 4; q++) acc[i][j][q] = 0.f;

    const int T = Kp / KC;

    #define LOAD_STAGE(t, st) do { \
        int k0 = (t) * KC; \
        _Pragma("unroll") \
        for (int arr = 0; arr < 4; arr++) { \
            int r0 = (arr < 2) ? m0 : n0; \
            int rmax = (arr < 2) ? M : N; \
            const ush* S = srcs[arr]; \
            uint32_t dbase = smb + (uint32_t)(((st)*STAGEH + arr*TILEH) * 2); \
            _Pragma("unroll") \
            for (int i = 0; i < 2; i++) { \
                int e = tid + i * 256; \
                int r = e >> 2, c16 = e & 3; \
                uint32_t daddr = dbase + (uint32_t)((r * RSH + c16 * 8) * 2); \
                int rg = r0 + r; \
                int rc = rg < rmax ? rg : (rmax - 1); \
                const ush* sp = S + (size_t)rc * Kp + k0 + c16 * 8; \
                int sz = (rg < rmax) ? 16 : 0; \
                asm volatile("cp.async.cg.shared.global [%0], [%1], 16, %2;" \
                             :: "r"(daddr), "l"(sp), "r"(sz)); \
            } \
        } \
        asm volatile("cp.async.commit_group;" ::: "memory"); \
    } while (0)

    LOAD_STAGE(0, 0);
    LOAD_STAGE(1, 1);
    int stc = 0;   // stage index of chunk t (circular)
    for (int t = 0; t < T; t++) {
        if (t + 1 < T) asm volatile("cp.async.wait_group 1;" ::: "memory");
        else           asm volatile("cp.async.wait_group 0;" ::: "memory");
        __syncthreads();
        if (t + 2 < T) {
            int stn = stc + 2; if (stn >= NSTG) stn -= NSTG;
            LOAD_STAGE(t + 2, stn);
        }
        const uint32_t uAh = smb + (uint32_t)((stc*STAGEH + 0*TILEH) * 2);
        const uint32_t uAl = smb + (uint32_t)((stc*STAGEH + 1*TILEH) * 2);
        const uint32_t uBh = smb + (uint32_t)((stc*STAGEH + 2*TILEH) * 2);
        const uint32_t uBl = smb + (uint32_t)((stc*STAGEH + 3*TILEH) * 2);
        #pragma unroll
        for (int k16 = 0; k16 < 32; k16 += 16) {
            uint32_t ah[4][4], al[4][4], bh[4][2], bl[4][2];
            {
                int arow = wm * 64 + (lane & 15);
                int akk = k16 + ((lane >> 4) << 3);
                #pragma unroll
                for (int mf = 0; mf < 4; mf++) {
                    uint32_t byteoff = (uint32_t)(((arow + mf * 16) * RSH + akk) << 1);
                    ldm4(ah[mf], uAh + byteoff);
                    ldm4(al[mf], uAl + byteoff);
                }
                int q = lane >> 3;
                int brow0 = wn * 32 + ((q >> 1) << 3) + (lane & 7);
                int bkk = k16 + ((q & 1) << 3);
                #pragma unroll
                for (int p = 0; p < 2; p++) {
                    uint32_t byteoff = (uint32_t)(((brow0 + p * 16) * RSH + bkk) << 1);
                    uint32_t tmp[4];
                    ldm4(tmp, uBh + byteoff);
                    bh[2*p][0] = tmp[0]; bh[2*p][1] = tmp[1];
                    bh[2*p+1][0] = tmp[2]; bh[2*p+1][1] = tmp[3];
                    ldm4(tmp, uBl + byteoff);
                    bl[2*p][0] = tmp[0]; bl[2*p][1] = tmp[1];
                    bl[2*p+1][0] = tmp[2]; bl[2*p+1][1] = tmp[3];
                }
            }
            #pragma unroll
            for (int mf = 0; mf < 4; mf++)
                #pragma unroll
                for (int nf = 0; nf < 4; nf++)
                    mma16816(acc[mf][nf], ah[mf], bh[nf]);
            #pragma unroll
            for (int mf = 0; mf < 4; mf++)
                #pragma unroll
                for (int nf = 0; nf < 4; nf++)
                    mma16816(acc[mf][nf], ah[mf], bl[nf]);
            #pragma unroll
            for (int mf = 0; mf < 4; mf++)
                #pragma unroll
                for (int nf = 0; nf < 4; nf++)
                    mma16816(acc[mf][nf], al[mf], bh[nf]);
        }
        stc++; if (stc >= NSTG) stc = 0;
        __syncthreads();
    }

    float* Cb = C + (size_t)b * sC;
    #pragma unroll
    for (int mf = 0; mf < 4; mf++) {
        int r = m0 + wm * 64 + mf * 16 + (lane >> 2);
        float br0 = biasRow ? biasRow[r] : 0.f;
        float br1 = biasRow ? biasRow[r + 8] : 0.f;
        #pragma unroll
        for (int nf = 0; nf < 4; nf++) {
            int c = n0 + wn * 32 + nf * 8 + ((lane & 3) << 1);
            #pragma unroll
            for (int u = 0; u < 2; u++) {
                int col = c + u;
                if (col < N) {
                    float bc = biasCol ? biasCol[col] : 0.f;
                    Cb[(size_t)r * N + col]       = acc[mf][nf][u]     + br0 + bc;
                    Cb[(size_t)(r + 8) * N + col] = acc[mf][nf][u + 2] + br1 + bc;
                }
            }
        }
    }
}

// ---------------- elementwise / setup kernels ----------------
__global__ void sa_init() {
    int i = blockIdx.x * 256 + threadIdx.x;
    if (i < NQ) g_flags[i] = 0;
    if (i < BQ) g_acc[i] = 0.f;
}

__global__ void cv_split(const float* __restrict__ src, ush* __restrict__ dh, ush* __restrict__ dl,
                         long long total, int Ksrc, int Kp,
                         const float* __restrict__ sc, const float* __restrict__ sh, int leaky)
{
    long long i = (long long)blockIdx.x * 256 + threadIdx.x;
    if (i >= total) return;
    int c = (int)(i % Kp);
    long long r = i / Kp;
    float v = 0.f;
    if (c < Ksrc) {
        v = src[r * Ksrc + c];
        if (sc) { v = sc[c] * v + sh[c]; if (leaky && v < 0.f) v *= 0.2f; }
    }
    split_write(v, dh + i, dl + i);
}

__global__ void cv_agg(const float* __restrict__ points, const float* __restrict__ xyz) {
    long long i = (long long)blockIdx.x * 256 + threadIdx.x;
    if (i >= (long long)BQ*NQ*KP1) return;
    int c = (int)(i % KP1); long long r = i / KP1;
    int n = (int)(r % NQ); int b = (int)(r / NQ);
    float v = 0.f;
    if (c < DQ) v = points[((size_t)b*DQ + c)*NQ + n];
    else if (c < SCQ) v = xyz[((size_t)b*3 + (c-DQ))*NQ + n];
    split_write(v, g_aggc_h + i, g_aggc_l + i);
}

__global__ void sa_ball(const float* __restrict__ xyz) {
    int w = (blockIdx.x * blockDim.x + threadIdx.x) >> 5;
    int lane = threadIdx.x & 31;
    if (w >= BQ * NQ) return;
    int b = w / NQ, n = w % NQ;
    const float* X = xyz + (size_t)b * 3 * NQ;
    float px = X[n], py = X[NQ+n], pz = X[2*NQ+n];
    float pn = px*px + py*py + pz*pz;
    const float RR = (float)(0.2 * 0.2);
    int* out = g_idx + (size_t)b * NSQ * NQ + n;
    int cnt = 0;
    for (int j0 = 0; j0 < NQ && cnt < NSQ; j0 += 32) {
        int j = j0 + lane;
        float qx = X[j], qy = X[NQ+j], qz = X[2*NQ+j];
        float sq = (pn + qx*qx+qy*qy+qz*qz) - 2.0f*(px*qx+py*qy+pz*qz);
        bool in = !(sq > RR);
        unsigned m = __ballot_sync(0xffffffffu, in);
        int pos = cnt + __popc(m & ((1u << lane) - 1u));
        if (in && pos < NSQ) out[(size_t)pos * NQ] = j;
        cnt += __popc(m);
    }
    __syncwarp();
    if (lane == 0) {
        int first = out[0];
        for (int t = cnt; t < NSQ; t++) out[(size_t)t * NQ] = first;
    }
}

__global__ void sa_bmt_c(const float* __restrict__ points, const float* __restrict__ xyz) {
    int n = blockIdx.x * 256 + threadIdx.x;
    int j = blockIdx.y, b = blockIdx.z;
    float v;
    if (j < OFF_P) v = xyz[((size_t)b*3 + j)*NQ + n];
    else if (j < OFF_GP) v = points[((size_t)b*DQ + (j-OFF_P))*NQ + n];
    else if (j < OFF_GX) {
        int t = j - OFF_GP, k = t >> 6, d = t & 63;
        int ii = g_idx[((size_t)b*NSQ + k)*NQ + n];
        v = points[((size_t)b*DQ + d)*NQ + ii];
    } else {
        int t = j - OFF_GX, k = t / 3, c = t % 3;
        int ii = g_idx[((size_t)b*NSQ + k)*NQ + n];
        v = xyz[((size_t)b*3 + c)*NQ + ii];
    }
    size_t o = ((size_t)b*JQ + j)*NQ + n;
    split_write(v, g_BmTc_h + o, g_BmTc_l + o);
}

__global__ void sa_cs_part(const float* __restrict__ X, int C, int totalRows, int rpc) {
    int chunk = blockIdx.x, tid = threadIdx.x;
    if (tid >= C) return;
    double s = 0.0, s2 = 0.0;
    int r1 = min((chunk + 1) * rpc, totalRows);
    for (int r = chunk * rpc; r < r1; r++) {
        double v = X[(size_t)r * C + tid];
        s += v; s2 += v * v;
    }
    g_part[((size_t)chunk * C + tid) * 2] = s;
    g_part[((size_t)chunk * C + tid) * 2 + 1] = s2;
}
__global__ void sa_cs_fin(int C, int nChunks, int count,
                          const float* __restrict__ gamma, const float* __restrict__ beta,
                          float* __restrict__ sc, float* __restrict__ sf) {
    int c = blockIdx.x, tid = threadIdx.x;
    double s = 0.0, s2 = 0.0;
    for (int i = tid; i < nChunks; i += 256) {
        s  += g_part[((size_t)i * C + c) * 2];
        s2 += g_part[((size_t)i * C + c) * 2 + 1];
    }
    __shared__ double sa[256], sb2[256];
    sa[tid] = s; sb2[tid] = s2; __syncthreads();
    for (int o = 128; o > 0; o >>= 1) {
        if (tid < o) { sa[tid] += sa[tid+o]; sb2[tid] += sb2[tid+o]; }
        __syncthreads();
    }
    if (tid == 0) {
        double n = (double)count, m = sa[0] / n;
        double var = sb2[0] / n - m * m; if (var < 0.0) var = 0.0;
        float scale = gamma[c] * rsqrtf((float)var + 1e-5f);
        sc[c] = scale; sf[c] = beta[c] - (float)m * scale;
    }
}

__global__ void sa_rstats(const float* __restrict__ X, int Cch, int L,
                          const float* __restrict__ gamma, const float* __restrict__ beta,
                          float* __restrict__ sc, float* __restrict__ sf) {
    int c = blockIdx.x, tid = threadIdx.x;
    double s = 0.0, s2 = 0.0;
    for (int b = 0; b < BQ; b++) {
        const float* p = X + ((size_t)b * Cch + c) * L;
        for (int i = tid; i < L; i += 256) { double v = p[i]; s += v; s2 += v * v; }
    }
    __shared__ double ss[256], ss2[256];
    ss[tid] = s; ss2[tid] = s2; __syncthreads();
    for (int o = 128; o > 0; o >>= 1) {
        if (tid < o) { ss[tid] += ss[tid+o]; ss2[tid] += ss2[tid+o]; }
        __syncthreads();
    }
    if (tid == 0) {
        double n = (double)BQ * L, m = ss[0] / n;
        double var = ss2[0] / n - m * m; if (var < 0.0) var = 0.0;
        float scale = gamma[c] * rsqrtf((float)var + 1e-5f);
        sc[c] = scale; sf[c] = beta[c] - (float)m * scale;
    }
}

__global__ void sa_softmax(float* __restrict__ H) {
    int s = blockIdx.x, b = blockIdx.y, tid = threadIdx.x;
    float* row = H + ((size_t)b * SQ + s) * NQ;
    __shared__ float buf[NQ];
    __shared__ float red[256], rv[256];
    __shared__ int ri[256];
    float a = g_s2[s], sh = g_sh2[s];
    float lmax = -3.4e38f;
    for (int i = tid; i < NQ; i += 256) { float y = a*row[i]+sh; buf[i] = y; lmax = fmaxf(lmax, y); }
    red[tid] = lmax; __syncthreads();
    for (int o = 128; o > 0; o >>= 1) { if (tid < o) red[tid] = fmaxf(red[tid], red[tid+o]); __syncthreads(); }
    float gmax = red[0]; __syncthreads();
    float lsum = 0.f;
    for (int i = tid; i < NQ; i += 256) { float e = expf(buf[i]-gmax); buf[i] = e; lsum += e; }
    red[tid] = lsum; __syncthreads();
    for (int o = 128; o > 0; o >>= 1) { if (tid < o) red[tid] += red[tid+o]; __syncthreads(); }
    float inv = 1.f / red[0]; __syncthreads();
    float lss = 0.f, bm = -1.f; int bi = 0;
    size_t rowoff = ((size_t)b * SQ + s) * NQ;
    for (int i = tid; i < NQ; i += 256) {
        float v = buf[i] * inv; row[i] = v; lss += v*v;
        split_write(v, g_Sc_h + rowoff + i, g_Sc_l + rowoff + i);
        if (v > bm) { bm = v; bi = i; }
    }
    red[tid] = lss; rv[tid] = bm; ri[tid] = bi; __syncthreads();
    for (int o = 128; o > 0; o >>= 1) {
        if (tid < o) {
            red[tid] += red[tid+o];
            if (rv[tid+o] > rv[tid] || (rv[tid+o] == rv[tid] && ri[tid+o] < ri[tid])) { rv[tid] = rv[tid+o]; ri[tid] = ri[tid+o]; }
        }
        __syncthreads();
    }
    if (tid == 0) {
        g_norm[b*SQ+s] = sqrtf(red[0]);
        if (b == 0) g_amax[s] = ri[0];
    }
}

__global__ void sa_flags() { int s = blockIdx.x*256 + threadIdx.x; if (s < SQ) g_flags[g_amax[s]] = 1; }

__global__ void sa_cos_epi() {
    size_t i = (size_t)blockIdx.x * 256 + threadIdx.x;
    int b = (int)(i / ((size_t)SQ*SQ)), r = (int)((i / SQ) % SQ), c = (int)(i % SQ);
    float v = 0.f;
    if (r != c) {
        float cm = g_inner[i] / (g_norm[b*SQ+r] * g_norm[b*SQ+c] + 1e-10f);
        v = cm * cm;
    }
    __shared__ float red[256];
    red[threadIdx.x] = v; __syncthreads();
    for (int o = 128; o > 0; o >>= 1) { if (threadIdx.x < o) red[threadIdx.x] += red[threadIdx.x+o]; __syncthreads(); }
    if (threadIdx.x == 0) atomicAdd(&g_acc[b], red[0]);
}

__global__ void sa_newxyz(float* __restrict__ out) {
    int i = blockIdx.x * 256 + threadIdx.x;
    if (i >= BQ*3*SQ) return;
    int s = i % SQ, c = (i/SQ) % 3, b = i/(3*SQ);
    out[i] = g_Cbig[((size_t)b*SQ + s)*JQ + OFF_X + c];
}

__global__ void sa_et_c() {
    int r = blockIdx.x, b = blockIdx.y, ch = threadIdx.x;
    int s = r % SQ, k = r / SQ;
    const float* Cr = g_Cbig + ((size_t)b*SQ + s)*JQ;
    float v = 0.f;
    if (ch < 64) v = Cr[OFF_P + ch];
    else if (ch < 128) { int d = ch - 64; v = Cr[OFF_GP + k*DQ + d] - Cr[OFF_P + d]; }
    else if (ch < 131) v = Cr[OFF_X + (ch - 128)];
    else if (ch < INCH) { int c3 = ch - 131; v = Cr[OFF_GX + k*3 + c3] - Cr[OFF_X + c3]; }
    size_t o = ((size_t)b*KSQ + r)*KPE + ch;
    split_write(v, g_ETc_h + o, g_ETc_l + o);
}

__global__ void sa_max(float* __restrict__ out) {
    int s = blockIdx.x, b = blockIdx.y, o = threadIdx.x;
    float sc = g_sc2[o], sf = g_sf2[o];
    float m = -3.4e38f;
    const float* base = g_O2T + ((size_t)b*KSQ + s)*C2Q + o;
    #pragma unroll
    for (int k = 0; k < NSQ; k++) {
        float y = sc * base[(size_t)k*SQ*C2Q] + sf;
        y = (y >= 0.f) ? y : 0.2f * y;
        m = fmaxf(m, y);
    }
    out[XYZ_OUT + ((size_t)b*C2Q + o)*SQ + s] = m;
}

__global__ void sa_scalars(float* __restrict__ out) {
    __shared__ float sfr[256]; __shared__ int sir[256];
    int tid = threadIdx.x;
    int cnt = 0;
    for (int i = tid; i < NQ; i += 256) cnt += g_flags[i];
    float l = (tid < BQ) ? sqrtf(g_acc[tid]) : 0.f;
    sfr[tid] = l; sir[tid] = cnt; __syncthreads();
    for (int o = 128; o > 0; o >>= 1) {
        if (tid < o) { sfr[tid] += sfr[tid+o]; sir[tid] += sir[tid+o]; }
        __syncthreads();
    }
    if (tid == 0) {
        out[XYZ_OUT + NP_OUT] = sfr[0] / (float)BQ;
        out[XYZ_OUT + NP_OUT + 1] = (float)sir[0];
    }
}

// ---------------- launch ----------------
static inline float* symf(const void* sym) { void* p = nullptr; cudaGetSymbolAddress(&p, sym); return (float*)p; }
static inline ush*   symu(const void* sym) { void* p = nullptr; cudaGetSymbolAddress(&p, sym); return (ush*)p; }

extern "C" void kernel_launch(void* const* d_in, const int* in_sizes, int n_in,
                              void* d_out, int out_size)
{
    const float* xyz   = (const float*)d_in[0];
    const float* points= (const float*)d_in[1];
    const float* w1_w = (const float*)d_in[2];
    const float* w1_b = (const float*)d_in[3];
    const float* bn1g = (const float*)d_in[4];
    const float* bn1b = (const float*)d_in[5];
    const float* w2_w = (const float*)d_in[6];
    const float* w2_b = (const float*)d_in[7];
    const float* bn2g = (const float*)d_in[8];
    const float* bn2b = (const float*)d_in[9];
    const float* c0w = (const float*)d_in[10];
    const float* c0b = (const float*)d_in[11];
    const float* g0  = (const float*)d_in[12];
    const float* b0  = (const float*)d_in[13];
    const float* c1w = (const float*)d_in[14];
    const float* c1b = (const float*)d_in[15];
    const float* g1  = (const float*)d_in[16];
    const float* b1  = (const float*)d_in[17];
    const float* c2w = (const float*)d_in[18];
    const float* c2b = (const float*)d_in[19];
    const float* g2  = (const float*)d_in[20];
    const float* b2  = (const float*)d_in[21];
    float* out = (float*)d_out;

    static bool attr = false;
    if (!attr) {
        cudaFuncSetAttribute(mma_gemm, cudaFuncAttributeMaxDynamicSharedMemorySize, SMEM_BYTES);
        attr = true;
    }

    float* p_h1t = symf(g_h1t);
    float* p_h2  = symf(g_h2);
    float* p_inner = symf(g_inner);
    float* p_C   = symf(g_Cbig);
    float* p_O0  = symf(g_O0T);
    float* p_O1  = symf(g_O1T);
    float* p_O2  = symf(g_O2T);
    float* p_s1 = symf(g_s1), *p_sh1 = symf(g_sh1);
    float* p_s2 = symf(g_s2), *p_sh2 = symf(g_sh2);
    float* p_sc0 = symf(g_sc0), *p_sf0 = symf(g_sf0);
    float* p_sc1 = symf(g_sc1), *p_sf1 = symf(g_sf1);
    float* p_sc2 = symf(g_sc2), *p_sf2 = symf(g_sf2);
    ush *aggh = symu(g_aggc_h), *aggl = symu(g_aggc_l);
    ush *w1h = symu(g_w1c_h), *w1l = symu(g_w1c_l);
    ush *h1h = symu(g_h1c_h), *h1l = symu(g_h1c_l);
    ush *w2h = symu(g_w2c_h), *w2l = symu(g_w2c_l);
    ush *Sh = symu(g_Sc_h), *Sl = symu(g_Sc_l);
    ush *Bmh = symu(g_BmTc_h), *Bml = symu(g_BmTc_l);
    ush *Eh = symu(g_ETc_h), *El = symu(g_ETc_l);
    ush *w0h = symu(g_c0wc_h), *w0l = symu(g_c0wc_l);
    ush *c1h = symu(g_c1wc_h), *c1l = symu(g_c1wc_l);
    ush *c2h = symu(g_c2wc_h), *c2l = symu(g_c2wc_l);
    ush *O0h = symu(g_O0c_h), *O0l = symu(g_O0c_l);
    ush *O1h = symu(g_O1c_h), *O1l = symu(g_O1c_l);

    sa_init<<<9, 256>>>();
    cv_agg<<<(int)(((long long)BQ*NQ*KP1 + 255)/256), 256>>>(points, xyz);
    cv_split<<<(SCQ*KP1 + 255)/256, 256>>>(w1_w, w1h, w1l, (long long)SCQ*KP1, SCQ, KP1, nullptr, nullptr, 0);
    cv_split<<<(SQ*KP1 + 255)/256, 256>>>(w2_w, w2h, w2l, (long long)SQ*KP1, SCQ, KP1, nullptr, nullptr, 0);
    cv_split<<<(C0Q*KPE + 255)/256, 256>>>(c0w, w0h, w0l, (long long)C0Q*KPE, INCH, KPE, nullptr, nullptr, 0);
    cv_split<<<(C1Q*C0Q + 255)/256, 256>>>(c1w, c1h, c1l, (long long)C1Q*C0Q, C0Q, C0Q, nullptr, nullptr, 0);
    cv_split<<<(C2Q*C1Q + 255)/256, 256>>>(c2w, c2h, c2l, (long long)C2Q*C1Q, C1Q, C1Q, nullptr, nullptr, 0);
    sa_ball<<<(BQ*NQ*32)/256, 256>>>(xyz);
    sa_bmt_c<<<dim3(NQ/256, JQ, BQ), 256>>>(points, xyz);

    // h1t = aggT * w1^T + w1_b
    mma_gemm<<<dim3(1, NQ/128, BQ), 256, SMEM_BYTES>>>(aggh, aggl, w1h, w1l, p_h1t,
        NQ, SCQ, KP1, (size_t)NQ*KP1, 0, (size_t)NQ*SCQ, nullptr, w1_b);
    sa_cs_part<<<128, 128>>>(p_h1t, SCQ, BQ*NQ, BQ*NQ/128);
    sa_cs_fin<<<SCQ, 256>>>(SCQ, 128, BQ*NQ, bn1g, bn1b, p_s1, p_sh1);
    cv_split<<<(int)(((long long)BQ*NQ*KP1 + 255)/256), 256>>>(p_h1t, h1h, h1l,
        (long long)BQ*NQ*KP1, SCQ, KP1, p_s1, p_sh1, 0);

    // h2 = w2 * bn1(h1)^T + w2_b
    mma_gemm<<<dim3(NQ/128, SQ/128, BQ), 256, SMEM_BYTES>>>(w2h, w2l, h1h, h1l, p_h2,
        SQ, NQ, KP1, 0, (size_t)NQ*KP1, (size_t)SQ*NQ, w2_b, nullptr);
    sa_rstats<<<SQ, 256>>>(p_h2, SQ, NQ, bn2g, bn2b, p_s2, p_sh2);
    sa_softmax<<<dim3(SQ, BQ), 256>>>(p_h2);
    sa_flags<<<2, 256>>>();

    // inner = S S^T
    mma_gemm<<<dim3(SQ/128, SQ/128, BQ), 256, SMEM_BYTES>>>(Sh, Sl, Sh, Sl, p_inner,
        SQ, SQ, NQ, (size_t)SQ*NQ, (size_t)SQ*NQ, (size_t)SQ*SQ, nullptr, nullptr);
    sa_cos_epi<<<(int)(((size_t)BQ*SQ*SQ)/256), 256>>>();

    // Cbig = S * BmT^T
    mma_gemm<<<dim3((JQ+127)/128, SQ/128, BQ), 256, SMEM_BYTES>>>(Sh, Sl, Bmh, Bml, p_C,
        SQ, JQ, NQ, (size_t)SQ*NQ, (size_t)JQ*NQ, (size_t)SQ*JQ, nullptr, nullptr);
    sa_newxyz<<<(BQ*3*SQ + 255)/256, 256>>>(out);
    sa_et_c<<<dim3(KSQ, BQ), KPE>>>();

    // conv stack (transposed outputs)
    mma_gemm<<<dim3(1, KSQ/128, BQ), 256, SMEM_BYTES>>>(Eh, El, w0h, w0l, p_O0,
        KSQ, C0Q, KPE, (size_t)KSQ*KPE, 0, (size_t)KSQ*C0Q, nullptr, c0b);
    sa_cs_part<<<256, 128>>>(p_O0, C0Q, BQ*KSQ, BQ*KSQ/256);
    sa_cs_fin<<<C0Q, 256>>>(C0Q, 256, BQ*KSQ, g0, b0, p_sc0, p_sf0);
    cv_split<<<(int)(((long long)BQ*KSQ*C0Q + 255)/256), 256>>>(p_O0, O0h, O0l,
        (long long)BQ*KSQ*C0Q, C0Q, C0Q, p_sc0, p_sf0, 1);

    mma_gemm<<<dim3(1, KSQ/128, BQ), 256, SMEM_BYTES>>>(O0h, O0l, c1h, c1l, p_O1,
        KSQ, C1Q, C0Q, (size_t)KSQ*C0Q, 0, (size_t)KSQ*C1Q, nullptr, c1b);
    sa_cs_part<<<256, 128>>>(p_O1, C1Q, BQ*KSQ, BQ*KSQ/256);
    sa_cs_fin<<<C1Q, 256>>>(C1Q, 256, BQ*KSQ, g1, b1, p_sc1, p_sf1);
    cv_split<<<(int)(((long long)BQ*KSQ*C1Q + 255)/256), 256>>>(p_O1, O1h, O1l,
        (long long)BQ*KSQ*C1Q, C1Q, C1Q, p_sc1, p_sf1, 1);

    mma_gemm<<<dim3(C2Q/128, KSQ/128, BQ), 256, SMEM_BYTES>>>(O1h, O1l, c2h, c2l, p_O2,
        KSQ, C2Q, C1Q, (size_t)KSQ*C1Q, 0, (size_t)KSQ*C2Q, nullptr, c2b);
    sa_cs_part<<<256, 256>>>(p_O2, C2Q, BQ*KSQ, BQ*KSQ/256);
    sa_cs_fin<<<C2Q, 256>>>(C2Q, 256, BQ*KSQ, g2, b2, p_sc2, p_sf2);

    sa_max<<<dim3(SQ, BQ), 256>>>(out);
    sa_scalars<<<1, 256>>>(out);
}

// round 7
// speedup vs baseline: 1.5306x; 1.5306x over previous
#include <cuda_runtime.h>
#include <cuda_bf16.h>
#include <math.h>
#include <stdint.h>

#define BQ 16
#define NQ 2048
#define DQ 64
#define SQ 512
#define NSQ 32
#define SCQ 67
#define INCH 134
#define C0Q 128
#define C1Q 128
#define C2Q 256
#define KSQ (NSQ*SQ)
#define JQ (3+DQ+NSQ*DQ+NSQ*3)   // 2211
#define OFF_X 0
#define OFF_P 3
#define OFF_GP 67
#define OFF_GX 2115
#define XYZ_OUT (BQ*3*SQ)
#define NP_OUT  ((size_t)BQ*C2Q*SQ)
#define KP1 96
#define KPE 160

typedef unsigned short ush;

// ---------------- fp32 scratch ----------------
__device__ float g_h1t [(size_t)BQ*NQ*SCQ];
__device__ float g_h2  [(size_t)BQ*SQ*NQ];
__device__ float g_inner[(size_t)BQ*SQ*SQ];
__device__ float g_Cbig[(size_t)BQ*SQ*JQ];
__device__ float g_O0T [(size_t)BQ*KSQ*C0Q];
__device__ float g_O1T [(size_t)BQ*KSQ*C1Q];
__device__ float g_O2T [(size_t)BQ*KSQ*C2Q];
__device__ float g_norm[BQ*SQ];
__device__ int   g_amax[SQ];
__device__ int   g_idx[(size_t)BQ*NSQ*NQ];
__device__ double g_part[(size_t)2048*256*2];
__device__ float g_s1[SCQ], g_sh1[SCQ];
__device__ float g_s2[SQ],  g_sh2[SQ];
__device__ float g_sc0[C0Q], g_sf0[C0Q];
__device__ float g_sc1[C1Q], g_sf1[C1Q];
__device__ float g_sc2[C2Q], g_sf2[C2Q];
__device__ float g_acc[BQ];
__device__ int   g_flags[NQ];

// ---------------- bf16 hi/lo operand arrays ----------------
__device__ ush g_aggc_h[(size_t)BQ*NQ*KP1],  g_aggc_l[(size_t)BQ*NQ*KP1];
__device__ ush g_w1c_h[SCQ*KP1],             g_w1c_l[SCQ*KP1];
__device__ ush g_h1c_h[(size_t)BQ*NQ*KP1],   g_h1c_l[(size_t)BQ*NQ*KP1];
__device__ ush g_w2c_h[SQ*KP1],              g_w2c_l[SQ*KP1];
__device__ ush g_Sc_h[(size_t)BQ*SQ*NQ],     g_Sc_l[(size_t)BQ*SQ*NQ];
__device__ ush g_BmTc_h[(size_t)BQ*JQ*NQ],   g_BmTc_l[(size_t)BQ*JQ*NQ];
__device__ ush g_ETc_h[(size_t)BQ*KSQ*KPE],  g_ETc_l[(size_t)BQ*KSQ*KPE];
__device__ ush g_c0wc_h[C0Q*KPE],            g_c0wc_l[C0Q*KPE];
__device__ ush g_c1wc_h[C1Q*C0Q],            g_c1wc_l[C1Q*C0Q];
__device__ ush g_c2wc_h[C2Q*C1Q],            g_c2wc_l[C2Q*C1Q];
__device__ ush g_O0c_h[(size_t)BQ*KSQ*C0Q],  g_O0c_l[(size_t)BQ*KSQ*C0Q];
__device__ ush g_O1c_h[(size_t)BQ*KSQ*C1Q],  g_O1c_l[(size_t)BQ*KSQ*C1Q];

// ---------------- helpers ----------------
__device__ __forceinline__ uint32_t smem_u32(const void* p) {
    uint32_t a;
    asm("{ .reg .u64 t; cvta.to.shared.u64 t, %1; cvt.u32.u64 %0, t; }" : "=r"(a) : "l"(p));
    return a;
}
__device__ __forceinline__ void ldm4(uint32_t* r, uint32_t addr) {
    asm volatile("ldmatrix.sync.aligned.m8n8.x4.shared.b16 {%0,%1,%2,%3}, [%4];"
        : "=r"(r[0]), "=r"(r[1]), "=r"(r[2]), "=r"(r[3]) : "r"(addr));
}
__device__ __forceinline__ void mma16816(float* c, const uint32_t* a, const uint32_t* b) {
    asm volatile("mma.sync.aligned.m16n8k16.row.col.f32.bf16.bf16.f32 "
        "{%0,%1,%2,%3}, {%4,%5,%6,%7}, {%8,%9}, {%0,%1,%2,%3};"
        : "+f"(c[0]), "+f"(c[1]), "+f"(c[2]), "+f"(c[3])
        : "r"(a[0]), "r"(a[1]), "r"(a[2]), "r"(a[3]), "r"(b[0]), "r"(b[1]));
}
__device__ __forceinline__ void split_write(float v, ush* ph, ush* pl) {
    __nv_bfloat16 h = __float2bfloat16(v);
    __nv_bfloat16 l = __float2bfloat16(v - __bfloat162float(h));
    *ph = __bfloat16_as_ushort(h);
    *pl = __bfloat16_as_ushort(l);
}

// ---------------- pipelined HMMA GEMM (2-stage) with fused BN-stats epilogue ----
// C[b](MxN) = A[b](MxKp) * B[b](NxKp)^T ; operands pre-split bf16 hi/lo.
// statMode: 0 none, 1 column stats (channels = N), 2 row stats (channels = M).
// triSkip: skip CTAs with blockIdx.x < blockIdx.y (symmetric output, upper only).
#define KC 32
#define RSH 40
#define TILEH (128*RSH)
#define STAGEH (4*TILEH)
#define SMEM_BYTES (2*STAGEH*2)   // 81920 B
__global__ void __launch_bounds__(256) mma_gemm(
    const ush* __restrict__ Ah, const ush* __restrict__ Al,
    const ush* __restrict__ Bh, const ush* __restrict__ Bl,
    float* __restrict__ C, int M, int N, int Kp,
    size_t sA, size_t sB, size_t sC,
    const float* __restrict__ biasRow, const float* __restrict__ biasCol,
    int statMode, double* __restrict__ statOut, int statC, int triSkip)
{
    if (triSkip && blockIdx.x < blockIdx.y) return;
    extern __shared__ ush sm[];
    const int tid = threadIdx.x;
    const int w = tid >> 5, lane = tid & 31;
    const int wm = w & 1, wn = w >> 1;
    const int m0 = blockIdx.y * 128, n0 = blockIdx.x * 128, b = blockIdx.z;
    const ush* srcs[4] = { Ah + (size_t)b*sA, Al + (size_t)b*sA,
                           Bh + (size_t)b*sB, Bl + (size_t)b*sB };
    const uint32_t smb = smem_u32(sm);

    float acc[4][4][4];
    #pragma unroll
    for (int i = 0; i < 4; i++)
        #pragma unroll
        for (int j = 0; j < 4; j++)
            #pragma unroll
            for (int q = 0; q < 4; q++) acc[i][j][q] = 0.f;

    const int T = Kp / KC;

    #define LOAD_STAGE(t, st) do { \
        int k0 = (t) * KC; \
        _Pragma("unroll") \
        for (int arr = 0; arr < 4; arr++) { \
            int r0 = (arr < 2) ? m0 : n0; \
            int rmax = (arr < 2) ? M : N; \
            const ush* S = srcs[arr]; \
            uint32_t dbase = smb + (uint32_t)(((st)*STAGEH + arr*TILEH) * 2); \
            _Pragma("unroll") \
            for (int i = 0; i < 2; i++) { \
                int e = tid + i * 256; \
                int r = e >> 2, c16 = e & 3; \
                uint32_t daddr = dbase + (uint32_t)((r * RSH + c16 * 8) * 2); \
                int rg = r0 + r; \
                int rc = rg < rmax ? rg : (rmax - 1); \
                const ush* sp = S + (size_t)rc * Kp + k0 + c16 * 8; \
                int sz = (rg < rmax) ? 16 : 0; \
                asm volatile("cp.async.cg.shared.global [%0], [%1], 16, %2;" \
                             :: "r"(daddr), "l"(sp), "r"(sz)); \
            } \
        } \
        asm volatile("cp.async.commit_group;" ::: "memory"); \
    } while (0)

    LOAD_STAGE(0, 0);
    for (int t = 0; t < T; t++) {
        const int st = t & 1;
        if (t + 1 < T) {
            LOAD_STAGE(t + 1, st ^ 1);
            asm volatile("cp.async.wait_group 1;" ::: "memory");
        } else {
            asm volatile("cp.async.wait_group 0;" ::: "memory");
        }
        __syncthreads();
        const uint32_t uAh = smb + (uint32_t)((st*STAGEH + 0*TILEH) * 2);
        const uint32_t uAl = smb + (uint32_t)((st*STAGEH + 1*TILEH) * 2);
        const uint32_t uBh = smb + (uint32_t)((st*STAGEH + 2*TILEH) * 2);
        const uint32_t uBl = smb + (uint32_t)((st*STAGEH + 3*TILEH) * 2);
        #pragma unroll
        for (int k16 = 0; k16 < 32; k16 += 16) {
            uint32_t ah[4][4], al[4][4], bh[4][2], bl[4][2];
            {
                int arow = wm * 64 + (lane & 15);
                int akk = k16 + ((lane >> 4) << 3);
                #pragma unroll
                for (int mf = 0; mf < 4; mf++) {
                    uint32_t byteoff = (uint32_t)(((arow + mf * 16) * RSH + akk) << 1);
                    ldm4(ah[mf], uAh + byteoff);
                    ldm4(al[mf], uAl + byteoff);
                }
                int q = lane >> 3;
                int brow0 = wn * 32 + ((q >> 1) << 3) + (lane & 7);
                int bkk = k16 + ((q & 1) << 3);
                #pragma unroll
                for (int p = 0; p < 2; p++) {
                    uint32_t byteoff = (uint32_t)(((brow0 + p * 16) * RSH + bkk) << 1);
                    uint32_t tmp[4];
                    ldm4(tmp, uBh + byteoff);
                    bh[2*p][0] = tmp[0]; bh[2*p][1] = tmp[1];
                    bh[2*p+1][0] = tmp[2]; bh[2*p+1][1] = tmp[3];
                    ldm4(tmp, uBl + byteoff);
                    bl[2*p][0] = tmp[0]; bl[2*p][1] = tmp[1];
                    bl[2*p+1][0] = tmp[2]; bl[2*p+1][1] = tmp[3];
                }
            }
            #pragma unroll
            for (int mf = 0; mf < 4; mf++)
                #pragma unroll
                for (int nf = 0; nf < 4; nf++)
                    mma16816(acc[mf][nf], ah[mf], bh[nf]);
            #pragma unroll
            for (int mf = 0; mf < 4; mf++)
                #pragma unroll
                for (int nf = 0; nf < 4; nf++)
                    mma16816(acc[mf][nf], ah[mf], bl[nf]);
            #pragma unroll
            for (int mf = 0; mf < 4; mf++)
                #pragma unroll
                for (int nf = 0; nf < 4; nf++)
                    mma16816(acc[mf][nf], al[mf], bh[nf]);
        }
        __syncthreads();
    }

    // epilogue: write C, accumulate per-thread stats partials
    float cs[8], cq[8];
    #pragma unroll
    for (int i = 0; i < 8; i++) { cs[i] = 0.f; cq[i] = 0.f; }
    float* Cb = C + (size_t)b * sC;
    #pragma unroll
    for (int mf = 0; mf < 4; mf++) {
        int r = m0 + wm * 64 + mf * 16 + (lane >> 2);
        float br0 = biasRow ? biasRow[r] : 0.f;
        float br1 = biasRow ? biasRow[r + 8] : 0.f;
        #pragma unroll
        for (int nf = 0; nf < 4; nf++) {
            int c = n0 + wn * 32 + nf * 8 + ((lane & 3) << 1);
            #pragma unroll
            for (int u = 0; u < 2; u++) {
                int col = c + u;
                float bc = (biasCol && col < N) ? biasCol[col] : 0.f;
                float v0 = acc[mf][nf][u]     + br0 + bc;
                float v1 = acc[mf][nf][u + 2] + br1 + bc;
                if (col < N) {
                    Cb[(size_t)r * N + col]       = v0;
                    Cb[(size_t)(r + 8) * N + col] = v1;
                }
                if (statMode == 1) {
                    cs[nf*2+u] += v0 + v1;
                    cq[nf*2+u] += v0*v0 + v1*v1;
                } else if (statMode == 2) {
                    cs[mf*2]   += v0; cq[mf*2]   += v0*v0;
                    cs[mf*2+1] += v1; cq[mf*2+1] += v1*v1;
                }
            }
        }
    }
    if (statMode == 0) return;
    float* ssum = (float*)sm;          // [128][16]
    float* ssq  = ssum + 2048;
    if (statMode == 1) {
        int g = wm * 8 + (lane >> 2);
        #pragma unroll
        for (int nf = 0; nf < 4; nf++)
            #pragma unroll
            for (int u = 0; u < 2; u++) {
                int colL = wn * 32 + nf * 8 + ((lane & 3) << 1) + u;
                ssum[colL * 16 + g] = cs[nf*2+u];
                ssq [colL * 16 + g] = cq[nf*2+u];
            }
        __syncthreads();
        if (tid < 128) {
            double s = 0.0, q = 0.0;
            #pragma unroll
            for (int g2 = 0; g2 < 16; g2++) { s += ssum[tid*16+g2]; q += ssq[tid*16+g2]; }
            int gcol = n0 + tid;
            if (gcol < N) {
                int chunk = blockIdx.z * gridDim.y + blockIdx.y;
                statOut[((size_t)chunk * statC + gcol) * 2]     = s;
                statOut[((size_t)chunk * statC + gcol) * 2 + 1] = q;
            }
        }
    } else {
        int h = wn * 4 + (lane & 3);
        #pragma unroll
        for (int mf = 0; mf < 4; mf++)
            #pragma unroll
            for (int hf = 0; hf < 2; hf++) {
                int rowL = wm * 64 + mf * 16 + (lane >> 2) + hf * 8;
                ssum[rowL * 16 + h] = cs[mf*2+hf];
                ssq [rowL * 16 + h] = cq[mf*2+hf];
            }
        __syncthreads();
        if (tid < 128) {
            double s = 0.0, q = 0.0;
            #pragma unroll
            for (int h2 = 0; h2 < 16; h2++) { s += ssum[tid*16+h2]; q += ssq[tid*16+h2]; }
            int grow = m0 + tid;
            int chunk = blockIdx.z * gridDim.x + blockIdx.x;
            statOut[((size_t)chunk * statC + grow) * 2]     = s;
            statOut[((size_t)chunk * statC + grow) * 2 + 1] = q;
        }
    }
}

// ---------------- elementwise / setup kernels ----------------
__global__ void sa_init() {
    int i = blockIdx.x * 256 + threadIdx.x;
    if (i < NQ) g_flags[i] = 0;
    if (i < BQ) g_acc[i] = 0.f;
}

__global__ void cv_split(const float* __restrict__ src, ush* __restrict__ dh, ush* __restrict__ dl,
                         long long total, int Ksrc, int Kp,
                         const float* __restrict__ sc, const float* __restrict__ sh, int leaky)
{
    long long i = (long long)blockIdx.x * 256 + threadIdx.x;
    if (i >= total) return;
    int c = (int)(i % Kp);
    long long r = i / Kp;
    float v = 0.f;
    if (c < Ksrc) {
        v = src[r * Ksrc + c];
        if (sc) { v = sc[c] * v + sh[c]; if (leaky && v < 0.f) v *= 0.2f; }
    }
    split_write(v, dh + i, dl + i);
}

__global__ void cv_agg(const float* __restrict__ points, const float* __restrict__ xyz) {
    long long i = (long long)blockIdx.x * 256 + threadIdx.x;
    if (i >= (long long)BQ*NQ*KP1) return;
    int c = (int)(i % KP1); long long r = i / KP1;
    int n = (int)(r % NQ); int b = (int)(r / NQ);
    float v = 0.f;
    if (c < DQ) v = points[((size_t)b*DQ + c)*NQ + n];
    else if (c < SCQ) v = xyz[((size_t)b*3 + (c-DQ))*NQ + n];
    split_write(v, g_aggc_h + i, g_aggc_l + i);
}

__global__ void sa_ball(const float* __restrict__ xyz) {
    int w = (blockIdx.x * blockDim.x + threadIdx.x) >> 5;
    int lane = threadIdx.x & 31;
    if (w >= BQ * NQ) return;
    int b = w / NQ, n = w % NQ;
    const float* X = xyz + (size_t)b * 3 * NQ;
    float px = X[n], py = X[NQ+n], pz = X[2*NQ+n];
    float pn = px*px + py*py + pz*pz;
    const float RR = (float)(0.2 * 0.2);
    int* out = g_idx + (size_t)b * NSQ * NQ + n;
    int cnt = 0;
    for (int j0 = 0; j0 < NQ && cnt < NSQ; j0 += 32) {
        int j = j0 + lane;
        float qx = X[j], qy = X[NQ+j], qz = X[2*NQ+j];
        float sq = (pn + qx*qx+qy*qy+qz*qz) - 2.0f*(px*qx+py*qy+pz*qz);
        bool in = !(sq > RR);
        unsigned m = __ballot_sync(0xffffffffu, in);
        int pos = cnt + __popc(m & ((1u << lane) - 1u));
        if (in && pos < NSQ) out[(size_t)pos * NQ] = j;
        cnt += __popc(m);
    }
    __syncwarp();
    if (lane == 0) {
        int first = out[0];
        for (int t = cnt; t < NSQ; t++) out[(size_t)t * NQ] = first;
    }
}

__global__ void sa_bmt_c(const float* __restrict__ points, const float* __restrict__ xyz) {
    int n = blockIdx.x * 256 + threadIdx.x;
    int j = blockIdx.y, b = blockIdx.z;
    float v;
    if (j < OFF_P) v = xyz[((size_t)b*3 + j)*NQ + n];
    else if (j < OFF_GP) v = points[((size_t)b*DQ + (j-OFF_P))*NQ + n];
    else if (j < OFF_GX) {
        int t = j - OFF_GP, k = t >> 6, d = t & 63;
        int ii = g_idx[((size_t)b*NSQ + k)*NQ + n];
        v = points[((size_t)b*DQ + d)*NQ + ii];
    } else {
        int t = j - OFF_GX, k = t / 3, c = t % 3;
        int ii = g_idx[((size_t)b*NSQ + k)*NQ + n];
        v = xyz[((size_t)b*3 + c)*NQ + ii];
    }
    size_t o = ((size_t)b*JQ + j)*NQ + n;
    split_write(v, g_BmTc_h + o, g_BmTc_l + o);
}

__global__ void sa_cs_fin(int C, int nChunks, int count,
                          const float* __restrict__ gamma, const float* __restrict__ beta,
                          float* __restrict__ sc, float* __restrict__ sf) {
    int c = blockIdx.x, tid = threadIdx.x;
    double s = 0.0, s2 = 0.0;
    for (int i = tid; i < nChunks; i += 256) {
        s  += g_part[((size_t)i * C + c) * 2];
        s2 += g_part[((size_t)i * C + c) * 2 + 1];
    }
    __shared__ double sa[256], sb2[256];
    sa[tid] = s; sb2[tid] = s2; __syncthreads();
    for (int o = 128; o > 0; o >>= 1) {
        if (tid < o) { sa[tid] += sa[tid+o]; sb2[tid] += sb2[tid+o]; }
        __syncthreads();
    }
    if (tid == 0) {
        double n = (double)count, m = sa[0] / n;
        double var = sb2[0] / n - m * m; if (var < 0.0) var = 0.0;
        float scale = gamma[c] * rsqrtf((float)var + 1e-5f);
        sc[c] = scale; sf[c] = beta[c] - (float)m * scale;
    }
}

__global__ void sa_softmax(float* __restrict__ H) {
    int s = blockIdx.x, b = blockIdx.y, tid = threadIdx.x;
    float* row = H + ((size_t)b * SQ + s) * NQ;
    __shared__ float buf[NQ];
    __shared__ float red[256], rv[256];
    __shared__ int ri[256];
    float a = g_s2[s], sh = g_sh2[s];
    float lmax = -3.4e38f;
    for (int i = tid; i < NQ; i += 256) { float y = a*row[i]+sh; buf[i] = y; lmax = fmaxf(lmax, y); }
    red[tid] = lmax; __syncthreads();
    for (int o = 128; o > 0; o >>= 1) { if (tid < o) red[tid] = fmaxf(red[tid], red[tid+o]); __syncthreads(); }
    float gmax = red[0]; __syncthreads();
    float lsum = 0.f;
    for (int i = tid; i < NQ; i += 256) { float e = expf(buf[i]-gmax); buf[i] = e; lsum += e; }
    red[tid] = lsum; __syncthreads();
    for (int o = 128; o > 0; o >>= 1) { if (tid < o) red[tid] += red[tid+o]; __syncthreads(); }
    float inv = 1.f / red[0]; __syncthreads();
    float lss = 0.f, bm = -1.f; int bi = 0;
    size_t rowoff = ((size_t)b * SQ + s) * NQ;
    for (int i = tid; i < NQ; i += 256) {
        float v = buf[i] * inv; row[i] = v; lss += v*v;
        split_write(v, g_Sc_h + rowoff + i, g_Sc_l + rowoff + i);
        if (v > bm) { bm = v; bi = i; }
    }
    red[tid] = lss; rv[tid] = bm; ri[tid] = bi; __syncthreads();
    for (int o = 128; o > 0; o >>= 1) {
        if (tid < o) {
            red[tid] += red[tid+o];
            if (rv[tid+o] > rv[tid] || (rv[tid+o] == rv[tid] && ri[tid+o] < ri[tid])) { rv[tid] = rv[tid+o]; ri[tid] = ri[tid+o]; }
        }
        __syncthreads();
    }
    if (tid == 0) {
        g_norm[b*SQ+s] = sqrtf(red[0]);
        if (b == 0) g_amax[s] = ri[0];
    }
}

__global__ void sa_flags() { int s = blockIdx.x*256 + threadIdx.x; if (s < SQ) g_flags[g_amax[s]] = 1; }

// upper triangle only (c > r), weighted 2x (matrix symmetric)
__global__ void sa_cos_epi() {
    size_t i = (size_t)blockIdx.x * 256 + threadIdx.x;
    int b = (int)(i / ((size_t)SQ*SQ)), r = (int)((i / SQ) % SQ), c = (int)(i % SQ);
    float v = 0.f;
    if (c > r) {
        float cm = g_inner[i] / (g_norm[b*SQ+r] * g_norm[b*SQ+c] + 1e-10f);
        v = 2.f * cm * cm;
    }
    __shared__ float red[256];
    red[threadIdx.x] = v; __syncthreads();
    for (int o = 128; o > 0; o >>= 1) { if (threadIdx.x < o) red[threadIdx.x] += red[threadIdx.x+o]; __syncthreads(); }
    if (threadIdx.x == 0) atomicAdd(&g_acc[b], red[0]);
}

__global__ void sa_newxyz(float* __restrict__ out) {
    int i = blockIdx.x * 256 + threadIdx.x;
    if (i >= BQ*3*SQ) return;
    int s = i % SQ, c = (i/SQ) % 3, b = i/(3*SQ);
    out[i] = g_Cbig[((size_t)b*SQ + s)*JQ + OFF_X + c];
}

__global__ void sa_et_c() {
    int r = blockIdx.x, b = blockIdx.y, ch = threadIdx.x;
    int s = r % SQ, k = r / SQ;
    const float* Cr = g_Cbig + ((size_t)b*SQ + s)*JQ;
    float v = 0.f;
    if (ch < 64) v = Cr[OFF_P + ch];
    else if (ch < 128) { int d = ch - 64; v = Cr[OFF_GP + k*DQ + d] - Cr[OFF_P + d]; }
    else if (ch < 131) v = Cr[OFF_X + (ch - 128)];
    else if (ch < INCH) { int c3 = ch - 131; v = Cr[OFF_GX + k*3 + c3] - Cr[OFF_X + c3]; }
    size_t o = ((size_t)b*KSQ + r)*KPE + ch;
    split_write(v, g_ETc_h + o, g_ETc_l + o);
}

__global__ void sa_max(float* __restrict__ out) {
    int s = blockIdx.x, b = blockIdx.y, o = threadIdx.x;
    float sc = g_sc2[o], sf = g_sf2[o];
    float m = -3.4e38f;
    const float* base = g_O2T + ((size_t)b*KSQ + s)*C2Q + o;
    #pragma unroll
    for (int k = 0; k < NSQ; k++) {
        float y = sc * base[(size_t)k*SQ*C2Q] + sf;
        y = (y >= 0.f) ? y : 0.2f * y;
        m = fmaxf(m, y);
    }
    out[XYZ_OUT + ((size_t)b*C2Q + o)*SQ + s] = m;
}

__global__ void sa_scalars(float* __restrict__ out) {
    __shared__ float sfr[256]; __shared__ int sir[256];
    int tid = threadIdx.x;
    int cnt = 0;
    for (int i = tid; i < NQ; i += 256) cnt += g_flags[i];
    float l = (tid < BQ) ? sqrtf(g_acc[tid]) : 0.f;
    sfr[tid] = l; sir[tid] = cnt; __syncthreads();
    for (int o = 128; o > 0; o >>= 1) {
        if (tid < o) { sfr[tid] += sfr[tid+o]; sir[tid] += sir[tid+o]; }
        __syncthreads();
    }
    if (tid == 0) {
        out[XYZ_OUT + NP_OUT] = sfr[0] / (float)BQ;
        out[XYZ_OUT + NP_OUT + 1] = (float)sir[0];
    }
}

// ---------------- launch ----------------
static inline float*  symf(const void* sym) { void* p = nullptr; cudaGetSymbolAddress(&p, sym); return (float*)p; }
static inline ush*    symu(const void* sym) { void* p = nullptr; cudaGetSymbolAddress(&p, sym); return (ush*)p; }
static inline double* symd(const void* sym) { void* p = nullptr; cudaGetSymbolAddress(&p, sym); return (double*)p; }

extern "C" void kernel_launch(void* const* d_in, const int* in_sizes, int n_in,
                              void* d_out, int out_size)
{
    const float* xyz   = (const float*)d_in[0];
    const float* points= (const float*)d_in[1];
    const float* w1_w = (const float*)d_in[2];
    const float* w1_b = (const float*)d_in[3];
    const float* bn1g = (const float*)d_in[4];
    const float* bn1b = (const float*)d_in[5];
    const float* w2_w = (const float*)d_in[6];
    const float* w2_b = (const float*)d_in[7];
    const float* bn2g = (const float*)d_in[8];
    const float* bn2b = (const float*)d_in[9];
    const float* c0w = (const float*)d_in[10];
    const float* c0b = (const float*)d_in[11];
    const float* g0  = (const float*)d_in[12];
    const float* b0  = (const float*)d_in[13];
    const float* c1w = (const float*)d_in[14];
    const float* c1b = (const float*)d_in[15];
    const float* g1  = (const float*)d_in[16];
    const float* b1  = (const float*)d_in[17];
    const float* c2w = (const float*)d_in[18];
    const float* c2b = (const float*)d_in[19];
    const float* g2  = (const float*)d_in[20];
    const float* b2  = (const float*)d_in[21];
    float* out = (float*)d_out;

    static bool attr = false;
    if (!attr) {
        cudaFuncSetAttribute(mma_gemm, cudaFuncAttributeMaxDynamicSharedMemorySize, SMEM_BYTES);
        attr = true;
    }

    float* p_h1t = symf(g_h1t);
    float* p_h2  = symf(g_h2);
    float* p_inner = symf(g_inner);
    float* p_C   = symf(g_Cbig);
    float* p_O0  = symf(g_O0T);
    float* p_O1  = symf(g_O1T);
    float* p_O2  = symf(g_O2T);
    double* p_part = symd(g_part);
    float* p_s1 = symf(g_s1), *p_sh1 = symf(g_sh1);
    float* p_s2 = symf(g_s2), *p_sh2 = symf(g_sh2);
    float* p_sc0 = symf(g_sc0), *p_sf0 = symf(g_sf0);
    float* p_sc1 = symf(g_sc1), *p_sf1 = symf(g_sf1);
    float* p_sc2 = symf(g_sc2), *p_sf2 = symf(g_sf2);
    ush *aggh = symu(g_aggc_h), *aggl = symu(g_aggc_l);
    ush *w1h = symu(g_w1c_h), *w1l = symu(g_w1c_l);
    ush *h1h = symu(g_h1c_h), *h1l = symu(g_h1c_l);
    ush *w2h = symu(g_w2c_h), *w2l = symu(g_w2c_l);
    ush *Sh = symu(g_Sc_h), *Sl = symu(g_Sc_l);
    ush *Bmh = symu(g_BmTc_h), *Bml = symu(g_BmTc_l);
    ush *Eh = symu(g_ETc_h), *El = symu(g_ETc_l);
    ush *w0h = symu(g_c0wc_h), *w0l = symu(g_c0wc_l);
    ush *c1h = symu(g_c1wc_h), *c1l = symu(g_c1wc_l);
    ush *c2h = symu(g_c2wc_h), *c2l = symu(g_c2wc_l);
    ush *O0h = symu(g_O0c_h), *O0l = symu(g_O0c_l);
    ush *O1h = symu(g_O1c_h), *O1l = symu(g_O1c_l);

    sa_init<<<9, 256>>>();
    cv_agg<<<(int)(((long long)BQ*NQ*KP1 + 255)/256), 256>>>(points, xyz);
    cv_split<<<(SCQ*KP1 + 255)/256, 256>>>(w1_w, w1h, w1l, (long long)SCQ*KP1, SCQ, KP1, nullptr, nullptr, 0);
    cv_split<<<(SQ*KP1 + 255)/256, 256>>>(w2_w, w2h, w2l, (long long)SQ*KP1, SCQ, KP1, nullptr, nullptr, 0);
    cv_split<<<(C0Q*KPE + 255)/256, 256>>>(c0w, w0h, w0l, (long long)C0Q*KPE, INCH, KPE, nullptr, nullptr, 0);
    cv_split<<<(C1Q*C0Q + 255)/256, 256>>>(c1w, c1h, c1l, (long long)C1Q*C0Q, C0Q, C0Q, nullptr, nullptr, 0);
    cv_split<<<(C2Q*C1Q + 255)/256, 256>>>(c2w, c2h, c2l, (long long)C2Q*C1Q, C1Q, C1Q, nullptr, nullptr, 0);
    sa_ball<<<(BQ*NQ*32)/256, 256>>>(xyz);
    sa_bmt_c<<<dim3(NQ/256, JQ, BQ), 256>>>(points, xyz);

    // h1t = aggT * w1^T + w1_b ; col-stats fused (chunks = 16*16 = 256)
    mma_gemm<<<dim3(1, NQ/128, BQ), 256, SMEM_BYTES>>>(aggh, aggl, w1h, w1l, p_h1t,
        NQ, SCQ, KP1, (size_t)NQ*KP1, 0, (size_t)NQ*SCQ, nullptr, w1_b, 1, p_part, SCQ, 0);
    sa_cs_fin<<<SCQ, 256>>>(SCQ, BQ*(NQ/128), BQ*NQ, bn1g, bn1b, p_s1, p_sh1);
    cv_split<<<(int)(((long long)BQ*NQ*KP1 + 255)/256), 256>>>(p_h1t, h1h, h1l,
        (long long)BQ*NQ*KP1, SCQ, KP1, p_s1, p_sh1, 0);

    // h2 = w2 * bn1(h1)^T + w2_b ; row-stats fused (chunks = 16*16 = 256)
    mma_gemm<<<dim3(NQ/128, SQ/128, BQ), 256, SMEM_BYTES>>>(w2h, w2l, h1h, h1l, p_h2,
        SQ, NQ, KP1, 0, (size_t)NQ*KP1, (size_t)SQ*NQ, w2_b, nullptr, 2, p_part, SQ, 0);
    sa_cs_fin<<<SQ, 256>>>(SQ, BQ*(NQ/128), BQ*NQ, bn2g, bn2b, p_s2, p_sh2);
    sa_softmax<<<dim3(SQ, BQ), 256>>>(p_h2);
    sa_flags<<<2, 256>>>();

    // inner = S S^T (upper-triangle tiles only)
    mma_gemm<<<dim3(SQ/128, SQ/128, BQ), 256, SMEM_BYTES>>>(Sh, Sl, Sh, Sl, p_inner,
        SQ, SQ, NQ, (size_t)SQ*NQ, (size_t)SQ*NQ, (size_t)SQ*SQ, nullptr, nullptr, 0, nullptr, 0, 1);
    sa_cos_epi<<<(int)(((size_t)BQ*SQ*SQ)/256), 256>>>();

    // Cbig = S * BmT^T
    mma_gemm<<<dim3((JQ+127)/128, SQ/128, BQ), 256, SMEM_BYTES>>>(Sh, Sl, Bmh, Bml, p_C,
        SQ, JQ, NQ, (size_t)SQ*NQ, (size_t)JQ*NQ, (size_t)SQ*JQ, nullptr, nullptr, 0, nullptr, 0, 0);
    sa_newxyz<<<(BQ*3*SQ + 255)/256, 256>>>(out);
    sa_et_c<<<dim3(KSQ, BQ), KPE>>>();

    // conv stack (transposed outputs); col-stats fused (chunks = 128*16 = 2048)
    mma_gemm<<<dim3(1, KSQ/128, BQ), 256, SMEM_BYTES>>>(Eh, El, w0h, w0l, p_O0,
        KSQ, C0Q, KPE, (size_t)KSQ*KPE, 0, (size_t)KSQ*C0Q, nullptr, c0b, 1, p_part, C0Q, 0);
    sa_cs_fin<<<C0Q, 256>>>(C0Q, BQ*(KSQ/128), BQ*KSQ, g0, b0, p_sc0, p_sf0);
    cv_split<<<(int)(((long long)BQ*KSQ*C0Q + 255)/256), 256>>>(p_O0, O0h, O0l,
        (long long)BQ*KSQ*C0Q, C0Q, C0Q, p_sc0, p_sf0, 1);

    mma_gemm<<<dim3(1, KSQ/128, BQ), 256, SMEM_BYTES>>>(O0h, O0l, c1h, c1l, p_O1,
        KSQ, C1Q, C0Q, (size_t)KSQ*C0Q, 0, (size_t)KSQ*C1Q, nullptr, c1b, 1, p_part, C1Q, 0);
    sa_cs_fin<<<C1Q, 256>>>(C1Q, BQ*(KSQ/128), BQ*KSQ, g1, b1, p_sc1, p_sf1);
    cv_split<<<(int)(((long long)BQ*KSQ*C1Q + 255)/256), 256>>>(p_O1, O1h, O1l,
        (long long)BQ*KSQ*C1Q, C1Q, C1Q, p_sc1, p_sf1, 1);

    mma_gemm<<<dim3(C2Q/128, KSQ/128, BQ), 256, SMEM_BYTES>>>(O1h, O1l, c2h, c2l, p_O2,
        KSQ, C2Q, C1Q, (size_t)KSQ*C1Q, 0, (size_t)KSQ*C2Q, nullptr, c2b, 1, p_part, C2Q, 0);
    sa_cs_fin<<<C2Q, 256>>>(C2Q, BQ*(KSQ/128), BQ*KSQ, g2, b2, p_sc2, p_sf2);

    sa_max<<<dim3(SQ, BQ), 256>>>(out);
    sa_scalars<<<1, 256>>>(out);
}

// round 8
// speedup vs baseline: 1.7199x; 1.1237x over previous
#include <cuda_runtime.h>
#include <cuda_bf16.h>
#include <math.h>
#include <stdint.h>

#define BQ 16
#define NQ 2048
#define DQ 64
#define SQ 512
#define NSQ 32
#define SCQ 67
#define INCH 134
#define C0Q 128
#define C1Q 128
#define C2Q 256
#define KSQ (NSQ*SQ)
#define JQ (3+DQ+NSQ*DQ+NSQ*3)   // 2211
#define OFF_X 0
#define OFF_P 3
#define OFF_GP 67
#define OFF_GX 2115
#define XYZ_OUT (BQ*3*SQ)
#define NP_OUT  ((size_t)BQ*C2Q*SQ)
#define KP1 96
#define KPE 160

typedef unsigned short ush;

// ---------------- fp32 scratch ----------------
__device__ float g_h1t [(size_t)BQ*NQ*SCQ];
__device__ float g_h2  [(size_t)BQ*SQ*NQ];
__device__ float g_Cbig[(size_t)BQ*SQ*JQ];
__device__ float g_O0T [(size_t)BQ*KSQ*C0Q];
__device__ float g_O1T [(size_t)BQ*KSQ*C1Q];
__device__ float g_O2T [(size_t)BQ*KSQ*C2Q];
__device__ float g_norm[BQ*SQ];
__device__ int   g_amax[SQ];
__device__ int   g_idx[(size_t)BQ*NSQ*NQ];
__device__ double g_part[(size_t)2048*256*2];
__device__ float g_s1[SCQ], g_sh1[SCQ];
__device__ float g_s2[SQ],  g_sh2[SQ];
__device__ float g_sc0[C0Q], g_sf0[C0Q];
__device__ float g_sc1[C1Q], g_sf1[C1Q];
__device__ float g_sc2[C2Q], g_sf2[C2Q];
__device__ float g_acc[BQ];
__device__ int   g_flags[NQ];

// ---------------- bf16 hi/lo operand arrays ----------------
__device__ ush g_aggc_h[(size_t)BQ*NQ*KP1],  g_aggc_l[(size_t)BQ*NQ*KP1];
__device__ ush g_w1c_h[SCQ*KP1],             g_w1c_l[SCQ*KP1];
__device__ ush g_h1c_h[(size_t)BQ*NQ*KP1],   g_h1c_l[(size_t)BQ*NQ*KP1];
__device__ ush g_w2c_h[SQ*KP1],              g_w2c_l[SQ*KP1];
__device__ ush g_Sc_h[(size_t)BQ*SQ*NQ],     g_Sc_l[(size_t)BQ*SQ*NQ];
__device__ ush g_BmTc_h[(size_t)BQ*JQ*NQ],   g_BmTc_l[(size_t)BQ*JQ*NQ];
__device__ ush g_ETc_h[(size_t)BQ*KSQ*KPE],  g_ETc_l[(size_t)BQ*KSQ*KPE];
__device__ ush g_c0wc_h[C0Q*KPE],            g_c0wc_l[C0Q*KPE];
__device__ ush g_c1wc_h[C1Q*C0Q],            g_c1wc_l[C1Q*C0Q];
__device__ ush g_c2wc_h[C2Q*C1Q],            g_c2wc_l[C2Q*C1Q];
__device__ ush g_O0c_h[(size_t)BQ*KSQ*C0Q],  g_O0c_l[(size_t)BQ*KSQ*C0Q];
__device__ ush g_O1c_h[(size_t)BQ*KSQ*C1Q],  g_O1c_l[(size_t)BQ*KSQ*C1Q];

// ---------------- helpers ----------------
__device__ __forceinline__ uint32_t smem_u32(const void* p) {
    uint32_t a;
    asm("{ .reg .u64 t; cvta.to.shared.u64 t, %1; cvt.u32.u64 %0, t; }" : "=r"(a) : "l"(p));
    return a;
}
__device__ __forceinline__ void ldm4(uint32_t* r, uint32_t addr) {
    asm volatile("ldmatrix.sync.aligned.m8n8.x4.shared.b16 {%0,%1,%2,%3}, [%4];"
        : "=r"(r[0]), "=r"(r[1]), "=r"(r[2]), "=r"(r[3]) : "r"(addr));
}
__device__ __forceinline__ void mma16816(float* c, const uint32_t* a, const uint32_t* b) {
    asm volatile("mma.sync.aligned.m16n8k16.row.col.f32.bf16.bf16.f32 "
        "{%0,%1,%2,%3}, {%4,%5,%6,%7}, {%8,%9}, {%0,%1,%2,%3};"
        : "+f"(c[0]), "+f"(c[1]), "+f"(c[2]), "+f"(c[3])
        : "r"(a[0]), "r"(a[1]), "r"(a[2]), "r"(a[3]), "r"(b[0]), "r"(b[1]));
}
__device__ __forceinline__ uint32_t split_pack(float v0, float v1, uint32_t* lo) {
    __nv_bfloat16 h0 = __float2bfloat16(v0), h1 = __float2bfloat16(v1);
    __nv_bfloat16 l0 = __float2bfloat16(v0 - __bfloat162float(h0));
    __nv_bfloat16 l1 = __float2bfloat16(v1 - __bfloat162float(h1));
    *lo = ((uint32_t)__bfloat16_as_ushort(l1) << 16) | __bfloat16_as_ushort(l0);
    return ((uint32_t)__bfloat16_as_ushort(h1) << 16) | __bfloat16_as_ushort(h0);
}
__device__ __forceinline__ void split_write(float v, ush* ph, ush* pl) {
    __nv_bfloat16 h = __float2bfloat16(v);
    __nv_bfloat16 l = __float2bfloat16(v - __bfloat162float(h));
    *ph = __bfloat16_as_ushort(h);
    *pl = __bfloat16_as_ushort(l);
}

// ---------------- pipelined HMMA GEMM (2-stage) with fused BN-stats / cos epilogues ----
// C[b](MxN) = A[b](MxKp) * B[b](NxKp)^T ; operands pre-split bf16 hi/lo.
// statMode: 0 none, 1 column stats (channels = N), 2 row stats (channels = M).
// triSkip: skip CTAs with blockIdx.x < blockIdx.y. cosMode: no C write; fused cosine-loss.
#define KC 32
#define RSH 40
#define TILEH (128*RSH)
#define STAGEH (4*TILEH)
#define SMEM_BYTES (2*STAGEH*2)   // 81920 B
__global__ void __launch_bounds__(256) mma_gemm(
    const ush* __restrict__ Ah, const ush* __restrict__ Al,
    const ush* __restrict__ Bh, const ush* __restrict__ Bl,
    float* __restrict__ C, int M, int N, int Kp,
    size_t sA, size_t sB, size_t sC,
    const float* __restrict__ biasRow, const float* __restrict__ biasCol,
    int statMode, double* __restrict__ statOut, int statC, int triSkip, int cosMode)
{
    if (triSkip && blockIdx.x < blockIdx.y) return;
    extern __shared__ ush sm[];
    const int tid = threadIdx.x;
    const int w = tid >> 5, lane = tid & 31;
    const int wm = w & 1, wn = w >> 1;
    const int m0 = blockIdx.y * 128, n0 = blockIdx.x * 128, b = blockIdx.z;
    const ush* srcs[4] = { Ah + (size_t)b*sA, Al + (size_t)b*sA,
                           Bh + (size_t)b*sB, Bl + (size_t)b*sB };
    const uint32_t smb = smem_u32(sm);

    float acc[4][4][4];
    #pragma unroll
    for (int i = 0; i < 4; i++)
        #pragma unroll
        for (int j = 0; j < 4; j++)
            #pragma unroll
            for (int q = 0; q < 4; q++) acc[i][j][q] = 0.f;

    const int T = Kp / KC;

    #define LOAD_STAGE(t, st) do { \
        int k0 = (t) * KC; \
        _Pragma("unroll") \
        for (int arr = 0; arr < 4; arr++) { \
            int r0 = (arr < 2) ? m0 : n0; \
            int rmax = (arr < 2) ? M : N; \
            const ush* S = srcs[arr]; \
            uint32_t dbase = smb + (uint32_t)(((st)*STAGEH + arr*TILEH) * 2); \
            _Pragma("unroll") \
            for (int i = 0; i < 2; i++) { \
                int e = tid + i * 256; \
                int r = e >> 2, c16 = e & 3; \
                uint32_t daddr = dbase + (uint32_t)((r * RSH + c16 * 8) * 2); \
                int rg = r0 + r; \
                int rc = rg < rmax ? rg : (rmax - 1); \
                const ush* sp = S + (size_t)rc * Kp + k0 + c16 * 8; \
                int sz = (rg < rmax) ? 16 : 0; \
                asm volatile("cp.async.cg.shared.global [%0], [%1], 16, %2;" \
                             :: "r"(daddr), "l"(sp), "r"(sz)); \
            } \
        } \
        asm volatile("cp.async.commit_group;" ::: "memory"); \
    } while (0)

    LOAD_STAGE(0, 0);
    for (int t = 0; t < T; t++) {
        const int st = t & 1;
        if (t + 1 < T) {
            LOAD_STAGE(t + 1, st ^ 1);
            asm volatile("cp.async.wait_group 1;" ::: "memory");
        } else {
            asm volatile("cp.async.wait_group 0;" ::: "memory");
        }
        __syncthreads();
        const uint32_t uAh = smb + (uint32_t)((st*STAGEH + 0*TILEH) * 2);
        const uint32_t uAl = smb + (uint32_t)((st*STAGEH + 1*TILEH) * 2);
        const uint32_t uBh = smb + (uint32_t)((st*STAGEH + 2*TILEH) * 2);
        const uint32_t uBl = smb + (uint32_t)((st*STAGEH + 3*TILEH) * 2);
        #pragma unroll
        for (int k16 = 0; k16 < 32; k16 += 16) {
            uint32_t ah[4][4], al[4][4], bh[4][2], bl[4][2];
            {
                int arow = wm * 64 + (lane & 15);
                int akk = k16 + ((lane >> 4) << 3);
                #pragma unroll
                for (int mf = 0; mf < 4; mf++) {
                    uint32_t byteoff = (uint32_t)(((arow + mf * 16) * RSH + akk) << 1);
                    ldm4(ah[mf], uAh + byteoff);
                    ldm4(al[mf], uAl + byteoff);
                }
                int q = lane >> 3;
                int brow0 = wn * 32 + ((q >> 1) << 3) + (lane & 7);
                int bkk = k16 + ((q & 1) << 3);
                #pragma unroll
                for (int p = 0; p < 2; p++) {
                    uint32_t byteoff = (uint32_t)(((brow0 + p * 16) * RSH + bkk) << 1);
                    uint32_t tmp[4];
                    ldm4(tmp, uBh + byteoff);
                    bh[2*p][0] = tmp[0]; bh[2*p][1] = tmp[1];
                    bh[2*p+1][0] = tmp[2]; bh[2*p+1][1] = tmp[3];
                    ldm4(tmp, uBl + byteoff);
                    bl[2*p][0] = tmp[0]; bl[2*p][1] = tmp[1];
                    bl[2*p+1][0] = tmp[2]; bl[2*p+1][1] = tmp[3];
                }
            }
            #pragma unroll
            for (int mf = 0; mf < 4; mf++)
                #pragma unroll
                for (int nf = 0; nf < 4; nf++)
                    mma16816(acc[mf][nf], ah[mf], bh[nf]);
            #pragma unroll
            for (int mf = 0; mf < 4; mf++)
                #pragma unroll
                for (int nf = 0; nf < 4; nf++)
                    mma16816(acc[mf][nf], ah[mf], bl[nf]);
            #pragma unroll
            for (int mf = 0; mf < 4; mf++)
                #pragma unroll
                for (int nf = 0; nf < 4; nf++)
                    mma16816(acc[mf][nf], al[mf], bh[nf]);
        }
        __syncthreads();
    }

    if (cosMode) {
        // fused cosine-loss epilogue: sum 2*cm^2 over strictly-upper elements
        const float* nb = g_norm + b * SQ;
        float part = 0.f;
        #pragma unroll
        for (int mf = 0; mf < 4; mf++) {
            int r = m0 + wm * 64 + mf * 16 + (lane >> 2);
            float nr0 = nb[r], nr1 = nb[r + 8];
            #pragma unroll
            for (int nf = 0; nf < 4; nf++) {
                #pragma unroll
                for (int u = 0; u < 2; u++) {
                    int col = n0 + wn * 32 + nf * 8 + ((lane & 3) << 1) + u;
                    float ncv = nb[col];
                    if (col > r) {
                        float cm = acc[mf][nf][u] / (nr0 * ncv + 1e-10f);
                        part += 2.f * cm * cm;
                    }
                    if (col > r + 8) {
                        float cm = acc[mf][nf][u + 2] / (nr1 * ncv + 1e-10f);
                        part += 2.f * cm * cm;
                    }
                }
            }
        }
        float* red = (float*)sm;
        red[tid] = part; __syncthreads();
        for (int off = 128; off > 0; off >>= 1) {
            if (tid < off) red[tid] += red[tid + off];
            __syncthreads();
        }
        if (tid == 0) atomicAdd(&g_acc[b], red[0]);
        return;
    }

    // epilogue: write C, accumulate per-thread stats partials
    float cs[8], cq[8];
    #pragma unroll
    for (int i = 0; i < 8; i++) { cs[i] = 0.f; cq[i] = 0.f; }
    float* Cb = C + (size_t)b * sC;
    #pragma unroll
    for (int mf = 0; mf < 4; mf++) {
        int r = m0 + wm * 64 + mf * 16 + (lane >> 2);
        float br0 = biasRow ? biasRow[r] : 0.f;
        float br1 = biasRow ? biasRow[r + 8] : 0.f;
        #pragma unroll
        for (int nf = 0; nf < 4; nf++) {
            int c = n0 + wn * 32 + nf * 8 + ((lane & 3) << 1);
            #pragma unroll
            for (int u = 0; u < 2; u++) {
                int col = c + u;
                float bc = (biasCol && col < N) ? biasCol[col] : 0.f;
                float v0 = acc[mf][nf][u]     + br0 + bc;
                float v1 = acc[mf][nf][u + 2] + br1 + bc;
                if (col < N) {
                    Cb[(size_t)r * N + col]       = v0;
                    Cb[(size_t)(r + 8) * N + col] = v1;
                }
                if (statMode == 1) {
                    cs[nf*2+u] += v0 + v1;
                    cq[nf*2+u] += v0*v0 + v1*v1;
                } else if (statMode == 2) {
                    cs[mf*2]   += v0; cq[mf*2]   += v0*v0;
                    cs[mf*2+1] += v1; cq[mf*2+1] += v1*v1;
                }
            }
        }
    }
    if (statMode == 0) return;
    float* ssum = (float*)sm;          // [128][16]
    float* ssq  = ssum + 2048;
    if (statMode == 1) {
        int g = wm * 8 + (lane >> 2);
        #pragma unroll
        for (int nf = 0; nf < 4; nf++)
            #pragma unroll
            for (int u = 0; u < 2; u++) {
                int colL = wn * 32 + nf * 8 + ((lane & 3) << 1) + u;
                ssum[colL * 16 + g] = cs[nf*2+u];
                ssq [colL * 16 + g] = cq[nf*2+u];
            }
        __syncthreads();
        if (tid < 128) {
            double s = 0.0, q = 0.0;
            #pragma unroll
            for (int g2 = 0; g2 < 16; g2++) { s += ssum[tid*16+g2]; q += ssq[tid*16+g2]; }
            int gcol = n0 + tid;
            if (gcol < N) {
                int chunk = blockIdx.z * gridDim.y + blockIdx.y;
                statOut[((size_t)chunk * statC + gcol) * 2]     = s;
                statOut[((size_t)chunk * statC + gcol) * 2 + 1] = q;
            }
        }
    } else {
        int h = wn * 4 + (lane & 3);
        #pragma unroll
        for (int mf = 0; mf < 4; mf++)
            #pragma unroll
            for (int hf = 0; hf < 2; hf++) {
                int rowL = wm * 64 + mf * 16 + (lane >> 2) + hf * 8;
                ssum[rowL * 16 + h] = cs[mf*2+hf];
                ssq [rowL * 16 + h] = cq[mf*2+hf];
            }
        __syncthreads();
        if (tid < 128) {
            double s = 0.0, q = 0.0;
            #pragma unroll
            for (int h2 = 0; h2 < 16; h2++) { s += ssum[tid*16+h2]; q += ssq[tid*16+h2]; }
            int grow = m0 + tid;
            int chunk = blockIdx.z * gridDim.x + blockIdx.x;
            statOut[((size_t)chunk * statC + grow) * 2]     = s;
            statOut[((size_t)chunk * statC + grow) * 2 + 1] = q;
        }
    }
}

// ---------------- elementwise / setup kernels ----------------
__global__ void sa_init() {
    int i = blockIdx.x * 256 + threadIdx.x;
    if (i < NQ) g_flags[i] = 0;
    if (i < BQ) g_acc[i] = 0.f;
}

// paired fp32 -> bf16 hi/lo split, vectorized ush2 stores; Kp even
__global__ void cv_split(const float* __restrict__ src, ush* __restrict__ dh, ush* __restrict__ dl,
                         long long totalPairs, int Ksrc, int Kp,
                         const float* __restrict__ sc, const float* __restrict__ sh, int leaky)
{
    long long i = (long long)blockIdx.x * 256 + threadIdx.x;
    if (i >= totalPairs) return;
    long long e = i * 2;
    int c = (int)(e % Kp);
    long long r = e / Kp;
    float v0 = 0.f, v1 = 0.f;
    if (c < Ksrc) {
        v0 = src[r * Ksrc + c];
        if (sc) { v0 = sc[c]*v0 + sh[c]; if (leaky && v0 < 0.f) v0 *= 0.2f; }
    }
    if (c + 1 < Ksrc) {
        v1 = src[r * Ksrc + c + 1];
        if (sc) { v1 = sc[c+1]*v1 + sh[c+1]; if (leaky && v1 < 0.f) v1 *= 0.2f; }
    }
    uint32_t lw, hw = split_pack(v0, v1, &lw);
    ((uint32_t*)dh)[i] = hw;
    ((uint32_t*)dl)[i] = lw;
}

__global__ void cv_agg(const float* __restrict__ points, const float* __restrict__ xyz) {
    long long i = (long long)blockIdx.x * 256 + threadIdx.x;
    if (i >= (long long)BQ*NQ*KP1/2) return;
    long long e = i * 2;
    int c = (int)(e % KP1); long long r = e / KP1;
    int n = (int)(r % NQ); int b = (int)(r / NQ);
    float v0 = 0.f, v1 = 0.f;
    if (c < DQ) v0 = points[((size_t)b*DQ + c)*NQ + n];
    else if (c < SCQ) v0 = xyz[((size_t)b*3 + (c-DQ))*NQ + n];
    int c1 = c + 1;
    if (c1 < DQ) v1 = points[((size_t)b*DQ + c1)*NQ + n];
    else if (c1 < SCQ) v1 = xyz[((size_t)b*3 + (c1-DQ))*NQ + n];
    uint32_t lw, hw = split_pack(v0, v1, &lw);
    ((uint32_t*)g_aggc_h)[i] = hw;
    ((uint32_t*)g_aggc_l)[i] = lw;
}

__global__ void sa_ball(const float* __restrict__ xyz) {
    int w = (blockIdx.x * blockDim.x + threadIdx.x) >> 5;
    int lane = threadIdx.x & 31;
    if (w >= BQ * NQ) return;
    int b = w / NQ, n = w % NQ;
    const float* X = xyz + (size_t)b * 3 * NQ;
    float px = X[n], py = X[NQ+n], pz = X[2*NQ+n];
    float pn = px*px + py*py + pz*pz;
    const float RR = (float)(0.2 * 0.2);
    int* out = g_idx + (size_t)b * NSQ * NQ + n;
    int cnt = 0;
    for (int j0 = 0; j0 < NQ && cnt < NSQ; j0 += 32) {
        int j = j0 + lane;
        float qx = X[j], qy = X[NQ+j], qz = X[2*NQ+j];
        float sq = (pn + qx*qx+qy*qy+qz*qz) - 2.0f*(px*qx+py*qy+pz*qz);
        bool in = !(sq > RR);
        unsigned m = __ballot_sync(0xffffffffu, in);
        int pos = cnt + __popc(m & ((1u << lane) - 1u));
        if (in && pos < NSQ) out[(size_t)pos * NQ] = j;
        cnt += __popc(m);
    }
    __syncwarp();
    if (lane == 0) {
        int first = out[0];
        for (int t = cnt; t < NSQ; t++) out[(size_t)t * NQ] = first;
    }
}

// BmTc (b,j,n) paired over n, ush2 stores
__global__ void sa_bmt_c(const float* __restrict__ points, const float* __restrict__ xyz) {
    int n = (blockIdx.x * 256 + threadIdx.x) * 2;
    int j = blockIdx.y, b = blockIdx.z;
    float v0, v1;
    if (j < OFF_P) {
        const float* p = xyz + ((size_t)b*3 + j)*NQ;
        v0 = p[n]; v1 = p[n+1];
    } else if (j < OFF_GP) {
        const float* p = points + ((size_t)b*DQ + (j-OFF_P))*NQ;
        v0 = p[n]; v1 = p[n+1];
    } else if (j < OFF_GX) {
        int t = j - OFF_GP, k = t >> 6, d = t & 63;
        const int* ip = g_idx + ((size_t)b*NSQ + k)*NQ;
        const float* p = points + ((size_t)b*DQ + d)*NQ;
        v0 = p[ip[n]]; v1 = p[ip[n+1]];
    } else {
        int t = j - OFF_GX, k = t / 3, c = t % 3;
        const int* ip = g_idx + ((size_t)b*NSQ + k)*NQ;
        const float* p = xyz + ((size_t)b*3 + c)*NQ;
        v0 = p[ip[n]]; v1 = p[ip[n+1]];
    }
    size_t o = (((size_t)b*JQ + j)*NQ + n) >> 1;
    uint32_t lw, hw = split_pack(v0, v1, &lw);
    ((uint32_t*)g_BmTc_h)[o] = hw;
    ((uint32_t*)g_BmTc_l)[o] = lw;
}

__global__ void sa_cs_fin(int C, int nChunks, int count,
                          const float* __restrict__ gamma, const float* __restrict__ beta,
                          float* __restrict__ sc, float* __restrict__ sf) {
    int c = blockIdx.x, tid = threadIdx.x;
    double s = 0.0, s2 = 0.0;
    for (int i = tid; i < nChunks; i += 256) {
        s  += g_part[((size_t)i * C + c) * 2];
        s2 += g_part[((size_t)i * C + c) * 2 + 1];
    }
    __shared__ double sa[256], sb2[256];
    sa[tid] = s; sb2[tid] = s2; __syncthreads();
    for (int o = 128; o > 0; o >>= 1) {
        if (tid < o) { sa[tid] += sa[tid+o]; sb2[tid] += sb2[tid+o]; }
        __syncthreads();
    }
    if (tid == 0) {
        double n = (double)count, m = sa[0] / n;
        double var = sb2[0] / n - m * m; if (var < 0.0) var = 0.0;
        float scale = gamma[c] * rsqrtf((float)var + 1e-5f);
        sc[c] = scale; sf[c] = beta[c] - (float)m * scale;
    }
}

// softmax (applies bn2 affine); writes ONLY bf16 split + norm + argmax
__global__ void sa_softmax(float* __restrict__ H) {
    int s = blockIdx.x, b = blockIdx.y, tid = threadIdx.x;
    float* row = H + ((size_t)b * SQ + s) * NQ;
    __shared__ float buf[NQ];
    __shared__ float red[256], rv[256];
    __shared__ int ri[256];
    float a = g_s2[s], sh = g_sh2[s];
    float lmax = -3.4e38f;
    for (int i = tid; i < NQ; i += 256) { float y = a*row[i]+sh; buf[i] = y; lmax = fmaxf(lmax, y); }
    red[tid] = lmax; __syncthreads();
    for (int o = 128; o > 0; o >>= 1) { if (tid < o) red[tid] = fmaxf(red[tid], red[tid+o]); __syncthreads(); }
    float gmax = red[0]; __syncthreads();
    float lsum = 0.f;
    for (int i = tid; i < NQ; i += 256) { float e = expf(buf[i]-gmax); buf[i] = e; lsum += e; }
    red[tid] = lsum; __syncthreads();
    for (int o = 128; o > 0; o >>= 1) { if (tid < o) red[tid] += red[tid+o]; __syncthreads(); }
    float inv = 1.f / red[0]; __syncthreads();
    float lss = 0.f, bm = -1.f; int bi = 0;
    size_t rowoff = ((size_t)b * SQ + s) * NQ;
    for (int i = tid; i < NQ; i += 256) {
        float v = buf[i] * inv; lss += v*v;
        split_write(v, g_Sc_h + rowoff + i, g_Sc_l + rowoff + i);
        if (v > bm) { bm = v; bi = i; }
    }
    red[tid] = lss; rv[tid] = bm; ri[tid] = bi; __syncthreads();
    for (int o = 128; o > 0; o >>= 1) {
        if (tid < o) {
            red[tid] += red[tid+o];
            if (rv[tid+o] > rv[tid] || (rv[tid+o] == rv[tid] && ri[tid+o] < ri[tid])) { rv[tid] = rv[tid+o]; ri[tid] = ri[tid+o]; }
        }
        __syncthreads();
    }
    if (tid == 0) {
        g_norm[b*SQ+s] = sqrtf(red[0]);
        if (b == 0) g_amax[s] = ri[0];
    }
}

__global__ void sa_flags() { int s = blockIdx.x*256 + threadIdx.x; if (s < SQ) g_flags[g_amax[s]] = 1; }

__global__ void sa_newxyz(float* __restrict__ out) {
    int i = blockIdx.x * 256 + threadIdx.x;
    if (i >= BQ*3*SQ) return;
    int s = i % SQ, c = (i/SQ) % 3, b = i/(3*SQ);
    out[i] = g_Cbig[((size_t)b*SQ + s)*JQ + OFF_X + c];
}

// ETc: block (80,4): x = channel pair, y = row-in-block; ush2 stores
__global__ void sa_et_c() {
    int r = blockIdx.x * 4 + threadIdx.y;
    int b = blockIdx.y;
    int ch = threadIdx.x * 2;
    int s = r % SQ, k = r / SQ;
    const float* Cr = g_Cbig + ((size_t)b*SQ + s)*JQ;
    float v[2];
    #pragma unroll
    for (int u = 0; u < 2; u++) {
        int c = ch + u;
        float x = 0.f;
        if (c < 64) x = Cr[OFF_P + c];
        else if (c < 128) { int d = c - 64; x = Cr[OFF_GP + k*DQ + d] - Cr[OFF_P + d]; }
        else if (c < 131) x = Cr[OFF_X + (c - 128)];
        else if (c < INCH) { int c3 = c - 131; x = Cr[OFF_GX + k*3 + c3] - Cr[OFF_X + c3]; }
        v[u] = x;
    }
    size_t o = (((size_t)b*KSQ + r)*KPE + ch) >> 1;
    uint32_t lw, hw = split_pack(v[0], v[1], &lw);
    ((uint32_t*)g_ETc_h)[o] = hw;
    ((uint32_t*)g_ETc_l)[o] = lw;
}

__global__ void sa_max(float* __restrict__ out) {
    int s = blockIdx.x, b = blockIdx.y, o = threadIdx.x;
    float sc = g_sc2[o], sf = g_sf2[o];
    float m = -3.4e38f;
    const float* base = g_O2T + ((size_t)b*KSQ + s)*C2Q + o;
    #pragma unroll
    for (int k = 0; k < NSQ; k++) {
        float y = sc * base[(size_t)k*SQ*C2Q] + sf;
        y = (y >= 0.f) ? y : 0.2f * y;
        m = fmaxf(m, y);
    }
    out[XYZ_OUT + ((size_t)b*C2Q + o)*SQ + s] = m;
}

__global__ void sa_scalars(float* __restrict__ out) {
    __shared__ float sfr[256]; __shared__ int sir[256];
    int tid = threadIdx.x;
    int cnt = 0;
    for (int i = tid; i < NQ; i += 256) cnt += g_flags[i];
    float l = (tid < BQ) ? sqrtf(g_acc[tid]) : 0.f;
    sfr[tid] = l; sir[tid] = cnt; __syncthreads();
    for (int o = 128; o > 0; o >>= 1) {
        if (tid < o) { sfr[tid] += sfr[tid+o]; sir[tid] += sir[tid+o]; }
        __syncthreads();
    }
    if (tid == 0) {
        out[XYZ_OUT + NP_OUT] = sfr[0] / (float)BQ;
        out[XYZ_OUT + NP_OUT + 1] = (float)sir[0];
    }
}

// ---------------- launch ----------------
static inline float*  symf(const void* sym) { void* p = nullptr; cudaGetSymbolAddress(&p, sym); return (float*)p; }
static inline ush*    symu(const void* sym) { void* p = nullptr; cudaGetSymbolAddress(&p, sym); return (ush*)p; }
static inline double* symd(const void* sym) { void* p = nullptr; cudaGetSymbolAddress(&p, sym); return (double*)p; }

extern "C" void kernel_launch(void* const* d_in, const int* in_sizes, int n_in,
                              void* d_out, int out_size)
{
    const float* xyz   = (const float*)d_in[0];
    const float* points= (const float*)d_in[1];
    const float* w1_w = (const float*)d_in[2];
    const float* w1_b = (const float*)d_in[3];
    const float* bn1g = (const float*)d_in[4];
    const float* bn1b = (const float*)d_in[5];
    const float* w2_w = (const float*)d_in[6];
    const float* w2_b = (const float*)d_in[7];
    const float* bn2g = (const float*)d_in[8];
    const float* bn2b = (const float*)d_in[9];
    const float* c0w = (const float*)d_in[10];
    const float* c0b = (const float*)d_in[11];
    const float* g0  = (const float*)d_in[12];
    const float* b0  = (const float*)d_in[13];
    const float* c1w = (const float*)d_in[14];
    const float* c1b = (const float*)d_in[15];
    const float* g1  = (const float*)d_in[16];
    const float* b1  = (const float*)d_in[17];
    const float* c2w = (const float*)d_in[18];
    const float* c2b = (const float*)d_in[19];
    const float* g2  = (const float*)d_in[20];
    const float* b2  = (const float*)d_in[21];
    float* out = (float*)d_out;

    static bool attr = false;
    if (!attr) {
        cudaFuncSetAttribute(mma_gemm, cudaFuncAttributeMaxDynamicSharedMemorySize, SMEM_BYTES);
        attr = true;
    }

    float* p_h1t = symf(g_h1t);
    float* p_h2  = symf(g_h2);
    float* p_C   = symf(g_Cbig);
    float* p_O0  = symf(g_O0T);
    float* p_O1  = symf(g_O1T);
    float* p_O2  = symf(g_O2T);
    double* p_part = symd(g_part);
    float* p_s1 = symf(g_s1), *p_sh1 = symf(g_sh1);
    float* p_s2 = symf(g_s2), *p_sh2 = symf(g_sh2);
    float* p_sc0 = symf(g_sc0), *p_sf0 = symf(g_sf0);
    float* p_sc1 = symf(g_sc1), *p_sf1 = symf(g_sf1);
    float* p_sc2 = symf(g_sc2), *p_sf2 = symf(g_sf2);
    ush *aggh = symu(g_aggc_h), *aggl = symu(g_aggc_l);
    ush *w1h = symu(g_w1c_h), *w1l = symu(g_w1c_l);
    ush *h1h = symu(g_h1c_h), *h1l = symu(g_h1c_l);
    ush *w2h = symu(g_w2c_h), *w2l = symu(g_w2c_l);
    ush *Sh = symu(g_Sc_h), *Sl = symu(g_Sc_l);
    ush *Bmh = symu(g_BmTc_h), *Bml = symu(g_BmTc_l);
    ush *Eh = symu(g_ETc_h), *El = symu(g_ETc_l);
    ush *w0h = symu(g_c0wc_h), *w0l = symu(g_c0wc_l);
    ush *c1h = symu(g_c1wc_h), *c1l = symu(g_c1wc_l);
    ush *c2h = symu(g_c2wc_h), *c2l = symu(g_c2wc_l);
    ush *O0h = symu(g_O0c_h), *O0l = symu(g_O0c_l);
    ush *O1h = symu(g_O1c_h), *O1l = symu(g_O1c_l);

    sa_init<<<9, 256>>>();
    cv_agg<<<(int)(((long long)BQ*NQ*KP1/2 + 255)/256), 256>>>(points, xyz);
    cv_split<<<(SCQ*KP1/2 + 255)/256, 256>>>(w1_w, w1h, w1l, (long long)SCQ*KP1/2, SCQ, KP1, nullptr, nullptr, 0);
    cv_split<<<(SQ*KP1/2 + 255)/256, 256>>>(w2_w, w2h, w2l, (long long)SQ*KP1/2, SCQ, KP1, nullptr, nullptr, 0);
    cv_split<<<(C0Q*KPE/2 + 255)/256, 256>>>(c0w, w0h, w0l, (long long)C0Q*KPE/2, INCH, KPE, nullptr, nullptr, 0);
    cv_split<<<(C1Q*C0Q/2 + 255)/256, 256>>>(c1w, c1h, c1l, (long long)C1Q*C0Q/2, C0Q, C0Q, nullptr, nullptr, 0);
    cv_split<<<(C2Q*C1Q/2 + 255)/256, 256>>>(c2w, c2h, c2l, (long long)C2Q*C1Q/2, C1Q, C1Q, nullptr, nullptr, 0);
    sa_ball<<<(BQ*NQ*32)/256, 256>>>(xyz);
    sa_bmt_c<<<dim3(NQ/512, JQ, BQ), 256>>>(points, xyz);

    // h1t = aggT * w1^T + w1_b ; col-stats fused
    mma_gemm<<<dim3(1, NQ/128, BQ), 256, SMEM_BYTES>>>(aggh, aggl, w1h, w1l, p_h1t,
        NQ, SCQ, KP1, (size_t)NQ*KP1, 0, (size_t)NQ*SCQ, nullptr, w1_b, 1, p_part, SCQ, 0, 0);
    sa_cs_fin<<<SCQ, 256>>>(SCQ, BQ*(NQ/128), BQ*NQ, bn1g, bn1b, p_s1, p_sh1);
    cv_split<<<(int)(((long long)BQ*NQ*KP1/2 + 255)/256), 256>>>(p_h1t, h1h, h1l,
        (long long)BQ*NQ*KP1/2, SCQ, KP1, p_s1, p_sh1, 0);

    // h2 = w2 * bn1(h1)^T + w2_b ; row-stats fused
    mma_gemm<<<dim3(NQ/128, SQ/128, BQ), 256, SMEM_BYTES>>>(w2h, w2l, h1h, h1l, p_h2,
        SQ, NQ, KP1, 0, (size_t)NQ*KP1, (size_t)SQ*NQ, w2_b, nullptr, 2, p_part, SQ, 0, 0);
    sa_cs_fin<<<SQ, 256>>>(SQ, BQ*(NQ/128), BQ*NQ, bn2g, bn2b, p_s2, p_sh2);
    sa_softmax<<<dim3(SQ, BQ), 256>>>(p_h2);
    sa_flags<<<2, 256>>>();

    // fused Gram + cosine loss (upper-triangle tiles only; no inner materialization)
    mma_gemm<<<dim3(SQ/128, SQ/128, BQ), 256, SMEM_BYTES>>>(Sh, Sl, Sh, Sl, p_h2,
        SQ, SQ, NQ, (size_t)SQ*NQ, (size_t)SQ*NQ, 0, nullptr, nullptr, 0, nullptr, 0, 1, 1);

    // Cbig = S * BmT^T
    mma_gemm<<<dim3((JQ+127)/128, SQ/128, BQ), 256, SMEM_BYTES>>>(Sh, Sl, Bmh, Bml, p_C,
        SQ, JQ, NQ, (size_t)SQ*NQ, (size_t)JQ*NQ, (size_t)SQ*JQ, nullptr, nullptr, 0, nullptr, 0, 0, 0);
    sa_newxyz<<<(BQ*3*SQ + 255)/256, 256>>>(out);
    sa_et_c<<<dim3(KSQ/4, BQ), dim3(80, 4)>>>();

    // conv stack (transposed outputs); col-stats fused
    mma_gemm<<<dim3(1, KSQ/128, BQ), 256, SMEM_BYTES>>>(Eh, El, w0h, w0l, p_O0,
        KSQ, C0Q, KPE, (size_t)KSQ*KPE, 0, (size_t)KSQ*C0Q, nullptr, c0b, 1, p_part, C0Q, 0, 0);
    sa_cs_fin<<<C0Q, 256>>>(C0Q, BQ*(KSQ/128), BQ*KSQ, g0, b0, p_sc0, p_sf0);
    cv_split<<<(int)(((long long)BQ*KSQ*C0Q/2 + 255)/256), 256>>>(p_O0, O0h, O0l,
        (long long)BQ*KSQ*C0Q/2, C0Q, C0Q, p_sc0, p_sf0, 1);

    mma_gemm<<<dim3(1, KSQ/128, BQ), 256, SMEM_BYTES>>>(O0h, O0l, c1h, c1l, p_O1,
        KSQ, C1Q, C0Q, (size_t)KSQ*C0Q, 0, (size_t)KSQ*C1Q, nullptr, c1b, 1, p_part, C1Q, 0, 0);
    sa_cs_fin<<<C1Q, 256>>>(C1Q, BQ*(KSQ/128), BQ*KSQ, g1, b1, p_sc1, p_sf1);
    cv_split<<<(int)(((long long)BQ*KSQ*C1Q/2 + 255)/256), 256>>>(p_O1, O1h, O1l,
        (long long)BQ*KSQ*C1Q/2, C1Q, C1Q, p_sc1, p_sf1, 1);

    mma_gemm<<<dim3(C2Q/128, KSQ/128, BQ), 256, SMEM_BYTES>>>(O1h, O1l, c2h, c2l, p_O2,
        KSQ, C2Q, C1Q, (size_t)KSQ*C1Q, 0, (size_t)KSQ*C2Q, nullptr, c2b, 1, p_part, C2Q, 0, 0);
    sa_cs_fin<<<C2Q, 256>>>(C2Q, BQ*(KSQ/128), BQ*KSQ, g2, b2, p_sc2, p_sf2);

    sa_max<<<dim3(SQ, BQ), 256>>>(out);
    sa_scalars<<<1, 256>>>(out);
}

// round 9
// speedup vs baseline: 1.7310x; 1.0065x over previous
#include <cuda_runtime.h>
#include <cuda_bf16.h>
#include <math.h>
#include <stdint.h>

#define BQ 16
#define NQ 2048
#define DQ 64
#define SQ 512
#define NSQ 32
#define SCQ 67
#define INCH 134
#define C0Q 128
#define C1Q 128
#define C2Q 256
#define KSQ (NSQ*SQ)
#define JQ (3+DQ+NSQ*DQ+NSQ*3)   // 2211
#define OFF_X 0
#define OFF_P 3
#define OFF_GP 67
#define OFF_GX 2115
#define XYZ_OUT (BQ*3*SQ)
#define NP_OUT  ((size_t)BQ*C2Q*SQ)
#define KP1 96
#define KPE 160

typedef unsigned short ush;

// ---------------- fp32 scratch ----------------
__device__ float g_h1t [(size_t)BQ*NQ*SCQ];
__device__ float g_h2  [(size_t)BQ*SQ*NQ];
__device__ float g_Cbig[(size_t)BQ*SQ*JQ];
__device__ float g_O0T [(size_t)BQ*KSQ*C0Q];
__device__ float g_O1T [(size_t)BQ*KSQ*C1Q];
__device__ float g_O2T [(size_t)BQ*KSQ*C2Q];
__device__ float g_norm[BQ*SQ];
__device__ int   g_amax[SQ];
__device__ int   g_idx[(size_t)BQ*NSQ*NQ];
__device__ double g_part[(size_t)2048*256*2];
__device__ float g_s1[SCQ], g_sh1[SCQ];
__device__ float g_s2[SQ],  g_sh2[SQ];
__device__ float g_sc0[C0Q], g_sf0[C0Q];
__device__ float g_sc1[C1Q], g_sf1[C1Q];
__device__ float g_sc2[C2Q], g_sf2[C2Q];
__device__ float g_acc[BQ];
__device__ int   g_flags[NQ];

// ---------------- bf16 hi/lo operand arrays ----------------
__device__ ush g_aggc_h[(size_t)BQ*NQ*KP1],  g_aggc_l[(size_t)BQ*NQ*KP1];
__device__ ush g_w1c_h[SCQ*KP1],             g_w1c_l[SCQ*KP1];
__device__ ush g_h1c_h[(size_t)BQ*NQ*KP1],   g_h1c_l[(size_t)BQ*NQ*KP1];
__device__ ush g_w2c_h[SQ*KP1],              g_w2c_l[SQ*KP1];
__device__ ush g_Sc_h[(size_t)BQ*SQ*NQ],     g_Sc_l[(size_t)BQ*SQ*NQ];
__device__ ush g_BmTc_h[(size_t)BQ*JQ*NQ],   g_BmTc_l[(size_t)BQ*JQ*NQ];
__device__ ush g_c0wc_h[C0Q*KPE],            g_c0wc_l[C0Q*KPE];
__device__ ush g_c1wc_h[C1Q*C0Q],            g_c1wc_l[C1Q*C0Q];
__device__ ush g_c2wc_h[C2Q*C1Q],            g_c2wc_l[C2Q*C1Q];

// ---------------- helpers ----------------
__device__ __forceinline__ uint32_t smem_u32(const void* p) {
    uint32_t a;
    asm("{ .reg .u64 t; cvta.to.shared.u64 t, %1; cvt.u32.u64 %0, t; }" : "=r"(a) : "l"(p));
    return a;
}
__device__ __forceinline__ void ldm4(uint32_t* r, uint32_t addr) {
    asm volatile("ldmatrix.sync.aligned.m8n8.x4.shared.b16 {%0,%1,%2,%3}, [%4];"
        : "=r"(r[0]), "=r"(r[1]), "=r"(r[2]), "=r"(r[3]) : "r"(addr));
}
__device__ __forceinline__ void mma16816(float* c, const uint32_t* a, const uint32_t* b) {
    asm volatile("mma.sync.aligned.m16n8k16.row.col.f32.bf16.bf16.f32 "
        "{%0,%1,%2,%3}, {%4,%5,%6,%7}, {%8,%9}, {%0,%1,%2,%3};"
        : "+f"(c[0]), "+f"(c[1]), "+f"(c[2]), "+f"(c[3])
        : "r"(a[0]), "r"(a[1]), "r"(a[2]), "r"(a[3]), "r"(b[0]), "r"(b[1]));
}
__device__ __forceinline__ uint32_t split_pack(float v0, float v1, uint32_t* lo) {
    __nv_bfloat16 h0 = __float2bfloat16(v0), h1 = __float2bfloat16(v1);
    __nv_bfloat16 l0 = __float2bfloat16(v0 - __bfloat162float(h0));
    __nv_bfloat16 l1 = __float2bfloat16(v1 - __bfloat162float(h1));
    *lo = ((uint32_t)__bfloat16_as_ushort(l1) << 16) | __bfloat16_as_ushort(l0);
    return ((uint32_t)__bfloat16_as_ushort(h1) << 16) | __bfloat16_as_ushort(h0);
}
__device__ __forceinline__ void split_write(float v, ush* ph, ush* pl) {
    __nv_bfloat16 h = __float2bfloat16(v);
    __nv_bfloat16 l = __float2bfloat16(v - __bfloat162float(h));
    *ph = __bfloat16_as_ushort(h);
    *pl = __bfloat16_as_ushort(l);
}
__device__ __forceinline__ float edge_val(const float* __restrict__ Cr, int k, int c) {
    if (c < 64) return Cr[OFF_P + c];
    if (c < 128) { int d = c - 64; return Cr[OFF_GP + k*DQ + d] - Cr[OFF_P + d]; }
    if (c < 131) return Cr[OFF_X + (c - 128)];
    if (c < INCH) { int c3 = c - 131; return Cr[OFF_GX + k*3 + c3] - Cr[OFF_X + c3]; }
    return 0.f;
}

// ---------------- pipelined HMMA GEMM (2-stage) with fused loaders/epilogues ----
// C[b](MxN) = A[b](MxKp) * B[b](NxKp)^T ; B pre-split bf16 hi/lo (cp.async).
// aMode: 0 A pre-split via cp.async; 1 A from fp32 (affine+leaky, split in loader);
//        2 A = edge features built from Cbig rows.
// statMode: 0 none, 1 column stats, 2 row stats. triSkip / cosMode as before.
#define KC 32
#define RSH 40
#define TILEH (128*RSH)
#define STAGEH (4*TILEH)
#define SMEM_BYTES (2*STAGEH*2)   // 81920 B
__global__ void __launch_bounds__(256) mma_gemm(
    const ush* __restrict__ Ah, const ush* __restrict__ Al,
    const ush* __restrict__ Bh, const ush* __restrict__ Bl,
    float* __restrict__ C, int M, int N, int Kp,
    size_t sA, size_t sB, size_t sC,
    const float* __restrict__ biasRow, const float* __restrict__ biasCol,
    int statMode, double* __restrict__ statOut, int statC, int triSkip, int cosMode,
    int aMode, const float* __restrict__ Afp, size_t sAfp,
    const float* __restrict__ scA, const float* __restrict__ shA)
{
    if (triSkip && blockIdx.x < blockIdx.y) return;
    extern __shared__ ush sm[];
    const int tid = threadIdx.x;
    const int w = tid >> 5, lane = tid & 31;
    const int wm = w & 1, wn = w >> 1;
    const int m0 = blockIdx.y * 128, n0 = blockIdx.x * 128, b = blockIdx.z;
    const ush* srcs[4] = { Ah + (size_t)b*sA, Al + (size_t)b*sA,
                           Bh + (size_t)b*sB, Bl + (size_t)b*sB };
    const float* Afpb = Afp ? (Afp + (size_t)b * sAfp) : (const float*)0;
    const uint32_t smb = smem_u32(sm);

    float acc[4][4][4];
    #pragma unroll
    for (int i = 0; i < 4; i++)
        #pragma unroll
        for (int j = 0; j < 4; j++)
            #pragma unroll
            for (int q = 0; q < 4; q++) acc[i][j][q] = 0.f;

    const int T = Kp / KC;

    #define LOAD_STAGE(t, st) do { \
        int k0 = (t) * KC; \
        if (aMode == 0) { \
            _Pragma("unroll") \
            for (int arr = 0; arr < 2; arr++) { \
                const ush* S = srcs[arr]; \
                uint32_t dbase = smb + (uint32_t)(((st)*STAGEH + arr*TILEH) * 2); \
                _Pragma("unroll") \
                for (int i = 0; i < 2; i++) { \
                    int e = tid + i * 256; \
                    int r = e >> 2, c16 = e & 3; \
                    uint32_t daddr = dbase + (uint32_t)((r * RSH + c16 * 8) * 2); \
                    int rg = m0 + r; \
                    int rc = rg < M ? rg : (M - 1); \
                    const ush* sp = S + (size_t)rc * Kp + k0 + c16 * 8; \
                    int sz = (rg < M) ? 16 : 0; \
                    asm volatile("cp.async.cg.shared.global [%0], [%1], 16, %2;" \
                                 :: "r"(daddr), "l"(sp), "r"(sz)); \
                } \
            } \
        } else if (aMode == 1) { \
            _Pragma("unroll") \
            for (int i = 0; i < 8; i++) { \
                int e = tid + i * 256; \
                int r = e >> 4, cw = e & 15; \
                int rg = m0 + r, kk = k0 + cw * 2; \
                float v0 = 0.f, v1 = 0.f; \
                if (rg < M) { \
                    v0 = Afpb[(size_t)rg * Kp + kk]; \
                    v1 = Afpb[(size_t)rg * Kp + kk + 1]; \
                    v0 = scA[kk] * v0 + shA[kk];       if (v0 < 0.f) v0 *= 0.2f; \
                    v1 = scA[kk+1] * v1 + shA[kk+1];   if (v1 < 0.f) v1 *= 0.2f; \
                } \
                uint32_t lw, hw = split_pack(v0, v1, &lw); \
                int idx = (st)*STAGEH + r * RSH + cw * 2; \
                *(uint32_t*)&sm[idx] = hw; \
                *(uint32_t*)&sm[idx + TILEH] = lw; \
            } \
        } else { \
            _Pragma("unroll") \
            for (int i = 0; i < 8; i++) { \
                int e = tid + i * 256; \
                int r = e >> 4, cw = e & 15; \
                int rg = m0 + r, kk = k0 + cw * 2; \
                int kgrp = rg >> 9, sloc = rg & 511; \
                const float* Cr = Afpb + (size_t)sloc * JQ; \
                float v0 = edge_val(Cr, kgrp, kk); \
                float v1 = edge_val(Cr, kgrp, kk + 1); \
                uint32_t lw, hw = split_pack(v0, v1, &lw); \
                int idx = (st)*STAGEH + r * RSH + cw * 2; \
                *(uint32_t*)&sm[idx] = hw; \
                *(uint32_t*)&sm[idx + TILEH] = lw; \
            } \
        } \
        _Pragma("unroll") \
        for (int arr = 2; arr < 4; arr++) { \
            const ush* S = srcs[arr]; \
            uint32_t dbase = smb + (uint32_t)(((st)*STAGEH + arr*TILEH) * 2); \
            _Pragma("unroll") \
            for (int i = 0; i < 2; i++) { \
                int e = tid + i * 256; \
                int r = e >> 2, c16 = e & 3; \
                uint32_t daddr = dbase + (uint32_t)((r * RSH + c16 * 8) * 2); \
                int rg = n0 + r; \
                int rc = rg < N ? rg : (N - 1); \
                const ush* sp = S + (size_t)rc * Kp + k0 + c16 * 8; \
                int sz = (rg < N) ? 16 : 0; \
                asm volatile("cp.async.cg.shared.global [%0], [%1], 16, %2;" \
                             :: "r"(daddr), "l"(sp), "r"(sz)); \
            } \
        } \
        asm volatile("cp.async.commit_group;" ::: "memory"); \
    } while (0)

    LOAD_STAGE(0, 0);
    for (int t = 0; t < T; t++) {
        const int st = t & 1;
        if (t + 1 < T) {
            LOAD_STAGE(t + 1, st ^ 1);
            asm volatile("cp.async.wait_group 1;" ::: "memory");
        } else {
            asm volatile("cp.async.wait_group 0;" ::: "memory");
        }
        __syncthreads();
        const uint32_t uAh = smb + (uint32_t)((st*STAGEH + 0*TILEH) * 2);
        const uint32_t uAl = smb + (uint32_t)((st*STAGEH + 1*TILEH) * 2);
        const uint32_t uBh = smb + (uint32_t)((st*STAGEH + 2*TILEH) * 2);
        const uint32_t uBl = smb + (uint32_t)((st*STAGEH + 3*TILEH) * 2);
        #pragma unroll
        for (int k16 = 0; k16 < 32; k16 += 16) {
            uint32_t ah[4][4], al[4][4], bh[4][2], bl[4][2];
            {
                int arow = wm * 64 + (lane & 15);
                int akk = k16 + ((lane >> 4) << 3);
                #pragma unroll
                for (int mf = 0; mf < 4; mf++) {
                    uint32_t byteoff = (uint32_t)(((arow + mf * 16) * RSH + akk) << 1);
                    ldm4(ah[mf], uAh + byteoff);
                    ldm4(al[mf], uAl + byteoff);
                }
                int q = lane >> 3;
                int brow0 = wn * 32 + ((q >> 1) << 3) + (lane & 7);
                int bkk = k16 + ((q & 1) << 3);
                #pragma unroll
                for (int p = 0; p < 2; p++) {
                    uint32_t byteoff = (uint32_t)(((brow0 + p * 16) * RSH + bkk) << 1);
                    uint32_t tmp[4];
                    ldm4(tmp, uBh + byteoff);
                    bh[2*p][0] = tmp[0]; bh[2*p][1] = tmp[1];
                    bh[2*p+1][0] = tmp[2]; bh[2*p+1][1] = tmp[3];
                    ldm4(tmp, uBl + byteoff);
                    bl[2*p][0] = tmp[0]; bl[2*p][1] = tmp[1];
                    bl[2*p+1][0] = tmp[2]; bl[2*p+1][1] = tmp[3];
                }
            }
            #pragma unroll
            for (int mf = 0; mf < 4; mf++)
                #pragma unroll
                for (int nf = 0; nf < 4; nf++)
                    mma16816(acc[mf][nf], ah[mf], bh[nf]);
            #pragma unroll
            for (int mf = 0; mf < 4; mf++)
                #pragma unroll
                for (int nf = 0; nf < 4; nf++)
                    mma16816(acc[mf][nf], ah[mf], bl[nf]);
            #pragma unroll
            for (int mf = 0; mf < 4; mf++)
                #pragma unroll
                for (int nf = 0; nf < 4; nf++)
                    mma16816(acc[mf][nf], al[mf], bh[nf]);
        }
        __syncthreads();
    }

    if (cosMode) {
        const float* nb = g_norm + b * SQ;
        float part = 0.f;
        #pragma unroll
        for (int mf = 0; mf < 4; mf++) {
            int r = m0 + wm * 64 + mf * 16 + (lane >> 2);
            float nr0 = nb[r], nr1 = nb[r + 8];
            #pragma unroll
            for (int nf = 0; nf < 4; nf++) {
                #pragma unroll
                for (int u = 0; u < 2; u++) {
                    int col = n0 + wn * 32 + nf * 8 + ((lane & 3) << 1) + u;
                    float ncv = nb[col];
                    if (col > r) {
                        float cm = acc[mf][nf][u] / (nr0 * ncv + 1e-10f);
                        part += 2.f * cm * cm;
                    }
                    if (col > r + 8) {
                        float cm = acc[mf][nf][u + 2] / (nr1 * ncv + 1e-10f);
                        part += 2.f * cm * cm;
                    }
                }
            }
        }
        float* red = (float*)sm;
        red[tid] = part; __syncthreads();
        for (int off = 128; off > 0; off >>= 1) {
            if (tid < off) red[tid] += red[tid + off];
            __syncthreads();
        }
        if (tid == 0) atomicAdd(&g_acc[b], red[0]);
        return;
    }

    float cs[8], cq[8];
    #pragma unroll
    for (int i = 0; i < 8; i++) { cs[i] = 0.f; cq[i] = 0.f; }
    float* Cb = C + (size_t)b * sC;
    #pragma unroll
    for (int mf = 0; mf < 4; mf++) {
        int r = m0 + wm * 64 + mf * 16 + (lane >> 2);
        float br0 = biasRow ? biasRow[r] : 0.f;
        float br1 = biasRow ? biasRow[r + 8] : 0.f;
        #pragma unroll
        for (int nf = 0; nf < 4; nf++) {
            int c = n0 + wn * 32 + nf * 8 + ((lane & 3) << 1);
            #pragma unroll
            for (int u = 0; u < 2; u++) {
                int col = c + u;
                float bc = (biasCol && col < N) ? biasCol[col] : 0.f;
                float v0 = acc[mf][nf][u]     + br0 + bc;
                float v1 = acc[mf][nf][u + 2] + br1 + bc;
                if (col < N) {
                    Cb[(size_t)r * N + col]       = v0;
                    Cb[(size_t)(r + 8) * N + col] = v1;
                }
                if (statMode == 1) {
                    cs[nf*2+u] += v0 + v1;
                    cq[nf*2+u] += v0*v0 + v1*v1;
                } else if (statMode == 2) {
                    cs[mf*2]   += v0; cq[mf*2]   += v0*v0;
                    cs[mf*2+1] += v1; cq[mf*2+1] += v1*v1;
                }
            }
        }
    }
    if (statMode == 0) return;
    float* ssum = (float*)sm;
    float* ssq  = ssum + 2048;
    if (statMode == 1) {
        int g = wm * 8 + (lane >> 2);
        #pragma unroll
        for (int nf = 0; nf < 4; nf++)
            #pragma unroll
            for (int u = 0; u < 2; u++) {
                int colL = wn * 32 + nf * 8 + ((lane & 3) << 1) + u;
                ssum[colL * 16 + g] = cs[nf*2+u];
                ssq [colL * 16 + g] = cq[nf*2+u];
            }
        __syncthreads();
        if (tid < 128) {
            double s = 0.0, q = 0.0;
            #pragma unroll
            for (int g2 = 0; g2 < 16; g2++) { s += ssum[tid*16+g2]; q += ssq[tid*16+g2]; }
            int gcol = n0 + tid;
            if (gcol < N) {
                int chunk = blockIdx.z * gridDim.y + blockIdx.y;
                statOut[((size_t)chunk * statC + gcol) * 2]     = s;
                statOut[((size_t)chunk * statC + gcol) * 2 + 1] = q;
            }
        }
    } else {
        int h = wn * 4 + (lane & 3);
        #pragma unroll
        for (int mf = 0; mf < 4; mf++)
            #pragma unroll
            for (int hf = 0; hf < 2; hf++) {
                int rowL = wm * 64 + mf * 16 + (lane >> 2) + hf * 8;
                ssum[rowL * 16 + h] = cs[mf*2+hf];
                ssq [rowL * 16 + h] = cq[mf*2+hf];
            }
        __syncthreads();
        if (tid < 128) {
            double s = 0.0, q = 0.0;
            #pragma unroll
            for (int h2 = 0; h2 < 16; h2++) { s += ssum[tid*16+h2]; q += ssq[tid*16+h2]; }
            int grow = m0 + tid;
            int chunk = blockIdx.z * gridDim.x + blockIdx.x;
            statOut[((size_t)chunk * statC + grow) * 2]     = s;
            statOut[((size_t)chunk * statC + grow) * 2 + 1] = q;
        }
    }
}

// ---------------- elementwise / setup kernels ----------------
__global__ void sa_init() {
    int i = blockIdx.x * 256 + threadIdx.x;
    if (i < NQ) g_flags[i] = 0;
    if (i < BQ) g_acc[i] = 0.f;
}

__global__ void cv_split(const float* __restrict__ src, ush* __restrict__ dh, ush* __restrict__ dl,
                         long long totalPairs, int Ksrc, int Kp,
                         const float* __restrict__ sc, const float* __restrict__ sh, int leaky)
{
    long long i = (long long)blockIdx.x * 256 + threadIdx.x;
    if (i >= totalPairs) return;
    long long e = i * 2;
    int c = (int)(e % Kp);
    long long r = e / Kp;
    float v0 = 0.f, v1 = 0.f;
    if (c < Ksrc) {
        v0 = src[r * Ksrc + c];
        if (sc) { v0 = sc[c]*v0 + sh[c]; if (leaky && v0 < 0.f) v0 *= 0.2f; }
    }
    if (c + 1 < Ksrc) {
        v1 = src[r * Ksrc + c + 1];
        if (sc) { v1 = sc[c+1]*v1 + sh[c+1]; if (leaky && v1 < 0.f) v1 *= 0.2f; }
    }
    uint32_t lw, hw = split_pack(v0, v1, &lw);
    ((uint32_t*)dh)[i] = hw;
    ((uint32_t*)dl)[i] = lw;
}

__global__ void cv_agg(const float* __restrict__ points, const float* __restrict__ xyz) {
    long long i = (long long)blockIdx.x * 256 + threadIdx.x;
    if (i >= (long long)BQ*NQ*KP1/2) return;
    long long e = i * 2;
    int c = (int)(e % KP1); long long r = e / KP1;
    int n = (int)(r % NQ); int b = (int)(r / NQ);
    float v0 = 0.f, v1 = 0.f;
    if (c < DQ) v0 = points[((size_t)b*DQ + c)*NQ + n];
    else if (c < SCQ) v0 = xyz[((size_t)b*3 + (c-DQ))*NQ + n];
    int c1 = c + 1;
    if (c1 < DQ) v1 = points[((size_t)b*DQ + c1)*NQ + n];
    else if (c1 < SCQ) v1 = xyz[((size_t)b*3 + (c1-DQ))*NQ + n];
    uint32_t lw, hw = split_pack(v0, v1, &lw);
    ((uint32_t*)g_aggc_h)[i] = hw;
    ((uint32_t*)g_aggc_l)[i] = lw;
}

__global__ void sa_ball(const float* __restrict__ xyz) {
    int w = (blockIdx.x * blockDim.x + threadIdx.x) >> 5;
    int lane = threadIdx.x & 31;
    if (w >= BQ * NQ) return;
    int b = w / NQ, n = w % NQ;
    const float* X = xyz + (size_t)b * 3 * NQ;
    float px = X[n], py = X[NQ+n], pz = X[2*NQ+n];
    float pn = px*px + py*py + pz*pz;
    const float RR = (float)(0.2 * 0.2);
    int* out = g_idx + (size_t)b * NSQ * NQ + n;
    int cnt = 0;
    for (int j0 = 0; j0 < NQ && cnt < NSQ; j0 += 32) {
        int j = j0 + lane;
        float qx = X[j], qy = X[NQ+j], qz = X[2*NQ+j];
        float sq = (pn + qx*qx+qy*qy+qz*qz) - 2.0f*(px*qx+py*qy+pz*qz);
        bool in = !(sq > RR);
        unsigned m = __ballot_sync(0xffffffffu, in);
        int pos = cnt + __popc(m & ((1u << lane) - 1u));
        if (in && pos < NSQ) out[(size_t)pos * NQ] = j;
        cnt += __popc(m);
    }
    __syncwarp();
    if (lane == 0) {
        int first = out[0];
        for (int t = cnt; t < NSQ; t++) out[(size_t)t * NQ] = first;
    }
}

__global__ void sa_bmt_c(const float* __restrict__ points, const float* __restrict__ xyz) {
    int n = (blockIdx.x * 256 + threadIdx.x) * 2;
    int j = blockIdx.y, b = blockIdx.z;
    float v0, v1;
    if (j < OFF_P) {
        const float* p = xyz + ((size_t)b*3 + j)*NQ;
        v0 = p[n]; v1 = p[n+1];
    } else if (j < OFF_GP) {
        const float* p = points + ((size_t)b*DQ + (j-OFF_P))*NQ;
        v0 = p[n]; v1 = p[n+1];
    } else if (j < OFF_GX) {
        int t = j - OFF_GP, k = t >> 6, d = t & 63;
        const int* ip = g_idx + ((size_t)b*NSQ + k)*NQ;
        const float* p = points + ((size_t)b*DQ + d)*NQ;
        v0 = p[ip[n]]; v1 = p[ip[n+1]];
    } else {
        int t = j - OFF_GX, k = t / 3, c = t % 3;
        const int* ip = g_idx + ((size_t)b*NSQ + k)*NQ;
        const float* p = xyz + ((size_t)b*3 + c)*NQ;
        v0 = p[ip[n]]; v1 = p[ip[n+1]];
    }
    size_t o = (((size_t)b*JQ + j)*NQ + n) >> 1;
    uint32_t lw, hw = split_pack(v0, v1, &lw);
    ((uint32_t*)g_BmTc_h)[o] = hw;
    ((uint32_t*)g_BmTc_l)[o] = lw;
}

__global__ void sa_cs_fin(int C, int nChunks, int count,
                          const float* __restrict__ gamma, const float* __restrict__ beta,
                          float* __restrict__ sc, float* __restrict__ sf) {
    int c = blockIdx.x, tid = threadIdx.x;
    double s = 0.0, s2 = 0.0;
    for (int i = tid; i < nChunks; i += 256) {
        s  += g_part[((size_t)i * C + c) * 2];
        s2 += g_part[((size_t)i * C + c) * 2 + 1];
    }
    __shared__ double sa[256], sb2[256];
    sa[tid] = s; sb2[tid] = s2; __syncthreads();
    for (int o = 128; o > 0; o >>= 1) {
        if (tid < o) { sa[tid] += sa[tid+o]; sb2[tid] += sb2[tid+o]; }
        __syncthreads();
    }
    if (tid == 0) {
        double n = (double)count, m = sa[0] / n;
        double var = sb2[0] / n - m * m; if (var < 0.0) var = 0.0;
        float scale = gamma[c] * rsqrtf((float)var + 1e-5f);
        sc[c] = scale; sf[c] = beta[c] - (float)m * scale;
    }
}

__global__ void sa_softmax(float* __restrict__ H) {
    int s = blockIdx.x, b = blockIdx.y, tid = threadIdx.x;
    float* row = H + ((size_t)b * SQ + s) * NQ;
    __shared__ float buf[NQ];
    __shared__ float red[256], rv[256];
    __shared__ int ri[256];
    float a = g_s2[s], sh = g_sh2[s];
    float lmax = -3.4e38f;
    for (int i = tid; i < NQ; i += 256) { float y = a*row[i]+sh; buf[i] = y; lmax = fmaxf(lmax, y); }
    red[tid] = lmax; __syncthreads();
    for (int o = 128; o > 0; o >>= 1) { if (tid < o) red[tid] = fmaxf(red[tid], red[tid+o]); __syncthreads(); }
    float gmax = red[0]; __syncthreads();
    float lsum = 0.f;
    for (int i = tid; i < NQ; i += 256) { float e = expf(buf[i]-gmax); buf[i] = e; lsum += e; }
    red[tid] = lsum; __syncthreads();
    for (int o = 128; o > 0; o >>= 1) { if (tid < o) red[tid] += red[tid+o]; __syncthreads(); }
    float inv = 1.f / red[0]; __syncthreads();
    float lss = 0.f, bm = -1.f; int bi = 0;
    size_t rowoff = ((size_t)b * SQ + s) * NQ;
    for (int i = tid; i < NQ; i += 256) {
        float v = buf[i] * inv; lss += v*v;
        split_write(v, g_Sc_h + rowoff + i, g_Sc_l + rowoff + i);
        if (v > bm) { bm = v; bi = i; }
    }
    red[tid] = lss; rv[tid] = bm; ri[tid] = bi; __syncthreads();
    for (int o = 128; o > 0; o >>= 1) {
        if (tid < o) {
            red[tid] += red[tid+o];
            if (rv[tid+o] > rv[tid] || (rv[tid+o] == rv[tid] && ri[tid+o] < ri[tid])) { rv[tid] = rv[tid+o]; ri[tid] = ri[tid+o]; }
        }
        __syncthreads();
    }
    if (tid == 0) {
        g_norm[b*SQ+s] = sqrtf(red[0]);
        if (b == 0) g_amax[s] = ri[0];
    }
}

__global__ void sa_flags() { int s = blockIdx.x*256 + threadIdx.x; if (s < SQ) g_flags[g_amax[s]] = 1; }

__global__ void sa_newxyz(float* __restrict__ out) {
    int i = blockIdx.x * 256 + threadIdx.x;
    if (i >= BQ*3*SQ) return;
    int s = i % SQ, c = (i/SQ) % 3, b = i/(3*SQ);
    out[i] = g_Cbig[((size_t)b*SQ + s)*JQ + OFF_X + c];
}

__global__ void sa_max(float* __restrict__ out) {
    int s = blockIdx.x, b = blockIdx.y, o = threadIdx.x;
    float sc = g_sc2[o], sf = g_sf2[o];
    float m = -3.4e38f;
    const float* base = g_O2T + ((size_t)b*KSQ + s)*C2Q + o;
    #pragma unroll
    for (int k = 0; k < NSQ; k++) {
        float y = sc * base[(size_t)k*SQ*C2Q] + sf;
        y = (y >= 0.f) ? y : 0.2f * y;
        m = fmaxf(m, y);
    }
    out[XYZ_OUT + ((size_t)b*C2Q + o)*SQ + s] = m;
}

__global__ void sa_scalars(float* __restrict__ out) {
    __shared__ float sfr[256]; __shared__ int sir[256];
    int tid = threadIdx.x;
    int cnt = 0;
    for (int i = tid; i < NQ; i += 256) cnt += g_flags[i];
    float l = (tid < BQ) ? sqrtf(g_acc[tid]) : 0.f;
    sfr[tid] = l; sir[tid] = cnt; __syncthreads();
    for (int o = 128; o > 0; o >>= 1) {
        if (tid < o) { sfr[tid] += sfr[tid+o]; sir[tid] += sir[tid+o]; }
        __syncthreads();
    }
    if (tid == 0) {
        out[XYZ_OUT + NP_OUT] = sfr[0] / (float)BQ;
        out[XYZ_OUT + NP_OUT + 1] = (float)sir[0];
    }
}

// ---------------- launch ----------------
static inline float*  symf(const void* sym) { void* p = nullptr; cudaGetSymbolAddress(&p, sym); return (float*)p; }
static inline ush*    symu(const void* sym) { void* p = nullptr; cudaGetSymbolAddress(&p, sym); return (ush*)p; }
static inline double* symd(const void* sym) { void* p = nullptr; cudaGetSymbolAddress(&p, sym); return (double*)p; }

extern "C" void kernel_launch(void* const* d_in, const int* in_sizes, int n_in,
                              void* d_out, int out_size)
{
    const float* xyz   = (const float*)d_in[0];
    const float* points= (const float*)d_in[1];
    const float* w1_w = (const float*)d_in[2];
    const float* w1_b = (const float*)d_in[3];
    const float* bn1g = (const float*)d_in[4];
    const float* bn1b = (const float*)d_in[5];
    const float* w2_w = (const float*)d_in[6];
    const float* w2_b = (const float*)d_in[7];
    const float* bn2g = (const float*)d_in[8];
    const float* bn2b = (const float*)d_in[9];
    const float* c0w = (const float*)d_in[10];
    const float* c0b = (const float*)d_in[11];
    const float* g0  = (const float*)d_in[12];
    const float* b0  = (const float*)d_in[13];
    const float* c1w = (const float*)d_in[14];
    const float* c1b = (const float*)d_in[15];
    const float* g1  = (const float*)d_in[16];
    const float* b1  = (const float*)d_in[17];
    const float* c2w = (const float*)d_in[18];
    const float* c2b = (const float*)d_in[19];
    const float* g2  = (const float*)d_in[20];
    const float* b2  = (const float*)d_in[21];
    float* out = (float*)d_out;

    static bool attr = false;
    if (!attr) {
        cudaFuncSetAttribute(mma_gemm, cudaFuncAttributeMaxDynamicSharedMemorySize, SMEM_BYTES);
        attr = true;
    }

    float* p_h1t = symf(g_h1t);
    float* p_h2  = symf(g_h2);
    float* p_C   = symf(g_Cbig);
    float* p_O0  = symf(g_O0T);
    float* p_O1  = symf(g_O1T);
    float* p_O2  = symf(g_O2T);
    double* p_part = symd(g_part);
    float* p_s1 = symf(g_s1), *p_sh1 = symf(g_sh1);
    float* p_s2 = symf(g_s2), *p_sh2 = symf(g_sh2);
    float* p_sc0 = symf(g_sc0), *p_sf0 = symf(g_sf0);
    float* p_sc1 = symf(g_sc1), *p_sf1 = symf(g_sf1);
    float* p_sc2 = symf(g_sc2), *p_sf2 = symf(g_sf2);
    ush *aggh = symu(g_aggc_h), *aggl = symu(g_aggc_l);
    ush *w1h = symu(g_w1c_h), *w1l = symu(g_w1c_l);
    ush *h1h = symu(g_h1c_h), *h1l = symu(g_h1c_l);
    ush *w2h = symu(g_w2c_h), *w2l = symu(g_w2c_l);
    ush *Sh = symu(g_Sc_h), *Sl = symu(g_Sc_l);
    ush *Bmh = symu(g_BmTc_h), *Bml = symu(g_BmTc_l);
    ush *w0h = symu(g_c0wc_h), *w0l = symu(g_c0wc_l);
    ush *c1h = symu(g_c1wc_h), *c1l = symu(g_c1wc_l);
    ush *c2h = symu(g_c2wc_h), *c2l = symu(g_c2wc_l);

    sa_init<<<9, 256>>>();
    cv_agg<<<(int)(((long long)BQ*NQ*KP1/2 + 255)/256), 256>>>(points, xyz);
    cv_split<<<(SCQ*KP1/2 + 255)/256, 256>>>(w1_w, w1h, w1l, (long long)SCQ*KP1/2, SCQ, KP1, nullptr, nullptr, 0);
    cv_split<<<(SQ*KP1/2 + 255)/256, 256>>>(w2_w, w2h, w2l, (long long)SQ*KP1/2, SCQ, KP1, nullptr, nullptr, 0);
    cv_split<<<(C0Q*KPE/2 + 255)/256, 256>>>(c0w, w0h, w0l, (long long)C0Q*KPE/2, INCH, KPE, nullptr, nullptr, 0);
    cv_split<<<(C1Q*C0Q/2 + 255)/256, 256>>>(c1w, c1h, c1l, (long long)C1Q*C0Q/2, C0Q, C0Q, nullptr, nullptr, 0);
    cv_split<<<(C2Q*C1Q/2 + 255)/256, 256>>>(c2w, c2h, c2l, (long long)C2Q*C1Q/2, C1Q, C1Q, nullptr, nullptr, 0);
    sa_ball<<<(BQ*NQ*32)/256, 256>>>(xyz);
    sa_bmt_c<<<dim3(NQ/512, JQ, BQ), 256>>>(points, xyz);

    // h1t = aggT * w1^T + w1_b ; col-stats fused
    mma_gemm<<<dim3(1, NQ/128, BQ), 256, SMEM_BYTES>>>(aggh, aggl, w1h, w1l, p_h1t,
        NQ, SCQ, KP1, (size_t)NQ*KP1, 0, (size_t)NQ*SCQ, nullptr, w1_b, 1, p_part, SCQ, 0, 0,
        0, nullptr, 0, nullptr, nullptr);
    sa_cs_fin<<<SCQ, 256>>>(SCQ, BQ*(NQ/128), BQ*NQ, bn1g, bn1b, p_s1, p_sh1);
    cv_split<<<(int)(((long long)BQ*NQ*KP1/2 + 255)/256), 256>>>(p_h1t, h1h, h1l,
        (long long)BQ*NQ*KP1/2, SCQ, KP1, p_s1, p_sh1, 0);

    // h2 = w2 * bn1(h1)^T + w2_b ; row-stats fused
    mma_gemm<<<dim3(NQ/128, SQ/128, BQ), 256, SMEM_BYTES>>>(w2h, w2l, h1h, h1l, p_h2,
        SQ, NQ, KP1, 0, (size_t)NQ*KP1, (size_t)SQ*NQ, w2_b, nullptr, 2, p_part, SQ, 0, 0,
        0, nullptr, 0, nullptr, nullptr);
    sa_cs_fin<<<SQ, 256>>>(SQ, BQ*(NQ/128), BQ*NQ, bn2g, bn2b, p_s2, p_sh2);
    sa_softmax<<<dim3(SQ, BQ), 256>>>(p_h2);
    sa_flags<<<2, 256>>>();

    // fused Gram + cosine loss (upper-triangle tiles only)
    mma_gemm<<<dim3(SQ/128, SQ/128, BQ), 256, SMEM_BYTES>>>(Sh, Sl, Sh, Sl, p_h2,
        SQ, SQ, NQ, (size_t)SQ*NQ, (size_t)SQ*NQ, 0, nullptr, nullptr, 0, nullptr, 0, 1, 1,
        0, nullptr, 0, nullptr, nullptr);

    // Cbig = S * BmT^T
    mma_gemm<<<dim3((JQ+127)/128, SQ/128, BQ), 256, SMEM_BYTES>>>(Sh, Sl, Bmh, Bml, p_C,
        SQ, JQ, NQ, (size_t)SQ*NQ, (size_t)JQ*NQ, (size_t)SQ*JQ, nullptr, nullptr, 0, nullptr, 0, 0, 0,
        0, nullptr, 0, nullptr, nullptr);
    sa_newxyz<<<(BQ*3*SQ + 255)/256, 256>>>(out);

    // conv0: A = edge features built from Cbig in-loader (aMode=2)
    mma_gemm<<<dim3(1, KSQ/128, BQ), 256, SMEM_BYTES>>>(w0h, w0l, w0h, w0l, p_O0,
        KSQ, C0Q, KPE, 0, 0, (size_t)KSQ*C0Q, nullptr, c0b, 1, p_part, C0Q, 0, 0,
        2, p_C, (size_t)SQ*JQ, nullptr, nullptr);
    sa_cs_fin<<<C0Q, 256>>>(C0Q, BQ*(KSQ/128), BQ*KSQ, g0, b0, p_sc0, p_sf0);

    // conv1: A = bn-affine+leaky of O0 fp32 in-loader (aMode=1)
    mma_gemm<<<dim3(1, KSQ/128, BQ), 256, SMEM_BYTES>>>(c1h, c1l, c1h, c1l, p_O1,
        KSQ, C1Q, C0Q, 0, 0, (size_t)KSQ*C1Q, nullptr, c1b, 1, p_part, C1Q, 0, 0,
        1, p_O0, (size_t)KSQ*C0Q, p_sc0, p_sf0);
    sa_cs_fin<<<C1Q, 256>>>(C1Q, BQ*(KSQ/128), BQ*KSQ, g1, b1, p_sc1, p_sf1);

    // conv2: A = bn-affine+leaky of O1 fp32 in-loader (aMode=1)
    mma_gemm<<<dim3(C2Q/128, KSQ/128, BQ), 256, SMEM_BYTES>>>(c2h, c2l, c2h, c2l, p_O2,
        KSQ, C2Q, C1Q, 0, 0, (size_t)KSQ*C2Q, nullptr, c2b, 1, p_part, C2Q, 0, 0,
        1, p_O1, (size_t)KSQ*C1Q, p_sc1, p_sf1);
    sa_cs_fin<<<C2Q, 256>>>(C2Q, BQ*(KSQ/128), BQ*KSQ, g2, b2, p_sc2, p_sf2);

    sa_max<<<dim3(SQ, BQ), 256>>>(out);
    sa_scalars<<<1, 256>>>(out);
}

// round 10
// speedup vs baseline: 1.8198x; 1.0513x over previous
#include <cuda_runtime.h>
#include <cuda_bf16.h>
#include <math.h>
#include <stdint.h>

#define BQ 16
#define NQ 2048
#define DQ 64
#define SQ 512
#define NSQ 32
#define SCQ 67
#define INCH 134
#define C0Q 128
#define C1Q 128
#define C2Q 256
#define KSQ (NSQ*SQ)
#define JQ (3+DQ+NSQ*DQ+NSQ*3)   // 2211
#define OFF_X 0
#define OFF_P 3
#define OFF_GP 67
#define OFF_GX 2115
#define XYZ_OUT (BQ*3*SQ)
#define NP_OUT  ((size_t)BQ*C2Q*SQ)
#define KP1 96
#define KPE 160

typedef unsigned short ush;

// ---------------- fp32 scratch ----------------
__device__ float g_h1t [(size_t)BQ*NQ*SCQ];
__device__ float g_h2  [(size_t)BQ*SQ*NQ];
__device__ float g_Cbig[(size_t)BQ*SQ*JQ];
__device__ float g_O0T [(size_t)BQ*KSQ*C0Q];
__device__ float g_O1T [(size_t)BQ*KSQ*C1Q];
__device__ float g_O2T [(size_t)BQ*KSQ*C2Q];
__device__ float g_norm[BQ*SQ];
__device__ int   g_amax[SQ];
__device__ int   g_idx[(size_t)BQ*NSQ*NQ];
__device__ double g_part[(size_t)2048*256*2];
__device__ float g_s1[SCQ], g_sh1[SCQ];
__device__ float g_s2[SQ],  g_sh2[SQ];
__device__ float g_sc0[C0Q], g_sf0[C0Q];
__device__ float g_sc1[C1Q], g_sf1[C1Q];
__device__ float g_sc2[C2Q], g_sf2[C2Q];
__device__ float g_acc[BQ];
__device__ int   g_flags[NQ];

// ---------------- bf16 hi/lo operand arrays ----------------
__device__ ush g_aggc_h[(size_t)BQ*NQ*KP1],  g_aggc_l[(size_t)BQ*NQ*KP1];
__device__ ush g_w1c_h[SCQ*KP1],             g_w1c_l[SCQ*KP1];
__device__ ush g_h1c_h[(size_t)BQ*NQ*KP1],   g_h1c_l[(size_t)BQ*NQ*KP1];
__device__ ush g_w2c_h[SQ*KP1],              g_w2c_l[SQ*KP1];
__device__ ush g_Sc_h[(size_t)BQ*SQ*NQ],     g_Sc_l[(size_t)BQ*SQ*NQ];
__device__ ush g_BmTc_h[(size_t)BQ*JQ*NQ],   g_BmTc_l[(size_t)BQ*JQ*NQ];
__device__ ush g_c0wc_h[C0Q*KPE],            g_c0wc_l[C0Q*KPE];
__device__ ush g_c1wc_h[C1Q*C0Q],            g_c1wc_l[C1Q*C0Q];
__device__ ush g_c2wc_h[C2Q*C1Q],            g_c2wc_l[C2Q*C1Q];

// ---------------- helpers ----------------
__device__ __forceinline__ uint32_t smem_u32(const void* p) {
    uint32_t a;
    asm("{ .reg .u64 t; cvta.to.shared.u64 t, %1; cvt.u32.u64 %0, t; }" : "=r"(a) : "l"(p));
    return a;
}
__device__ __forceinline__ void ldm4(uint32_t* r, uint32_t addr) {
    asm volatile("ldmatrix.sync.aligned.m8n8.x4.shared.b16 {%0,%1,%2,%3}, [%4];"
        : "=r"(r[0]), "=r"(r[1]), "=r"(r[2]), "=r"(r[3]) : "r"(addr));
}
__device__ __forceinline__ void mma16816(float* c, const uint32_t* a, const uint32_t* b) {
    asm volatile("mma.sync.aligned.m16n8k16.row.col.f32.bf16.bf16.f32 "
        "{%0,%1,%2,%3}, {%4,%5,%6,%7}, {%8,%9}, {%0,%1,%2,%3};"
        : "+f"(c[0]), "+f"(c[1]), "+f"(c[2]), "+f"(c[3])
        : "r"(a[0]), "r"(a[1]), "r"(a[2]), "r"(a[3]), "r"(b[0]), "r"(b[1]));
}
__device__ __forceinline__ uint32_t split_pack(float v0, float v1, uint32_t* lo) {
    __nv_bfloat16 h0 = __float2bfloat16(v0), h1 = __float2bfloat16(v1);
    __nv_bfloat16 l0 = __float2bfloat16(v0 - __bfloat162float(h0));
    __nv_bfloat16 l1 = __float2bfloat16(v1 - __bfloat162float(h1));
    *lo = ((uint32_t)__bfloat16_as_ushort(l1) << 16) | __bfloat16_as_ushort(l0);
    return ((uint32_t)__bfloat16_as_ushort(h1) << 16) | __bfloat16_as_ushort(h0);
}
__device__ __forceinline__ void split_write(float v, ush* ph, ush* pl) {
    __nv_bfloat16 h = __float2bfloat16(v);
    __nv_bfloat16 l = __float2bfloat16(v - __bfloat162float(h));
    *ph = __bfloat16_as_ushort(h);
    *pl = __bfloat16_as_ushort(l);
}
__device__ __forceinline__ float edge_val(const float* __restrict__ Cr, int k, int c) {
    if (c < 64) return Cr[OFF_P + c];
    if (c < 128) { int d = c - 64; return Cr[OFF_GP + k*DQ + d] - Cr[OFF_P + d]; }
    if (c < 131) return Cr[OFF_X + (c - 128)];
    if (c < INCH) { int c3 = c - 131; return Cr[OFF_GX + k*3 + c3] - Cr[OFF_X + c3]; }
    return 0.f;
}

// ---------------- pipelined HMMA GEMM (2-stage) with fused loaders/epilogues ----
#define KC 32
#define RSH 40
#define TILEH (128*RSH)
#define STAGEH (4*TILEH)
#define SMEM_BYTES (2*STAGEH*2)   // 81920 B
__global__ void __launch_bounds__(256) mma_gemm(
    const ush* __restrict__ Ah, const ush* __restrict__ Al,
    const ush* __restrict__ Bh, const ush* __restrict__ Bl,
    float* __restrict__ C, int M, int N, int Kp,
    size_t sA, size_t sB, size_t sC,
    const float* __restrict__ biasRow, const float* __restrict__ biasCol,
    int statMode, double* __restrict__ statOut, int statC, int triSkip, int cosMode,
    int aMode, const float* __restrict__ Afp, size_t sAfp,
    const float* __restrict__ scA, const float* __restrict__ shA)
{
    if (triSkip && blockIdx.x < blockIdx.y) return;
    extern __shared__ ush sm[];
    const int tid = threadIdx.x;
    const int w = tid >> 5, lane = tid & 31;
    const int wm = w & 1, wn = w >> 1;
    const int m0 = blockIdx.y * 128, n0 = blockIdx.x * 128, b = blockIdx.z;
    const ush* srcs[4] = { Ah + (size_t)b*sA, Al + (size_t)b*sA,
                           Bh + (size_t)b*sB, Bl + (size_t)b*sB };
    const float* Afpb = Afp ? (Afp + (size_t)b * sAfp) : (const float*)0;
    const uint32_t smb = smem_u32(sm);

    float acc[4][4][4];
    #pragma unroll
    for (int i = 0; i < 4; i++)
        #pragma unroll
        for (int j = 0; j < 4; j++)
            #pragma unroll
            for (int q = 0; q < 4; q++) acc[i][j][q] = 0.f;

    const int T = Kp / KC;

    #define LOAD_STAGE(t, st) do { \
        int k0 = (t) * KC; \
        if (aMode == 0) { \
            _Pragma("unroll") \
            for (int arr = 0; arr < 2; arr++) { \
                const ush* S = srcs[arr]; \
                uint32_t dbase = smb + (uint32_t)(((st)*STAGEH + arr*TILEH) * 2); \
                _Pragma("unroll") \
                for (int i = 0; i < 2; i++) { \
                    int e = tid + i * 256; \
                    int r = e >> 2, c16 = e & 3; \
                    uint32_t daddr = dbase + (uint32_t)((r * RSH + c16 * 8) * 2); \
                    int rg = m0 + r; \
                    int rc = rg < M ? rg : (M - 1); \
                    const ush* sp = S + (size_t)rc * Kp + k0 + c16 * 8; \
                    int sz = (rg < M) ? 16 : 0; \
                    asm volatile("cp.async.cg.shared.global [%0], [%1], 16, %2;" \
                                 :: "r"(daddr), "l"(sp), "r"(sz)); \
                } \
            } \
        } else if (aMode == 1) { \
            _Pragma("unroll") \
            for (int i = 0; i < 8; i++) { \
                int e = tid + i * 256; \
                int r = e >> 4, cw = e & 15; \
                int rg = m0 + r, kk = k0 + cw * 2; \
                float v0 = 0.f, v1 = 0.f; \
                if (rg < M) { \
                    v0 = Afpb[(size_t)rg * Kp + kk]; \
                    v1 = Afpb[(size_t)rg * Kp + kk + 1]; \
                    v0 = scA[kk] * v0 + shA[kk];       if (v0 < 0.f) v0 *= 0.2f; \
                    v1 = scA[kk+1] * v1 + shA[kk+1];   if (v1 < 0.f) v1 *= 0.2f; \
                } \
                uint32_t lw, hw = split_pack(v0, v1, &lw); \
                int idx = (st)*STAGEH + r * RSH + cw * 2; \
                *(uint32_t*)&sm[idx] = hw; \
                *(uint32_t*)&sm[idx + TILEH] = lw; \
            } \
        } else { \
            _Pragma("unroll") \
            for (int i = 0; i < 8; i++) { \
                int e = tid + i * 256; \
                int r = e >> 4, cw = e & 15; \
                int rg = m0 + r, kk = k0 + cw * 2; \
                int kgrp = rg >> 9, sloc = rg & 511; \
                const float* Cr = Afpb + (size_t)sloc * JQ; \
                float v0 = edge_val(Cr, kgrp, kk); \
                float v1 = edge_val(Cr, kgrp, kk + 1); \
                uint32_t lw, hw = split_pack(v0, v1, &lw); \
                int idx = (st)*STAGEH + r * RSH + cw * 2; \
                *(uint32_t*)&sm[idx] = hw; \
                *(uint32_t*)&sm[idx + TILEH] = lw; \
            } \
        } \
        _Pragma("unroll") \
        for (int arr = 2; arr < 4; arr++) { \
            const ush* S = srcs[arr]; \
            uint32_t dbase = smb + (uint32_t)(((st)*STAGEH + arr*TILEH) * 2); \
            _Pragma("unroll") \
            for (int i = 0; i < 2; i++) { \
                int e = tid + i * 256; \
                int r = e >> 2, c16 = e & 3; \
                uint32_t daddr = dbase + (uint32_t)((r * RSH + c16 * 8) * 2); \
                int rg = n0 + r; \
                int rc = rg < N ? rg : (N - 1); \
                const ush* sp = S + (size_t)rc * Kp + k0 + c16 * 8; \
                int sz = (rg < N) ? 16 : 0; \
                asm volatile("cp.async.cg.shared.global [%0], [%1], 16, %2;" \
                             :: "r"(daddr), "l"(sp), "r"(sz)); \
            } \
        } \
        asm volatile("cp.async.commit_group;" ::: "memory"); \
    } while (0)

    LOAD_STAGE(0, 0);
    for (int t = 0; t < T; t++) {
        const int st = t & 1;
        if (t + 1 < T) {
            LOAD_STAGE(t + 1, st ^ 1);
            asm volatile("cp.async.wait_group 1;" ::: "memory");
        } else {
            asm volatile("cp.async.wait_group 0;" ::: "memory");
        }
        __syncthreads();
        const uint32_t uAh = smb + (uint32_t)((st*STAGEH + 0*TILEH) * 2);
        const uint32_t uAl = smb + (uint32_t)((st*STAGEH + 1*TILEH) * 2);
        const uint32_t uBh = smb + (uint32_t)((st*STAGEH + 2*TILEH) * 2);
        const uint32_t uBl = smb + (uint32_t)((st*STAGEH + 3*TILEH) * 2);
        #pragma unroll
        for (int k16 = 0; k16 < 32; k16 += 16) {
            uint32_t ah[4][4], al[4][4], bh[4][2], bl[4][2];
            {
                int arow = wm * 64 + (lane & 15);
                int akk = k16 + ((lane >> 4) << 3);
                #pragma unroll
                for (int mf = 0; mf < 4; mf++) {
                    uint32_t byteoff = (uint32_t)(((arow + mf * 16) * RSH + akk) << 1);
                    ldm4(ah[mf], uAh + byteoff);
                    ldm4(al[mf], uAl + byteoff);
                }
                int q = lane >> 3;
                int brow0 = wn * 32 + ((q >> 1) << 3) + (lane & 7);
                int bkk = k16 + ((q & 1) << 3);
                #pragma unroll
                for (int p = 0; p < 2; p++) {
                    uint32_t byteoff = (uint32_t)(((brow0 + p * 16) * RSH + bkk) << 1);
                    uint32_t tmp[4];
                    ldm4(tmp, uBh + byteoff);
                    bh[2*p][0] = tmp[0]; bh[2*p][1] = tmp[1];
                    bh[2*p+1][0] = tmp[2]; bh[2*p+1][1] = tmp[3];
                    ldm4(tmp, uBl + byteoff);
                    bl[2*p][0] = tmp[0]; bl[2*p][1] = tmp[1];
                    bl[2*p+1][0] = tmp[2]; bl[2*p+1][1] = tmp[3];
                }
            }
            #pragma unroll
            for (int mf = 0; mf < 4; mf++)
                #pragma unroll
                for (int nf = 0; nf < 4; nf++)
                    mma16816(acc[mf][nf], ah[mf], bh[nf]);
            #pragma unroll
            for (int mf = 0; mf < 4; mf++)
                #pragma unroll
                for (int nf = 0; nf < 4; nf++)
                    mma16816(acc[mf][nf], ah[mf], bl[nf]);
            #pragma unroll
            for (int mf = 0; mf < 4; mf++)
                #pragma unroll
                for (int nf = 0; nf < 4; nf++)
                    mma16816(acc[mf][nf], al[mf], bh[nf]);
        }
        __syncthreads();
    }

    if (cosMode) {
        const float* nb = g_norm + b * SQ;
        float part = 0.f;
        #pragma unroll
        for (int mf = 0; mf < 4; mf++) {
            int r = m0 + wm * 64 + mf * 16 + (lane >> 2);
            float nr0 = nb[r], nr1 = nb[r + 8];
            #pragma unroll
            for (int nf = 0; nf < 4; nf++) {
                #pragma unroll
                for (int u = 0; u < 2; u++) {
                    int col = n0 + wn * 32 + nf * 8 + ((lane & 3) << 1) + u;
                    float ncv = nb[col];
                    if (col > r) {
                        float cm = acc[mf][nf][u] / (nr0 * ncv + 1e-10f);
                        part += 2.f * cm * cm;
                    }
                    if (col > r + 8) {
                        float cm = acc[mf][nf][u + 2] / (nr1 * ncv + 1e-10f);
                        part += 2.f * cm * cm;
                    }
                }
            }
        }
        float* red = (float*)sm;
        red[tid] = part; __syncthreads();
        for (int off = 128; off > 0; off >>= 1) {
            if (tid < off) red[tid] += red[tid + off];
            __syncthreads();
        }
        if (tid == 0) atomicAdd(&g_acc[b], red[0]);
        return;
    }

    float cs[8], cq[8];
    #pragma unroll
    for (int i = 0; i < 8; i++) { cs[i] = 0.f; cq[i] = 0.f; }
    float* Cb = C + (size_t)b * sC;
    #pragma unroll
    for (int mf = 0; mf < 4; mf++) {
        int r = m0 + wm * 64 + mf * 16 + (lane >> 2);
        float br0 = biasRow ? biasRow[r] : 0.f;
        float br1 = biasRow ? biasRow[r + 8] : 0.f;
        #pragma unroll
        for (int nf = 0; nf < 4; nf++) {
            int c = n0 + wn * 32 + nf * 8 + ((lane & 3) << 1);
            #pragma unroll
            for (int u = 0; u < 2; u++) {
                int col = c + u;
                float bc = (biasCol && col < N) ? biasCol[col] : 0.f;
                float v0 = acc[mf][nf][u]     + br0 + bc;
                float v1 = acc[mf][nf][u + 2] + br1 + bc;
                if (col < N) {
                    Cb[(size_t)r * N + col]       = v0;
                    Cb[(size_t)(r + 8) * N + col] = v1;
                }
                if (statMode == 1) {
                    cs[nf*2+u] += v0 + v1;
                    cq[nf*2+u] += v0*v0 + v1*v1;
                } else if (statMode == 2) {
                    cs[mf*2]   += v0; cq[mf*2]   += v0*v0;
                    cs[mf*2+1] += v1; cq[mf*2+1] += v1*v1;
                }
            }
        }
    }
    if (statMode == 0) return;
    float* ssum = (float*)sm;
    float* ssq  = ssum + 2048;
    if (statMode == 1) {
        int g = wm * 8 + (lane >> 2);
        #pragma unroll
        for (int nf = 0; nf < 4; nf++)
            #pragma unroll
            for (int u = 0; u < 2; u++) {
                int colL = wn * 32 + nf * 8 + ((lane & 3) << 1) + u;
                ssum[colL * 16 + g] = cs[nf*2+u];
                ssq [colL * 16 + g] = cq[nf*2+u];
            }
        __syncthreads();
        if (tid < 128) {
            double s = 0.0, q = 0.0;
            #pragma unroll
            for (int g2 = 0; g2 < 16; g2++) { s += ssum[tid*16+g2]; q += ssq[tid*16+g2]; }
            int gcol = n0 + tid;
            if (gcol < N) {
                int chunk = blockIdx.z * gridDim.y + blockIdx.y;
                statOut[((size_t)chunk * statC + gcol) * 2]     = s;
                statOut[((size_t)chunk * statC + gcol) * 2 + 1] = q;
            }
        }
    } else {
        int h = wn * 4 + (lane & 3);
        #pragma unroll
        for (int mf = 0; mf < 4; mf++)
            #pragma unroll
            for (int hf = 0; hf < 2; hf++) {
                int rowL = wm * 64 + mf * 16 + (lane >> 2) + hf * 8;
                ssum[rowL * 16 + h] = cs[mf*2+hf];
                ssq [rowL * 16 + h] = cq[mf*2+hf];
            }
        __syncthreads();
        if (tid < 128) {
            double s = 0.0, q = 0.0;
            #pragma unroll
            for (int h2 = 0; h2 < 16; h2++) { s += ssum[tid*16+h2]; q += ssq[tid*16+h2]; }
            int grow = m0 + tid;
            int chunk = blockIdx.z * gridDim.x + blockIdx.x;
            statOut[((size_t)chunk * statC + grow) * 2]     = s;
            statOut[((size_t)chunk * statC + grow) * 2 + 1] = q;
        }
    }
}

// ---------------- elementwise / setup kernels ----------------
__global__ void sa_init() {
    int i = blockIdx.x * 256 + threadIdx.x;
    if (i < NQ) g_flags[i] = 0;
    if (i < BQ) g_acc[i] = 0.f;
}

__global__ void cv_split(const float* __restrict__ src, ush* __restrict__ dh, ush* __restrict__ dl,
                         long long totalPairs, int Ksrc, int Kp,
                         const float* __restrict__ sc, const float* __restrict__ sh, int leaky)
{
    long long i = (long long)blockIdx.x * 256 + threadIdx.x;
    if (i >= totalPairs) return;
    long long e = i * 2;
    int c = (int)(e % Kp);
    long long r = e / Kp;
    float v0 = 0.f, v1 = 0.f;
    if (c < Ksrc) {
        v0 = src[r * Ksrc + c];
        if (sc) { v0 = sc[c]*v0 + sh[c]; if (leaky && v0 < 0.f) v0 *= 0.2f; }
    }
    if (c + 1 < Ksrc) {
        v1 = src[r * Ksrc + c + 1];
        if (sc) { v1 = sc[c+1]*v1 + sh[c+1]; if (leaky && v1 < 0.f) v1 *= 0.2f; }
    }
    uint32_t lw, hw = split_pack(v0, v1, &lw);
    ((uint32_t*)dh)[i] = hw;
    ((uint32_t*)dl)[i] = lw;
}

__global__ void cv_agg(const float* __restrict__ points, const float* __restrict__ xyz) {
    long long i = (long long)blockIdx.x * 256 + threadIdx.x;
    if (i >= (long long)BQ*NQ*KP1/2) return;
    long long e = i * 2;
    int c = (int)(e % KP1); long long r = e / KP1;
    int n = (int)(r % NQ); int b = (int)(r / NQ);
    float v0 = 0.f, v1 = 0.f;
    if (c < DQ) v0 = points[((size_t)b*DQ + c)*NQ + n];
    else if (c < SCQ) v0 = xyz[((size_t)b*3 + (c-DQ))*NQ + n];
    int c1 = c + 1;
    if (c1 < DQ) v1 = points[((size_t)b*DQ + c1)*NQ + n];
    else if (c1 < SCQ) v1 = xyz[((size_t)b*3 + (c1-DQ))*NQ + n];
    uint32_t lw, hw = split_pack(v0, v1, &lw);
    ((uint32_t*)g_aggc_h)[i] = hw;
    ((uint32_t*)g_aggc_l)[i] = lw;
}

__global__ void sa_ball(const float* __restrict__ xyz) {
    int w = (blockIdx.x * blockDim.x + threadIdx.x) >> 5;
    int lane = threadIdx.x & 31;
    if (w >= BQ * NQ) return;
    int b = w / NQ, n = w % NQ;
    const float* X = xyz + (size_t)b * 3 * NQ;
    float px = X[n], py = X[NQ+n], pz = X[2*NQ+n];
    float pn = px*px + py*py + pz*pz;
    const float RR = (float)(0.2 * 0.2);
    int* out = g_idx + (size_t)b * NSQ * NQ + n;
    int cnt = 0;
    for (int j0 = 0; j0 < NQ && cnt < NSQ; j0 += 32) {
        int j = j0 + lane;
        float qx = X[j], qy = X[NQ+j], qz = X[2*NQ+j];
        float sq = (pn + qx*qx+qy*qy+qz*qz) - 2.0f*(px*qx+py*qy+pz*qz);
        bool in = !(sq > RR);
        unsigned m = __ballot_sync(0xffffffffu, in);
        int pos = cnt + __popc(m & ((1u << lane) - 1u));
        if (in && pos < NSQ) out[(size_t)pos * NQ] = j;
        cnt += __popc(m);
    }
    __syncwarp();
    if (lane == 0) {
        int first = out[0];
        for (int t = cnt; t < NSQ; t++) out[(size_t)t * NQ] = first;
    }
}

__global__ void sa_bmt_c(const float* __restrict__ points, const float* __restrict__ xyz) {
    int n = (blockIdx.x * 256 + threadIdx.x) * 2;
    int j = blockIdx.y, b = blockIdx.z;
    float v0, v1;
    if (j < OFF_P) {
        const float* p = xyz + ((size_t)b*3 + j)*NQ;
        v0 = p[n]; v1 = p[n+1];
    } else if (j < OFF_GP) {
        const float* p = points + ((size_t)b*DQ + (j-OFF_P))*NQ;
        v0 = p[n]; v1 = p[n+1];
    } else if (j < OFF_GX) {
        int t = j - OFF_GP, k = t >> 6, d = t & 63;
        const int* ip = g_idx + ((size_t)b*NSQ + k)*NQ;
        const float* p = points + ((size_t)b*DQ + d)*NQ;
        v0 = p[ip[n]]; v1 = p[ip[n+1]];
    } else {
        int t = j - OFF_GX, k = t / 3, c = t % 3;
        const int* ip = g_idx + ((size_t)b*NSQ + k)*NQ;
        const float* p = xyz + ((size_t)b*3 + c)*NQ;
        v0 = p[ip[n]]; v1 = p[ip[n+1]];
    }
    size_t o = (((size_t)b*JQ + j)*NQ + n) >> 1;
    uint32_t lw, hw = split_pack(v0, v1, &lw);
    ((uint32_t*)g_BmTc_h)[o] = hw;
    ((uint32_t*)g_BmTc_l)[o] = lw;
}

__global__ void sa_cs_fin(int C, int nChunks, int count,
                          const float* __restrict__ gamma, const float* __restrict__ beta,
                          float* __restrict__ sc, float* __restrict__ sf) {
    int c = blockIdx.x, tid = threadIdx.x;
    double s = 0.0, s2 = 0.0;
    for (int i = tid; i < nChunks; i += 256) {
        s  += g_part[((size_t)i * C + c) * 2];
        s2 += g_part[((size_t)i * C + c) * 2 + 1];
    }
    __shared__ double sa[256], sb2[256];
    sa[tid] = s; sb2[tid] = s2; __syncthreads();
    for (int o = 128; o > 0; o >>= 1) {
        if (tid < o) { sa[tid] += sa[tid+o]; sb2[tid] += sb2[tid+o]; }
        __syncthreads();
    }
    if (tid == 0) {
        double n = (double)count, m = sa[0] / n;
        double var = sb2[0] / n - m * m; if (var < 0.0) var = 0.0;
        float scale = gamma[c] * rsqrtf((float)var + 1e-5f);
        sc[c] = scale; sf[c] = beta[c] - (float)m * scale;
    }
}

__global__ void sa_softmax(float* __restrict__ H) {
    int s = blockIdx.x, b = blockIdx.y, tid = threadIdx.x;
    float* row = H + ((size_t)b * SQ + s) * NQ;
    __shared__ float buf[NQ];
    __shared__ float red[256], rv[256];
    __shared__ int ri[256];
    float a = g_s2[s], sh = g_sh2[s];
    float lmax = -3.4e38f;
    for (int i = tid; i < NQ; i += 256) { float y = a*row[i]+sh; buf[i] = y; lmax = fmaxf(lmax, y); }
    red[tid] = lmax; __syncthreads();
    for (int o = 128; o > 0; o >>= 1) { if (tid < o) red[tid] = fmaxf(red[tid], red[tid+o]); __syncthreads(); }
    float gmax = red[0]; __syncthreads();
    float lsum = 0.f;
    for (int i = tid; i < NQ; i += 256) { float e = expf(buf[i]-gmax); buf[i] = e; lsum += e; }
    red[tid] = lsum; __syncthreads();
    for (int o = 128; o > 0; o >>= 1) { if (tid < o) red[tid] += red[tid+o]; __syncthreads(); }
    float inv = 1.f / red[0]; __syncthreads();
    float lss = 0.f, bm = -1.f; int bi = 0;
    size_t rowoff = ((size_t)b * SQ + s) * NQ;
    for (int i = tid; i < NQ; i += 256) {
        float v = buf[i] * inv; lss += v*v;
        split_write(v, g_Sc_h + rowoff + i, g_Sc_l + rowoff + i);
        if (v > bm) { bm = v; bi = i; }
    }
    red[tid] = lss; rv[tid] = bm; ri[tid] = bi; __syncthreads();
    for (int o = 128; o > 0; o >>= 1) {
        if (tid < o) {
            red[tid] += red[tid+o];
            if (rv[tid+o] > rv[tid] || (rv[tid+o] == rv[tid] && ri[tid+o] < ri[tid])) { rv[tid] = rv[tid+o]; ri[tid] = ri[tid+o]; }
        }
        __syncthreads();
    }
    if (tid == 0) {
        g_norm[b*SQ+s] = sqrtf(red[0]);
        if (b == 0) g_amax[s] = ri[0];
    }
}

__global__ void sa_flags() { int s = blockIdx.x*256 + threadIdx.x; if (s < SQ) g_flags[g_amax[s]] = 1; }

__global__ void sa_newxyz(float* __restrict__ out) {
    int i = blockIdx.x * 256 + threadIdx.x;
    if (i >= BQ*3*SQ) return;
    int s = i % SQ, c = (i/SQ) % 3, b = i/(3*SQ);
    out[i] = g_Cbig[((size_t)b*SQ + s)*JQ + OFF_X + c];
}

__global__ void sa_max(float* __restrict__ out) {
    int s = blockIdx.x, b = blockIdx.y, o = threadIdx.x;
    float sc = g_sc2[o], sf = g_sf2[o];
    float m = -3.4e38f;
    const float* base = g_O2T + ((size_t)b*KSQ + s)*C2Q + o;
    #pragma unroll
    for (int k = 0; k < NSQ; k++) {
        float y = sc * base[(size_t)k*SQ*C2Q] + sf;
        y = (y >= 0.f) ? y : 0.2f * y;
        m = fmaxf(m, y);
    }
    out[XYZ_OUT + ((size_t)b*C2Q + o)*SQ + s] = m;
}

__global__ void sa_scalars(float* __restrict__ out) {
    __shared__ float sfr[256]; __shared__ int sir[256];
    int tid = threadIdx.x;
    int cnt = 0;
    for (int i = tid; i < NQ; i += 256) cnt += g_flags[i];
    float l = (tid < BQ) ? sqrtf(g_acc[tid]) : 0.f;
    sfr[tid] = l; sir[tid] = cnt; __syncthreads();
    for (int o = 128; o > 0; o >>= 1) {
        if (tid < o) { sfr[tid] += sfr[tid+o]; sir[tid] += sir[tid+o]; }
        __syncthreads();
    }
    if (tid == 0) {
        out[XYZ_OUT + NP_OUT] = sfr[0] / (float)BQ;
        out[XYZ_OUT + NP_OUT + 1] = (float)sir[0];
    }
}

// ---------------- launch ----------------
static inline float*  symf(const void* sym) { void* p = nullptr; cudaGetSymbolAddress(&p, sym); return (float*)p; }
static inline ush*    symu(const void* sym) { void* p = nullptr; cudaGetSymbolAddress(&p, sym); return (ush*)p; }
static inline double* symd(const void* sym) { void* p = nullptr; cudaGetSymbolAddress(&p, sym); return (double*)p; }

extern "C" void kernel_launch(void* const* d_in, const int* in_sizes, int n_in,
                              void* d_out, int out_size)
{
    const float* xyz   = (const float*)d_in[0];
    const float* points= (const float*)d_in[1];
    const float* w1_w = (const float*)d_in[2];
    const float* w1_b = (const float*)d_in[3];
    const float* bn1g = (const float*)d_in[4];
    const float* bn1b = (const float*)d_in[5];
    const float* w2_w = (const float*)d_in[6];
    const float* w2_b = (const float*)d_in[7];
    const float* bn2g = (const float*)d_in[8];
    const float* bn2b = (const float*)d_in[9];
    const float* c0w = (const float*)d_in[10];
    const float* c0b = (const float*)d_in[11];
    const float* g0  = (const float*)d_in[12];
    const float* b0  = (const float*)d_in[13];
    const float* c1w = (const float*)d_in[14];
    const float* c1b = (const float*)d_in[15];
    const float* g1  = (const float*)d_in[16];
    const float* b1  = (const float*)d_in[17];
    const float* c2w = (const float*)d_in[18];
    const float* c2b = (const float*)d_in[19];
    const float* g2  = (const float*)d_in[20];
    const float* b2  = (const float*)d_in[21];
    float* out = (float*)d_out;

    static bool inited = false;
    static cudaStream_t s1;
    static cudaEvent_t eA, eB, eS, eG;
    if (!inited) {
        cudaFuncSetAttribute(mma_gemm, cudaFuncAttributeMaxDynamicSharedMemorySize, SMEM_BYTES);
        cudaStreamCreateWithFlags(&s1, cudaStreamNonBlocking);
        cudaEventCreateWithFlags(&eA, cudaEventDisableTiming);
        cudaEventCreateWithFlags(&eB, cudaEventDisableTiming);
        cudaEventCreateWithFlags(&eS, cudaEventDisableTiming);
        cudaEventCreateWithFlags(&eG, cudaEventDisableTiming);
        inited = true;
    }

    float* p_h1t = symf(g_h1t);
    float* p_h2  = symf(g_h2);
    float* p_C   = symf(g_Cbig);
    float* p_O0  = symf(g_O0T);
    float* p_O1  = symf(g_O1T);
    float* p_O2  = symf(g_O2T);
    double* p_part = symd(g_part);
    float* p_s1 = symf(g_s1), *p_sh1 = symf(g_sh1);
    float* p_s2 = symf(g_s2), *p_sh2 = symf(g_sh2);
    float* p_sc0 = symf(g_sc0), *p_sf0 = symf(g_sf0);
    float* p_sc1 = symf(g_sc1), *p_sf1 = symf(g_sf1);
    float* p_sc2 = symf(g_sc2), *p_sf2 = symf(g_sf2);
    ush *aggh = symu(g_aggc_h), *aggl = symu(g_aggc_l);
    ush *w1h = symu(g_w1c_h), *w1l = symu(g_w1c_l);
    ush *h1h = symu(g_h1c_h), *h1l = symu(g_h1c_l);
    ush *w2h = symu(g_w2c_h), *w2l = symu(g_w2c_l);
    ush *Sh = symu(g_Sc_h), *Sl = symu(g_Sc_l);
    ush *Bmh = symu(g_BmTc_h), *Bml = symu(g_BmTc_l);
    ush *w0h = symu(g_c0wc_h), *w0l = symu(g_c0wc_l);
    ush *c1h = symu(g_c1wc_h), *c1l = symu(g_c1wc_l);
    ush *c2h = symu(g_c2wc_h), *c2l = symu(g_c2wc_l);

    // fork: side chain (ball -> BmT build -> conv-weight splits) on s1
    cudaEventRecord(eA, 0);
    cudaStreamWaitEvent(s1, eA, 0);
    sa_ball<<<(BQ*NQ*32)/256, 256, 0, s1>>>(xyz);
    sa_bmt_c<<<dim3(NQ/512, JQ, BQ), 256, 0, s1>>>(points, xyz);
    cv_split<<<(C0Q*KPE/2 + 255)/256, 256, 0, s1>>>(c0w, w0h, w0l, (long long)C0Q*KPE/2, INCH, KPE, nullptr, nullptr, 0);
    cv_split<<<(C1Q*C0Q/2 + 255)/256, 256, 0, s1>>>(c1w, c1h, c1l, (long long)C1Q*C0Q/2, C0Q, C0Q, nullptr, nullptr, 0);
    cv_split<<<(C2Q*C1Q/2 + 255)/256, 256, 0, s1>>>(c2w, c2h, c2l, (long long)C2Q*C1Q/2, C1Q, C1Q, nullptr, nullptr, 0);
    cudaEventRecord(eB, s1);

    // main chain
    sa_init<<<9, 256>>>();
    cv_agg<<<(int)(((long long)BQ*NQ*KP1/2 + 255)/256), 256>>>(points, xyz);
    cv_split<<<(SCQ*KP1/2 + 255)/256, 256>>>(w1_w, w1h, w1l, (long long)SCQ*KP1/2, SCQ, KP1, nullptr, nullptr, 0);
    cv_split<<<(SQ*KP1/2 + 255)/256, 256>>>(w2_w, w2h, w2l, (long long)SQ*KP1/2, SCQ, KP1, nullptr, nullptr, 0);

    // h1t = aggT * w1^T + w1_b ; col-stats fused
    mma_gemm<<<dim3(1, NQ/128, BQ), 256, SMEM_BYTES>>>(aggh, aggl, w1h, w1l, p_h1t,
        NQ, SCQ, KP1, (size_t)NQ*KP1, 0, (size_t)NQ*SCQ, nullptr, w1_b, 1, p_part, SCQ, 0, 0,
        0, nullptr, 0, nullptr, nullptr);
    sa_cs_fin<<<SCQ, 256>>>(SCQ, BQ*(NQ/128), BQ*NQ, bn1g, bn1b, p_s1, p_sh1);
    cv_split<<<(int)(((long long)BQ*NQ*KP1/2 + 255)/256), 256>>>(p_h1t, h1h, h1l,
        (long long)BQ*NQ*KP1/2, SCQ, KP1, p_s1, p_sh1, 0);

    // h2 = w2 * bn1(h1)^T + w2_b ; row-stats fused
    mma_gemm<<<dim3(NQ/128, SQ/128, BQ), 256, SMEM_BYTES>>>(w2h, w2l, h1h, h1l, p_h2,
        SQ, NQ, KP1, 0, (size_t)NQ*KP1, (size_t)SQ*NQ, w2_b, nullptr, 2, p_part, SQ, 0, 0,
        0, nullptr, 0, nullptr, nullptr);
    sa_cs_fin<<<SQ, 256>>>(SQ, BQ*(NQ/128), BQ*NQ, bn2g, bn2b, p_s2, p_sh2);
    sa_softmax<<<dim3(SQ, BQ), 256>>>(p_h2);
    cudaEventRecord(eS, 0);
    sa_flags<<<2, 256>>>();

    // Gram + cosine loss on s1 (overlaps Cbig/conv0 on main stream)
    cudaStreamWaitEvent(s1, eS, 0);
    mma_gemm<<<dim3(SQ/128, SQ/128, BQ), 256, SMEM_BYTES, s1>>>(Sh, Sl, Sh, Sl, p_h2,
        SQ, SQ, NQ, (size_t)SQ*NQ, (size_t)SQ*NQ, 0, nullptr, nullptr, 0, nullptr, 0, 1, 1,
        0, nullptr, 0, nullptr, nullptr);
    cudaEventRecord(eG, s1);

    // Cbig = S * BmT^T (needs BmT from side chain)
    cudaStreamWaitEvent(0, eB, 0);
    mma_gemm<<<dim3((JQ+127)/128, SQ/128, BQ), 256, SMEM_BYTES>>>(Sh, Sl, Bmh, Bml, p_C,
        SQ, JQ, NQ, (size_t)SQ*NQ, (size_t)JQ*NQ, (size_t)SQ*JQ, nullptr, nullptr, 0, nullptr, 0, 0, 0,
        0, nullptr, 0, nullptr, nullptr);
    sa_newxyz<<<(BQ*3*SQ + 255)/256, 256>>>(out);

    // conv0: A = edge features from Cbig in-loader
    mma_gemm<<<dim3(1, KSQ/128, BQ), 256, SMEM_BYTES>>>(w0h, w0l, w0h, w0l, p_O0,
        KSQ, C0Q, KPE, 0, 0, (size_t)KSQ*C0Q, nullptr, c0b, 1, p_part, C0Q, 0, 0,
        2, p_C, (size_t)SQ*JQ, nullptr, nullptr);
    sa_cs_fin<<<C0Q, 256>>>(C0Q, BQ*(KSQ/128), BQ*KSQ, g0, b0, p_sc0, p_sf0);

    // conv1: A = bn-affine+leaky of O0 fp32 in-loader
    mma_gemm<<<dim3(1, KSQ/128, BQ), 256, SMEM_BYTES>>>(c1h, c1l, c1h, c1l, p_O1,
        KSQ, C1Q, C0Q, 0, 0, (size_t)KSQ*C1Q, nullptr, c1b, 1, p_part, C1Q, 0, 0,
        1, p_O0, (size_t)KSQ*C0Q, p_sc0, p_sf0);
    sa_cs_fin<<<C1Q, 256>>>(C1Q, BQ*(KSQ/128), BQ*KSQ, g1, b1, p_sc1, p_sf1);

    // conv2: A = bn-affine+leaky of O1 fp32 in-loader
    mma_gemm<<<dim3(C2Q/128, KSQ/128, BQ), 256, SMEM_BYTES>>>(c2h, c2l, c2h, c2l, p_O2,
        KSQ, C2Q, C1Q, 0, 0, (size_t)KSQ*C2Q, nullptr, c2b, 1, p_part, C2Q, 0, 0,
        1, p_O1, (size_t)KSQ*C1Q, p_sc1, p_sf1);
    sa_cs_fin<<<C2Q, 256>>>(C2Q, BQ*(KSQ/128), BQ*KSQ, g2, b2, p_sc2, p_sf2);

    sa_max<<<dim3(SQ, BQ), 256>>>(out);
    // join Gram branch before final scalars
    cudaStreamWaitEvent(0, eG, 0);
    sa_scalars<<<1, 256>>>(out);
}

// round 11
// speedup vs baseline: 1.8691x; 1.0271x over previous
#include <cuda_runtime.h>
#include <cuda_bf16.h>
#include <math.h>
#include <stdint.h>

#define BQ 16
#define NQ 2048
#define DQ 64
#define SQ 512
#define NSQ 32
#define SCQ 67
#define INCH 134
#define C0Q 128
#define C1Q 128
#define C2Q 256
#define KSQ (NSQ*SQ)
#define JQ (3+DQ+NSQ*DQ+NSQ*3)   // 2211
#define OFF_X 0
#define OFF_P 3
#define OFF_GP 67
#define OFF_GX 2115
#define XYZ_OUT (BQ*3*SQ)
#define NP_OUT  ((size_t)BQ*C2Q*SQ)
#define KP1 96
#define KPE 160

typedef unsigned short ush;

// ---------------- fp32 scratch ----------------
__device__ float g_h1t [(size_t)BQ*NQ*SCQ];
__device__ float g_h2  [(size_t)BQ*SQ*NQ];
__device__ float g_Cbig[(size_t)BQ*SQ*JQ];
__device__ float g_O0T [(size_t)BQ*KSQ*C0Q];
__device__ float g_O1T [(size_t)BQ*KSQ*C1Q];
__device__ float g_O2T [(size_t)BQ*KSQ*C2Q];
__device__ float g_norm[BQ*SQ];
__device__ int   g_amax[SQ];
__device__ int   g_idx[(size_t)BQ*NSQ*NQ];
__device__ double g_part[(size_t)2048*256*2];
__device__ float g_s1[SCQ], g_sh1[SCQ];
__device__ float g_s2[SQ],  g_sh2[SQ];
__device__ float g_sc0[C0Q], g_sf0[C0Q];
__device__ float g_sc1[C1Q], g_sf1[C1Q];
__device__ float g_sc2[C2Q], g_sf2[C2Q];
__device__ float g_acc[BQ];
__device__ int   g_flags[NQ];

// ---------------- bf16 hi/lo operand arrays ----------------
__device__ ush g_aggc_h[(size_t)BQ*NQ*KP1],  g_aggc_l[(size_t)BQ*NQ*KP1];
__device__ ush g_w1c_h[SCQ*KP1],             g_w1c_l[SCQ*KP1];
__device__ ush g_h1c_h[(size_t)BQ*NQ*KP1],   g_h1c_l[(size_t)BQ*NQ*KP1];
__device__ ush g_w2c_h[SQ*KP1],              g_w2c_l[SQ*KP1];
__device__ ush g_Sc_h[(size_t)BQ*SQ*NQ],     g_Sc_l[(size_t)BQ*SQ*NQ];
__device__ ush g_BmTc_h[(size_t)BQ*JQ*NQ],   g_BmTc_l[(size_t)BQ*JQ*NQ];
__device__ ush g_c0wc_h[C0Q*KPE],            g_c0wc_l[C0Q*KPE];
__device__ ush g_c1wc_h[C1Q*C0Q],            g_c1wc_l[C1Q*C0Q];
__device__ ush g_c2wc_h[C2Q*C1Q],            g_c2wc_l[C2Q*C1Q];

// ---------------- helpers ----------------
__device__ __forceinline__ uint32_t smem_u32(const void* p) {
    uint32_t a;
    asm("{ .reg .u64 t; cvta.to.shared.u64 t, %1; cvt.u32.u64 %0, t; }" : "=r"(a) : "l"(p));
    return a;
}
__device__ __forceinline__ void ldm4(uint32_t* r, uint32_t addr) {
    asm volatile("ldmatrix.sync.aligned.m8n8.x4.shared.b16 {%0,%1,%2,%3}, [%4];"
        : "=r"(r[0]), "=r"(r[1]), "=r"(r[2]), "=r"(r[3]) : "r"(addr));
}
__device__ __forceinline__ void mma16816(float* c, const uint32_t* a, const uint32_t* b) {
    asm volatile("mma.sync.aligned.m16n8k16.row.col.f32.bf16.bf16.f32 "
        "{%0,%1,%2,%3}, {%4,%5,%6,%7}, {%8,%9}, {%0,%1,%2,%3};"
        : "+f"(c[0]), "+f"(c[1]), "+f"(c[2]), "+f"(c[3])
        : "r"(a[0]), "r"(a[1]), "r"(a[2]), "r"(a[3]), "r"(b[0]), "r"(b[1]));
}
__device__ __forceinline__ uint32_t split_pack(float v0, float v1, uint32_t* lo) {
    __nv_bfloat16 h0 = __float2bfloat16(v0), h1 = __float2bfloat16(v1);
    __nv_bfloat16 l0 = __float2bfloat16(v0 - __bfloat162float(h0));
    __nv_bfloat16 l1 = __float2bfloat16(v1 - __bfloat162float(h1));
    *lo = ((uint32_t)__bfloat16_as_ushort(l1) << 16) | __bfloat16_as_ushort(l0);
    return ((uint32_t)__bfloat16_as_ushort(h1) << 16) | __bfloat16_as_ushort(h0);
}
__device__ __forceinline__ void split_write(float v, ush* ph, ush* pl) {
    __nv_bfloat16 h = __float2bfloat16(v);
    __nv_bfloat16 l = __float2bfloat16(v - __bfloat162float(h));
    *ph = __bfloat16_as_ushort(h);
    *pl = __bfloat16_as_ushort(l);
}
__device__ __forceinline__ float edge_val(const float* __restrict__ Cr, int k, int c) {
    if (c < 64) return Cr[OFF_P + c];
    if (c < 128) { int d = c - 64; return Cr[OFF_GP + k*DQ + d] - Cr[OFF_P + d]; }
    if (c < 131) return Cr[OFF_X + (c - 128)];
    if (c < INCH) { int c3 = c - 131; return Cr[OFF_GX + k*3 + c3] - Cr[OFF_X + c3]; }
    return 0.f;
}

// ---------------- pipelined HMMA GEMM (2-stage) with fused loaders/epilogues ----
#define KC 32
#define RSH 40
#define TILEH (128*RSH)
#define STAGEH (4*TILEH)
#define SMEM_BYTES (2*STAGEH*2)   // 81920 B
__global__ void __launch_bounds__(256, 2) mma_gemm(
    const ush* __restrict__ Ah, const ush* __restrict__ Al,
    const ush* __restrict__ Bh, const ush* __restrict__ Bl,
    float* __restrict__ C, int M, int N, int Kp,
    size_t sA, size_t sB, size_t sC,
    const float* __restrict__ biasRow, const float* __restrict__ biasCol,
    int statMode, double* __restrict__ statOut, int statC, int triSkip, int cosMode,
    int aMode, const float* __restrict__ Afp, size_t sAfp,
    const float* __restrict__ scA, const float* __restrict__ shA)
{
    if (triSkip && blockIdx.x < blockIdx.y) return;
    extern __shared__ ush sm[];
    const int tid = threadIdx.x;
    const int w = tid >> 5, lane = tid & 31;
    const int wm = w & 1, wn = w >> 1;
    const int m0 = blockIdx.y * 128, n0 = blockIdx.x * 128, b = blockIdx.z;
    const ush* srcs[4] = { Ah + (size_t)b*sA, Al + (size_t)b*sA,
                           Bh + (size_t)b*sB, Bl + (size_t)b*sB };
    const float* Afpb = Afp ? (Afp + (size_t)b * sAfp) : (const float*)0;
    const uint32_t smb = smem_u32(sm);

    float acc[4][4][4];
    #pragma unroll
    for (int i = 0; i < 4; i++)
        #pragma unroll
        for (int j = 0; j < 4; j++)
            #pragma unroll
            for (int q = 0; q < 4; q++) acc[i][j][q] = 0.f;

    const int T = Kp / KC;

    #define LOAD_STAGE(t, st) do { \
        int k0 = (t) * KC; \
        if (aMode == 0) { \
            _Pragma("unroll") \
            for (int arr = 0; arr < 2; arr++) { \
                const ush* S = srcs[arr]; \
                uint32_t dbase = smb + (uint32_t)(((st)*STAGEH + arr*TILEH) * 2); \
                _Pragma("unroll") \
                for (int i = 0; i < 2; i++) { \
                    int e = tid + i * 256; \
                    int r = e >> 2, c16 = e & 3; \
                    uint32_t daddr = dbase + (uint32_t)((r * RSH + c16 * 8) * 2); \
                    int rg = m0 + r; \
                    int rc = rg < M ? rg : (M - 1); \
                    const ush* sp = S + (size_t)rc * Kp + k0 + c16 * 8; \
                    int sz = (rg < M) ? 16 : 0; \
                    asm volatile("cp.async.cg.shared.global [%0], [%1], 16, %2;" \
                                 :: "r"(daddr), "l"(sp), "r"(sz)); \
                } \
            } \
        } else if (aMode == 1) { \
            _Pragma("unroll") \
            for (int i = 0; i < 8; i++) { \
                int e = tid + i * 256; \
                int r = e >> 4, cw = e & 15; \
                int rg = m0 + r, kk = k0 + cw * 2; \
                float v0 = 0.f, v1 = 0.f; \
                if (rg < M) { \
                    v0 = Afpb[(size_t)rg * Kp + kk]; \
                    v1 = Afpb[(size_t)rg * Kp + kk + 1]; \
                    v0 = scA[kk] * v0 + shA[kk];       if (v0 < 0.f) v0 *= 0.2f; \
                    v1 = scA[kk+1] * v1 + shA[kk+1];   if (v1 < 0.f) v1 *= 0.2f; \
                } \
                uint32_t lw, hw = split_pack(v0, v1, &lw); \
                int idx = (st)*STAGEH + r * RSH + cw * 2; \
                *(uint32_t*)&sm[idx] = hw; \
                *(uint32_t*)&sm[idx + TILEH] = lw; \
            } \
        } else { \
            _Pragma("unroll") \
            for (int i = 0; i < 8; i++) { \
                int e = tid + i * 256; \
                int r = e >> 4, cw = e & 15; \
                int rg = m0 + r, kk = k0 + cw * 2; \
                int kgrp = rg >> 9, sloc = rg & 511; \
                const float* Cr = Afpb + (size_t)sloc * JQ; \
                float v0 = edge_val(Cr, kgrp, kk); \
                float v1 = edge_val(Cr, kgrp, kk + 1); \
                uint32_t lw, hw = split_pack(v0, v1, &lw); \
                int idx = (st)*STAGEH + r * RSH + cw * 2; \
                *(uint32_t*)&sm[idx] = hw; \
                *(uint32_t*)&sm[idx + TILEH] = lw; \
            } \
        } \
        _Pragma("unroll") \
        for (int arr = 2; arr < 4; arr++) { \
            const ush* S = srcs[arr]; \
            uint32_t dbase = smb + (uint32_t)(((st)*STAGEH + arr*TILEH) * 2); \
            _Pragma("unroll") \
            for (int i = 0; i < 2; i++) { \
                int e = tid + i * 256; \
                int r = e >> 2, c16 = e & 3; \
                uint32_t daddr = dbase + (uint32_t)((r * RSH + c16 * 8) * 2); \
                int rg = n0 + r; \
                int rc = rg < N ? rg : (N - 1); \
                const ush* sp = S + (size_t)rc * Kp + k0 + c16 * 8; \
                int sz = (rg < N) ? 16 : 0; \
                asm volatile("cp.async.cg.shared.global [%0], [%1], 16, %2;" \
                             :: "r"(daddr), "l"(sp), "r"(sz)); \
            } \
        } \
        asm volatile("cp.async.commit_group;" ::: "memory"); \
    } while (0)

    LOAD_STAGE(0, 0);
    for (int t = 0; t < T; t++) {
        const int st = t & 1;
        if (t + 1 < T) {
            LOAD_STAGE(t + 1, st ^ 1);
            asm volatile("cp.async.wait_group 1;" ::: "memory");
        } else {
            asm volatile("cp.async.wait_group 0;" ::: "memory");
        }
        __syncthreads();
        const uint32_t uAh = smb + (uint32_t)((st*STAGEH + 0*TILEH) * 2);
        const uint32_t uAl = smb + (uint32_t)((st*STAGEH + 1*TILEH) * 2);
        const uint32_t uBh = smb + (uint32_t)((st*STAGEH + 2*TILEH) * 2);
        const uint32_t uBl = smb + (uint32_t)((st*STAGEH + 3*TILEH) * 2);
        #pragma unroll
        for (int k16 = 0; k16 < 32; k16 += 16) {
            const int arow = wm * 64 + (lane & 15);
            const int akk = k16 + ((lane >> 4) << 3);
            uint32_t bh[4][2], bl[4][2];
            {
                int q = lane >> 3;
                int brow0 = wn * 32 + ((q >> 1) << 3) + (lane & 7);
                int bkk = k16 + ((q & 1) << 3);
                #pragma unroll
                for (int p = 0; p < 2; p++) {
                    uint32_t byteoff = (uint32_t)(((brow0 + p * 16) * RSH + bkk) << 1);
                    uint32_t tmp[4];
                    ldm4(tmp, uBh + byteoff);
                    bh[2*p][0] = tmp[0]; bh[2*p][1] = tmp[1];
                    bh[2*p+1][0] = tmp[2]; bh[2*p+1][1] = tmp[3];
                    ldm4(tmp, uBl + byteoff);
                    bl[2*p][0] = tmp[0]; bl[2*p][1] = tmp[1];
                    bl[2*p+1][0] = tmp[2]; bl[2*p+1][1] = tmp[3];
                }
            }
            {
                // hi-A passes first: keeps ah live only through these two passes
                uint32_t ah[4][4];
                #pragma unroll
                for (int mf = 0; mf < 4; mf++) {
                    uint32_t byteoff = (uint32_t)(((arow + mf * 16) * RSH + akk) << 1);
                    ldm4(ah[mf], uAh + byteoff);
                }
                #pragma unroll
                for (int mf = 0; mf < 4; mf++)
                    #pragma unroll
                    for (int nf = 0; nf < 4; nf++)
                        mma16816(acc[mf][nf], ah[mf], bh[nf]);
                #pragma unroll
                for (int mf = 0; mf < 4; mf++)
                    #pragma unroll
                    for (int nf = 0; nf < 4; nf++)
                        mma16816(acc[mf][nf], ah[mf], bl[nf]);
            }
            {
                // lo-A pass last: al fragments allocated after ah is dead
                uint32_t al[4][4];
                #pragma unroll
                for (int mf = 0; mf < 4; mf++) {
                    uint32_t byteoff = (uint32_t)(((arow + mf * 16) * RSH + akk) << 1);
                    ldm4(al[mf], uAl + byteoff);
                }
                #pragma unroll
                for (int mf = 0; mf < 4; mf++)
                    #pragma unroll
                    for (int nf = 0; nf < 4; nf++)
                        mma16816(acc[mf][nf], al[mf], bh[nf]);
            }
        }
        __syncthreads();
    }

    if (cosMode) {
        const float* nb = g_norm + b * SQ;
        float part = 0.f;
        #pragma unroll
        for (int mf = 0; mf < 4; mf++) {
            int r = m0 + wm * 64 + mf * 16 + (lane >> 2);
            float nr0 = nb[r], nr1 = nb[r + 8];
            #pragma unroll
            for (int nf = 0; nf < 4; nf++) {
                #pragma unroll
                for (int u = 0; u < 2; u++) {
                    int col = n0 + wn * 32 + nf * 8 + ((lane & 3) << 1) + u;
                    float ncv = nb[col];
                    if (col > r) {
                        float cm = acc[mf][nf][u] / (nr0 * ncv + 1e-10f);
                        part += 2.f * cm * cm;
                    }
                    if (col > r + 8) {
                        float cm = acc[mf][nf][u + 2] / (nr1 * ncv + 1e-10f);
                        part += 2.f * cm * cm;
                    }
                }
            }
        }
        float* red = (float*)sm;
        red[tid] = part; __syncthreads();
        for (int off = 128; off > 0; off >>= 1) {
            if (tid < off) red[tid] += red[tid + off];
            __syncthreads();
        }
        if (tid == 0) atomicAdd(&g_acc[b], red[0]);
        return;
    }

    float cs[8], cq[8];
    #pragma unroll
    for (int i = 0; i < 8; i++) { cs[i] = 0.f; cq[i] = 0.f; }
    float* Cb = C + (size_t)b * sC;
    #pragma unroll
    for (int mf = 0; mf < 4; mf++) {
        int r = m0 + wm * 64 + mf * 16 + (lane >> 2);
        float br0 = biasRow ? biasRow[r] : 0.f;
        float br1 = biasRow ? biasRow[r + 8] : 0.f;
        #pragma unroll
        for (int nf = 0; nf < 4; nf++) {
            int c = n0 + wn * 32 + nf * 8 + ((lane & 3) << 1);
            #pragma unroll
            for (int u = 0; u < 2; u++) {
                int col = c + u;
                float bc = (biasCol && col < N) ? biasCol[col] : 0.f;
                float v0 = acc[mf][nf][u]     + br0 + bc;
                float v1 = acc[mf][nf][u + 2] + br1 + bc;
                if (col < N) {
                    Cb[(size_t)r * N + col]       = v0;
                    Cb[(size_t)(r + 8) * N + col] = v1;
                }
                if (statMode == 1) {
                    cs[nf*2+u] += v0 + v1;
                    cq[nf*2+u] += v0*v0 + v1*v1;
                } else if (statMode == 2) {
                    cs[mf*2]   += v0; cq[mf*2]   += v0*v0;
                    cs[mf*2+1] += v1; cq[mf*2+1] += v1*v1;
                }
            }
        }
    }
    if (statMode == 0) return;
    float* ssum = (float*)sm;
    float* ssq  = ssum + 2048;
    if (statMode == 1) {
        int g = wm * 8 + (lane >> 2);
        #pragma unroll
        for (int nf = 0; nf < 4; nf++)
            #pragma unroll
            for (int u = 0; u < 2; u++) {
                int colL = wn * 32 + nf * 8 + ((lane & 3) << 1) + u;
                ssum[colL * 16 + g] = cs[nf*2+u];
                ssq [colL * 16 + g] = cq[nf*2+u];
            }
        __syncthreads();
        if (tid < 128) {
            double s = 0.0, q = 0.0;
            #pragma unroll
            for (int g2 = 0; g2 < 16; g2++) { s += ssum[tid*16+g2]; q += ssq[tid*16+g2]; }
            int gcol = n0 + tid;
            if (gcol < N) {
                int chunk = blockIdx.z * gridDim.y + blockIdx.y;
                statOut[((size_t)chunk * statC + gcol) * 2]     = s;
                statOut[((size_t)chunk * statC + gcol) * 2 + 1] = q;
            }
        }
    } else {
        int h = wn * 4 + (lane & 3);
        #pragma unroll
        for (int mf = 0; mf < 4; mf++)
            #pragma unroll
            for (int hf = 0; hf < 2; hf++) {
                int rowL = wm * 64 + mf * 16 + (lane >> 2) + hf * 8;
                ssum[rowL * 16 + h] = cs[mf*2+hf];
                ssq [rowL * 16 + h] = cq[mf*2+hf];
            }
        __syncthreads();
        if (tid < 128) {
            double s = 0.0, q = 0.0;
            #pragma unroll
            for (int h2 = 0; h2 < 16; h2++) { s += ssum[tid*16+h2]; q += ssq[tid*16+h2]; }
            int grow = m0 + tid;
            int chunk = blockIdx.z * gridDim.x + blockIdx.x;
            statOut[((size_t)chunk * statC + grow) * 2]     = s;
            statOut[((size_t)chunk * statC + grow) * 2 + 1] = q;
        }
    }
}

// ---------------- elementwise / setup kernels ----------------
__global__ void sa_init() {
    int i = blockIdx.x * 256 + threadIdx.x;
    if (i < NQ) g_flags[i] = 0;
    if (i < BQ) g_acc[i] = 0.f;
}

__global__ void cv_split(const float* __restrict__ src, ush* __restrict__ dh, ush* __restrict__ dl,
                         long long totalPairs, int Ksrc, int Kp,
                         const float* __restrict__ sc, const float* __restrict__ sh, int leaky)
{
    long long i = (long long)blockIdx.x * 256 + threadIdx.x;
    if (i >= totalPairs) return;
    long long e = i * 2;
    int c = (int)(e % Kp);
    long long r = e / Kp;
    float v0 = 0.f, v1 = 0.f;
    if (c < Ksrc) {
        v0 = src[r * Ksrc + c];
        if (sc) { v0 = sc[c]*v0 + sh[c]; if (leaky && v0 < 0.f) v0 *= 0.2f; }
    }
    if (c + 1 < Ksrc) {
        v1 = src[r * Ksrc + c + 1];
        if (sc) { v1 = sc[c+1]*v1 + sh[c+1]; if (leaky && v1 < 0.f) v1 *= 0.2f; }
    }
    uint32_t lw, hw = split_pack(v0, v1, &lw);
    ((uint32_t*)dh)[i] = hw;
    ((uint32_t*)dl)[i] = lw;
}

__global__ void cv_agg(const float* __restrict__ points, const float* __restrict__ xyz) {
    long long i = (long long)blockIdx.x * 256 + threadIdx.x;
    if (i >= (long long)BQ*NQ*KP1/2) return;
    long long e = i * 2;
    int c = (int)(e % KP1); long long r = e / KP1;
    int n = (int)(r % NQ); int b = (int)(r / NQ);
    float v0 = 0.f, v1 = 0.f;
    if (c < DQ) v0 = points[((size_t)b*DQ + c)*NQ + n];
    else if (c < SCQ) v0 = xyz[((size_t)b*3 + (c-DQ))*NQ + n];
    int c1 = c + 1;
    if (c1 < DQ) v1 = points[((size_t)b*DQ + c1)*NQ + n];
    else if (c1 < SCQ) v1 = xyz[((size_t)b*3 + (c1-DQ))*NQ + n];
    uint32_t lw, hw = split_pack(v0, v1, &lw);
    ((uint32_t*)g_aggc_h)[i] = hw;
    ((uint32_t*)g_aggc_l)[i] = lw;
}

__global__ void sa_ball(const float* __restrict__ xyz) {
    int w = (blockIdx.x * blockDim.x + threadIdx.x) >> 5;
    int lane = threadIdx.x & 31;
    if (w >= BQ * NQ) return;
    int b = w / NQ, n = w % NQ;
    const float* X = xyz + (size_t)b * 3 * NQ;
    float px = X[n], py = X[NQ+n], pz = X[2*NQ+n];
    float pn = px*px + py*py + pz*pz;
    const float RR = (float)(0.2 * 0.2);
    int* out = g_idx + (size_t)b * NSQ * NQ + n;
    int cnt = 0;
    for (int j0 = 0; j0 < NQ && cnt < NSQ; j0 += 32) {
        int j = j0 + lane;
        float qx = X[j], qy = X[NQ+j], qz = X[2*NQ+j];
        float sq = (pn + qx*qx+qy*qy+qz*qz) - 2.0f*(px*qx+py*qy+pz*qz);
        bool in = !(sq > RR);
        unsigned m = __ballot_sync(0xffffffffu, in);
        int pos = cnt + __popc(m & ((1u << lane) - 1u));
        if (in && pos < NSQ) out[(size_t)pos * NQ] = j;
        cnt += __popc(m);
    }
    __syncwarp();
    if (lane == 0) {
        int first = out[0];
        for (int t = cnt; t < NSQ; t++) out[(size_t)t * NQ] = first;
    }
}

__global__ void sa_bmt_c(const float* __restrict__ points, const float* __restrict__ xyz) {
    int n = (blockIdx.x * 256 + threadIdx.x) * 2;
    int j = blockIdx.y, b = blockIdx.z;
    float v0, v1;
    if (j < OFF_P) {
        const float* p = xyz + ((size_t)b*3 + j)*NQ;
        v0 = p[n]; v1 = p[n+1];
    } else if (j < OFF_GP) {
        const float* p = points + ((size_t)b*DQ + (j-OFF_P))*NQ;
        v0 = p[n]; v1 = p[n+1];
    } else if (j < OFF_GX) {
        int t = j - OFF_GP, k = t >> 6, d = t & 63;
        const int* ip = g_idx + ((size_t)b*NSQ + k)*NQ;
        const float* p = points + ((size_t)b*DQ + d)*NQ;
        v0 = p[ip[n]]; v1 = p[ip[n+1]];
    } else {
        int t = j - OFF_GX, k = t / 3, c = t % 3;
        const int* ip = g_idx + ((size_t)b*NSQ + k)*NQ;
        const float* p = xyz + ((size_t)b*3 + c)*NQ;
        v0 = p[ip[n]]; v1 = p[ip[n+1]];
    }
    size_t o = (((size_t)b*JQ + j)*NQ + n) >> 1;
    uint32_t lw, hw = split_pack(v0, v1, &lw);
    ((uint32_t*)g_BmTc_h)[o] = hw;
    ((uint32_t*)g_BmTc_l)[o] = lw;
}

__global__ void sa_cs_fin(int C, int nChunks, int count,
                          const float* __restrict__ gamma, const float* __restrict__ beta,
                          float* __restrict__ sc, float* __restrict__ sf) {
    int c = blockIdx.x, tid = threadIdx.x;
    double s = 0.0, s2 = 0.0;
    for (int i = tid; i < nChunks; i += 256) {
        s  += g_part[((size_t)i * C + c) * 2];
        s2 += g_part[((size_t)i * C + c) * 2 + 1];
    }
    __shared__ double sa[256], sb2[256];
    sa[tid] = s; sb2[tid] = s2; __syncthreads();
    for (int o = 128; o > 0; o >>= 1) {
        if (tid < o) { sa[tid] += sa[tid+o]; sb2[tid] += sb2[tid+o]; }
        __syncthreads();
    }
    if (tid == 0) {
        double n = (double)count, m = sa[0] / n;
        double var = sb2[0] / n - m * m; if (var < 0.0) var = 0.0;
        float scale = gamma[c] * rsqrtf((float)var + 1e-5f);
        sc[c] = scale; sf[c] = beta[c] - (float)m * scale;
    }
}

__global__ void sa_softmax(float* __restrict__ H) {
    int s = blockIdx.x, b = blockIdx.y, tid = threadIdx.x;
    float* row = H + ((size_t)b * SQ + s) * NQ;
    __shared__ float buf[NQ];
    __shared__ float red[256], rv[256];
    __shared__ int ri[256];
    float a = g_s2[s], sh = g_sh2[s];
    float lmax = -3.4e38f;
    for (int i = tid; i < NQ; i += 256) { float y = a*row[i]+sh; buf[i] = y; lmax = fmaxf(lmax, y); }
    red[tid] = lmax; __syncthreads();
    for (int o = 128; o > 0; o >>= 1) { if (tid < o) red[tid] = fmaxf(red[tid], red[tid+o]); __syncthreads(); }
    float gmax = red[0]; __syncthreads();
    float lsum = 0.f;
    for (int i = tid; i < NQ; i += 256) { float e = expf(buf[i]-gmax); buf[i] = e; lsum += e; }
    red[tid] = lsum; __syncthreads();
    for (int o = 128; o > 0; o >>= 1) { if (tid < o) red[tid] += red[tid+o]; __syncthreads(); }
    float inv = 1.f / red[0]; __syncthreads();
    float lss = 0.f, bm = -1.f; int bi = 0;
    size_t rowoff = ((size_t)b * SQ + s) * NQ;
    for (int i = tid; i < NQ; i += 256) {
        float v = buf[i] * inv; lss += v*v;
        split_write(v, g_Sc_h + rowoff + i, g_Sc_l + rowoff + i);
        if (v > bm) { bm = v; bi = i; }
    }
    red[tid] = lss; rv[tid] = bm; ri[tid] = bi; __syncthreads();
    for (int o = 128; o > 0; o >>= 1) {
        if (tid < o) {
            red[tid] += red[tid+o];
            if (rv[tid+o] > rv[tid] || (rv[tid+o] == rv[tid] && ri[tid+o] < ri[tid])) { rv[tid] = rv[tid+o]; ri[tid] = ri[tid+o]; }
        }
        __syncthreads();
    }
    if (tid == 0) {
        g_norm[b*SQ+s] = sqrtf(red[0]);
        if (b == 0) g_amax[s] = ri[0];
    }
}

__global__ void sa_flags() { int s = blockIdx.x*256 + threadIdx.x; if (s < SQ) g_flags[g_amax[s]] = 1; }

__global__ void sa_newxyz(float* __restrict__ out) {
    int i = blockIdx.x * 256 + threadIdx.x;
    if (i >= BQ*3*SQ) return;
    int s = i % SQ, c = (i/SQ) % 3, b = i/(3*SQ);
    out[i] = g_Cbig[((size_t)b*SQ + s)*JQ + OFF_X + c];
}

__global__ void sa_max(float* __restrict__ out) {
    int s = blockIdx.x, b = blockIdx.y, o = threadIdx.x;
    float sc = g_sc2[o], sf = g_sf2[o];
    float m = -3.4e38f;
    const float* base = g_O2T + ((size_t)b*KSQ + s)*C2Q + o;
    #pragma unroll
    for (int k = 0; k < NSQ; k++) {
        float y = sc * base[(size_t)k*SQ*C2Q] + sf;
        y = (y >= 0.f) ? y : 0.2f * y;
        m = fmaxf(m, y);
    }
    out[XYZ_OUT + ((size_t)b*C2Q + o)*SQ + s] = m;
}

__global__ void sa_scalars(float* __restrict__ out) {
    __shared__ float sfr[256]; __shared__ int sir[256];
    int tid = threadIdx.x;
    int cnt = 0;
    for (int i = tid; i < NQ; i += 256) cnt += g_flags[i];
    float l = (tid < BQ) ? sqrtf(g_acc[tid]) : 0.f;
    sfr[tid] = l; sir[tid] = cnt; __syncthreads();
    for (int o = 128; o > 0; o >>= 1) {
        if (tid < o) { sfr[tid] += sfr[tid+o]; sir[tid] += sir[tid+o]; }
        __syncthreads();
    }
    if (tid == 0) {
        out[XYZ_OUT + NP_OUT] = sfr[0] / (float)BQ;
        out[XYZ_OUT + NP_OUT + 1] = (float)sir[0];
    }
}

// ---------------- launch ----------------
static inline float*  symf(const void* sym) { void* p = nullptr; cudaGetSymbolAddress(&p, sym); return (float*)p; }
static inline ush*    symu(const void* sym) { void* p = nullptr; cudaGetSymbolAddress(&p, sym); return (ush*)p; }
static inline double* symd(const void* sym) { void* p = nullptr; cudaGetSymbolAddress(&p, sym); return (double*)p; }

extern "C" void kernel_launch(void* const* d_in, const int* in_sizes, int n_in,
                              void* d_out, int out_size)
{
    const float* xyz   = (const float*)d_in[0];
    const float* points= (const float*)d_in[1];
    const float* w1_w = (const float*)d_in[2];
    const float* w1_b = (const float*)d_in[3];
    const float* bn1g = (const float*)d_in[4];
    const float* bn1b = (const float*)d_in[5];
    const float* w2_w = (const float*)d_in[6];
    const float* w2_b = (const float*)d_in[7];
    const float* bn2g = (const float*)d_in[8];
    const float* bn2b = (const float*)d_in[9];
    const float* c0w = (const float*)d_in[10];
    const float* c0b = (const float*)d_in[11];
    const float* g0  = (const float*)d_in[12];
    const float* b0  = (const float*)d_in[13];
    const float* c1w = (const float*)d_in[14];
    const float* c1b = (const float*)d_in[15];
    const float* g1  = (const float*)d_in[16];
    const float* b1  = (const float*)d_in[17];
    const float* c2w = (const float*)d_in[18];
    const float* c2b = (const float*)d_in[19];
    const float* g2  = (const float*)d_in[20];
    const float* b2  = (const float*)d_in[21];
    float* out = (float*)d_out;

    static bool inited = false;
    static cudaStream_t s1;
    static cudaEvent_t eA, eB, eS, eG;
    if (!inited) {
        cudaFuncSetAttribute(mma_gemm, cudaFuncAttributeMaxDynamicSharedMemorySize, SMEM_BYTES);
        cudaStreamCreateWithFlags(&s1, cudaStreamNonBlocking);
        cudaEventCreateWithFlags(&eA, cudaEventDisableTiming);
        cudaEventCreateWithFlags(&eB, cudaEventDisableTiming);
        cudaEventCreateWithFlags(&eS, cudaEventDisableTiming);
        cudaEventCreateWithFlags(&eG, cudaEventDisableTiming);
        inited = true;
    }

    float* p_h1t = symf(g_h1t);
    float* p_h2  = symf(g_h2);
    float* p_C   = symf(g_Cbig);
    float* p_O0  = symf(g_O0T);
    float* p_O1  = symf(g_O1T);
    float* p_O2  = symf(g_O2T);
    double* p_part = symd(g_part);
    float* p_s1 = symf(g_s1), *p_sh1 = symf(g_sh1);
    float* p_s2 = symf(g_s2), *p_sh2 = symf(g_sh2);
    float* p_sc0 = symf(g_sc0), *p_sf0 = symf(g_sf0);
    float* p_sc1 = symf(g_sc1), *p_sf1 = symf(g_sf1);
    float* p_sc2 = symf(g_sc2), *p_sf2 = symf(g_sf2);
    ush *aggh = symu(g_aggc_h), *aggl = symu(g_aggc_l);
    ush *w1h = symu(g_w1c_h), *w1l = symu(g_w1c_l);
    ush *h1h = symu(g_h1c_h), *h1l = symu(g_h1c_l);
    ush *w2h = symu(g_w2c_h), *w2l = symu(g_w2c_l);
    ush *Sh = symu(g_Sc_h), *Sl = symu(g_Sc_l);
    ush *Bmh = symu(g_BmTc_h), *Bml = symu(g_BmTc_l);
    ush *w0h = symu(g_c0wc_h), *w0l = symu(g_c0wc_l);
    ush *c1h = symu(g_c1wc_h), *c1l = symu(g_c1wc_l);
    ush *c2h = symu(g_c2wc_h), *c2l = symu(g_c2wc_l);

    // fork: side chain (ball -> BmT build -> conv-weight splits) on s1
    cudaEventRecord(eA, 0);
    cudaStreamWaitEvent(s1, eA, 0);
    sa_ball<<<(BQ*NQ*32)/256, 256, 0, s1>>>(xyz);
    sa_bmt_c<<<dim3(NQ/512, JQ, BQ), 256, 0, s1>>>(points, xyz);
    cv_split<<<(C0Q*KPE/2 + 255)/256, 256, 0, s1>>>(c0w, w0h, w0l, (long long)C0Q*KPE/2, INCH, KPE, nullptr, nullptr, 0);
    cv_split<<<(C1Q*C0Q/2 + 255)/256, 256, 0, s1>>>(c1w, c1h, c1l, (long long)C1Q*C0Q/2, C0Q, C0Q, nullptr, nullptr, 0);
    cv_split<<<(C2Q*C1Q/2 + 255)/256, 256, 0, s1>>>(c2w, c2h, c2l, (long long)C2Q*C1Q/2, C1Q, C1Q, nullptr, nullptr, 0);
    cudaEventRecord(eB, s1);

    // main chain
    sa_init<<<9, 256>>>();
    cv_agg<<<(int)(((long long)BQ*NQ*KP1/2 + 255)/256), 256>>>(points, xyz);
    cv_split<<<(SCQ*KP1/2 + 255)/256, 256>>>(w1_w, w1h, w1l, (long long)SCQ*KP1/2, SCQ, KP1, nullptr, nullptr, 0);
    cv_split<<<(SQ*KP1/2 + 255)/256, 256>>>(w2_w, w2h, w2l, (long long)SQ*KP1/2, SCQ, KP1, nullptr, nullptr, 0);

    // h1t = aggT * w1^T + w1_b ; col-stats fused
    mma_gemm<<<dim3(1, NQ/128, BQ), 256, SMEM_BYTES>>>(aggh, aggl, w1h, w1l, p_h1t,
        NQ, SCQ, KP1, (size_t)NQ*KP1, 0, (size_t)NQ*SCQ, nullptr, w1_b, 1, p_part, SCQ, 0, 0,
        0, nullptr, 0, nullptr, nullptr);
    sa_cs_fin<<<SCQ, 256>>>(SCQ, BQ*(NQ/128), BQ*NQ, bn1g, bn1b, p_s1, p_sh1);
    cv_split<<<(int)(((long long)BQ*NQ*KP1/2 + 255)/256), 256>>>(p_h1t, h1h, h1l,
        (long long)BQ*NQ*KP1/2, SCQ, KP1, p_s1, p_sh1, 0);

    // h2 = w2 * bn1(h1)^T + w2_b ; row-stats fused
    mma_gemm<<<dim3(NQ/128, SQ/128, BQ), 256, SMEM_BYTES>>>(w2h, w2l, h1h, h1l, p_h2,
        SQ, NQ, KP1, 0, (size_t)NQ*KP1, (size_t)SQ*NQ, w2_b, nullptr, 2, p_part, SQ, 0, 0,
        0, nullptr, 0, nullptr, nullptr);
    sa_cs_fin<<<SQ, 256>>>(SQ, BQ*(NQ/128), BQ*NQ, bn2g, bn2b, p_s2, p_sh2);
    sa_softmax<<<dim3(SQ, BQ), 256>>>(p_h2);
    cudaEventRecord(eS, 0);
    sa_flags<<<2, 256>>>();

    // Gram + cosine loss on s1 (overlaps Cbig/conv0 on main stream)
    cudaStreamWaitEvent(s1, eS, 0);
    mma_gemm<<<dim3(SQ/128, SQ/128, BQ), 256, SMEM_BYTES, s1>>>(Sh, Sl, Sh, Sl, p_h2,
        SQ, SQ, NQ, (size_t)SQ*NQ, (size_t)SQ*NQ, 0, nullptr, nullptr, 0, nullptr, 0, 1, 1,
        0, nullptr, 0, nullptr, nullptr);
    cudaEventRecord(eG, s1);

    // Cbig = S * BmT^T (needs BmT from side chain)
    cudaStreamWaitEvent(0, eB, 0);
    mma_gemm<<<dim3((JQ+127)/128, SQ/128, BQ), 256, SMEM_BYTES>>>(Sh, Sl, Bmh, Bml, p_C,
        SQ, JQ, NQ, (size_t)SQ*NQ, (size_t)JQ*NQ, (size_t)SQ*JQ, nullptr, nullptr, 0, nullptr, 0, 0, 0,
        0, nullptr, 0, nullptr, nullptr);
    sa_newxyz<<<(BQ*3*SQ + 255)/256, 256>>>(out);

    // conv0: A = edge features from Cbig in-loader
    mma_gemm<<<dim3(1, KSQ/128, BQ), 256, SMEM_BYTES>>>(w0h, w0l, w0h, w0l, p_O0,
        KSQ, C0Q, KPE, 0, 0, (size_t)KSQ*C0Q, nullptr, c0b, 1, p_part, C0Q, 0, 0,
        2, p_C, (size_t)SQ*JQ, nullptr, nullptr);
    sa_cs_fin<<<C0Q, 256>>>(C0Q, BQ*(KSQ/128), BQ*KSQ, g0, b0, p_sc0, p_sf0);

    // conv1: A = bn-affine+leaky of O0 fp32 in-loader
    mma_gemm<<<dim3(1, KSQ/128, BQ), 256, SMEM_BYTES>>>(c1h, c1l, c1h, c1l, p_O1,
        KSQ, C1Q, C0Q, 0, 0, (size_t)KSQ*C1Q, nullptr, c1b, 1, p_part, C1Q, 0, 0,
        1, p_O0, (size_t)KSQ*C0Q, p_sc0, p_sf0);
    sa_cs_fin<<<C1Q, 256>>>(C1Q, BQ*(KSQ/128), BQ*KSQ, g1, b1, p_sc1, p_sf1);

    // conv2: A = bn-affine+leaky of O1 fp32 in-loader
    mma_gemm<<<dim3(C2Q/128, KSQ/128, BQ), 256, SMEM_BYTES>>>(c2h, c2l, c2h, c2l, p_O2,
        KSQ, C2Q, C1Q, 0, 0, (size_t)KSQ*C2Q, nullptr, c2b, 1, p_part, C2Q, 0, 0,
        1, p_O1, (size_t)KSQ*C1Q, p_sc1, p_sf1);
    sa_cs_fin<<<C2Q, 256>>>(C2Q, BQ*(KSQ/128), BQ*KSQ, g2, b2, p_sc2, p_sf2);

    sa_max<<<dim3(SQ, BQ), 256>>>(out);
    // join Gram branch before final scalars
    cudaStreamWaitEvent(0, eG, 0);
    sa_scalars<<<1, 256>>>(out);
}